// round 1
// baseline (speedup 1.0000x reference)
#include <cuda_runtime.h>
#include <cuda_fp16.h>
#include <math.h>

#define S 2048
#define H 1536
#define NQ 12
#define NKV 2
#define D 128
#define IFF 8960
#define LAYERS 4
#define QDIM (NQ*D)      // 1536
#define KVDIM (NKV*D)    // 256
#define EPS 1e-6f
#define SCALE 0.08838834764831845f   // 1/sqrt(128)

// ---------------- device scratch (allocation-free) ----------------
__device__ float g_x[S*H];
__device__ float g_h[S*H];
__device__ float g_q[S*QDIM];
__device__ float g_k[S*KVDIM];
__device__ float g_v[S*KVDIM];
__device__ float g_attn[S*QDIM];
__device__ float g_act[S*IFF];

// ---------------- copy ----------------
__global__ void copy_kernel(const float4* __restrict__ src, float4* __restrict__ dst, int n) {
    int i = blockIdx.x * blockDim.x + threadIdx.x;
    if (i < n) dst[i] = src[i];
}

// ---------------- RMSNorm: one block per row ----------------
__global__ void rmsnorm_kernel(const float* __restrict__ x, const float* __restrict__ w,
                               float* __restrict__ out) {
    int row = blockIdx.x;
    const float* xr = x + (size_t)row * H;
    float ss = 0.f;
    for (int c = threadIdx.x; c < H; c += 256) { float v = xr[c]; ss += v * v; }
    __shared__ float red[256];
    red[threadIdx.x] = ss;
    __syncthreads();
    for (int off = 128; off > 0; off >>= 1) {
        if (threadIdx.x < off) red[threadIdx.x] += red[threadIdx.x + off];
        __syncthreads();
    }
    float rs = 1.0f / sqrtf(red[0] / (float)H + EPS);
    float* orow = out + (size_t)row * H;
    for (int c = threadIdx.x; c < H; c += 256) orow[c] = xr[c] * rs * w[c];
}

// ---------------- SGEMM: 64x64x16 tile, 4x4 microtile, 256 threads ----------------
// MODE 0: C = A@B + bias    MODE 1: C = A@B + R    MODE 2: C = silu(A@B)*(A@B2)
template <int MODE>
__global__ void __launch_bounds__(256) sgemm_kernel(
    const float* __restrict__ A, const float* __restrict__ B, const float* __restrict__ B2,
    const float* __restrict__ bias, const float* __restrict__ R, float* __restrict__ C,
    int K, int lda, int ldb, int ldc)
{
    __shared__ float As[16][68];
    __shared__ float Bs[16][64];
    __shared__ float Bs2[(MODE == 2) ? 16 : 1][64];

    int tid = threadIdx.x;
    int bm = blockIdx.y * 64, bn = blockIdx.x * 64;
    int tx = tid & 15, ty = tid >> 4;
    int am = tid >> 2, ak = (tid & 3) << 2;
    int bk = tid >> 4, bn4 = (tid & 15) << 2;

    const float* Ap  = A + (size_t)(bm + am) * lda + ak;
    const float* Bp  = B + (size_t)bk * ldb + bn + bn4;
    const float* B2p = (MODE == 2) ? (B2 + (size_t)bk * ldb + bn + bn4) : nullptr;

    float acc[16];
    float acc2[16];
#pragma unroll
    for (int i = 0; i < 16; i++) { acc[i] = 0.f; acc2[i] = 0.f; }

    for (int k0 = 0; k0 < K; k0 += 16) {
        float4 av = *(const float4*)(Ap + k0);
        As[ak + 0][am] = av.x; As[ak + 1][am] = av.y;
        As[ak + 2][am] = av.z; As[ak + 3][am] = av.w;
        *(float4*)&Bs[bk][bn4] = *(const float4*)(Bp + (size_t)k0 * ldb);
        if (MODE == 2)
            *(float4*)&Bs2[bk][bn4] = *(const float4*)(B2p + (size_t)k0 * ldb);
        __syncthreads();
#pragma unroll
        for (int kk = 0; kk < 16; kk++) {
            float4 a4 = *(const float4*)&As[kk][ty << 2];
            float4 b4 = *(const float4*)&Bs[kk][tx << 2];
            float ar[4] = {a4.x, a4.y, a4.z, a4.w};
            float br[4] = {b4.x, b4.y, b4.z, b4.w};
            if (MODE == 2) {
                float4 c4 = *(const float4*)&Bs2[kk][tx << 2];
                float cr[4] = {c4.x, c4.y, c4.z, c4.w};
#pragma unroll
                for (int i = 0; i < 4; i++)
#pragma unroll
                    for (int j = 0; j < 4; j++) {
                        acc[i * 4 + j]  += ar[i] * br[j];
                        acc2[i * 4 + j] += ar[i] * cr[j];
                    }
            } else {
#pragma unroll
                for (int i = 0; i < 4; i++)
#pragma unroll
                    for (int j = 0; j < 4; j++)
                        acc[i * 4 + j] += ar[i] * br[j];
            }
        }
        __syncthreads();
    }

#pragma unroll
    for (int i = 0; i < 4; i++) {
        int m = bm + (ty << 2) + i;
        int n0 = bn + (tx << 2);
        float vals[4];
        if (MODE == 1) {
            float4 r4 = *(const float4*)(R + (size_t)m * ldc + n0);
            vals[0] = acc[i * 4 + 0] + r4.x; vals[1] = acc[i * 4 + 1] + r4.y;
            vals[2] = acc[i * 4 + 2] + r4.z; vals[3] = acc[i * 4 + 3] + r4.w;
        } else if (MODE == 2) {
#pragma unroll
            for (int j = 0; j < 4; j++) {
                float gte = acc[i * 4 + j];
                vals[j] = gte / (1.f + expf(-gte)) * acc2[i * 4 + j];
            }
        } else {
#pragma unroll
            for (int j = 0; j < 4; j++)
                vals[j] = acc[i * 4 + j] + (bias ? bias[n0 + j] : 0.f);
        }
        float4 outv = {vals[0], vals[1], vals[2], vals[3]};
        *(float4*)(C + (size_t)m * ldc + n0) = outv;
    }
}

// ---------------- RoPE + fp16 round-trip on K,V ----------------
// grid: (S, NQ + 2*NKV), block: 128.  slot<12: q rope; 12-13: k rope+fp16; 14-15: v fp16
__global__ void rope_kernel(float* __restrict__ q, float* __restrict__ k, float* __restrict__ v,
                            const float* __restrict__ cp, const float* __restrict__ sp) {
    int s = blockIdx.x, slot = blockIdx.y, d = threadIdx.x;
    float c = cp[s * D + d], sn = sp[s * D + d];
    if (slot < NQ) {
        float* row = q + (size_t)s * QDIM + slot * D;
        float a = row[d]; float b = row[d ^ 64];
        float rot = (d < 64) ? -b : b;
        __syncthreads();
        row[d] = a * c + rot * sn;
    } else if (slot < NQ + NKV) {
        float* row = k + (size_t)s * KVDIM + (slot - NQ) * D;
        float a = row[d]; float b = row[d ^ 64];
        float rot = (d < 64) ? -b : b;
        __syncthreads();
        row[d] = __half2float(__float2half_rn(a * c + rot * sn));
    } else {
        float* row = v + (size_t)s * KVDIM + (slot - NQ - NKV) * D;
        float a = row[d];
        __syncthreads();
        row[d] = __half2float(__float2half_rn(a));
    }
}

// ---------------- causal flash attention, BM=BN=32, 256 threads ----------------
// 8 threads per query row; thread (r,g) owns out cols {g*4 + jj*32}.
#define PAD 132
__global__ void attn_kernel(const float* __restrict__ q, const float* __restrict__ k,
                            const float* __restrict__ v, float* __restrict__ o) {
    extern __shared__ float sm[];
    float* qs = sm;                  // 32*132
    float* ks = sm + 32 * PAD;       // 32*132
    float* vs = sm + 2 * 32 * PAD;   // 32*132
    float* ps = sm + 3 * 32 * PAD;   // 32*32

    int bq = blockIdx.x, h = blockIdx.y;
    int kvh = h / (NQ / NKV);
    int tid = threadIdx.x;
    int r = tid >> 3, g = tid & 7;
    int q0 = bq * 32;

#pragma unroll
    for (int j = 0; j < 4; j++) {
        int e = tid + j * 256;
        int row = e >> 5, c4 = (e & 31) << 2;
        float4 t = *(const float4*)(q + (size_t)(q0 + row) * QDIM + h * D + c4);
        t.x *= SCALE; t.y *= SCALE; t.z *= SCALE; t.w *= SCALE;
        *(float4*)&qs[row * PAD + c4] = t;
    }

    float m = -1e30f, l = 0.f;
    float acc[16];
#pragma unroll
    for (int i = 0; i < 16; i++) acc[i] = 0.f;

    for (int kt = 0; kt <= bq; kt++) {
        int kk0 = kt * 32;
        __syncthreads();
#pragma unroll
        for (int j = 0; j < 4; j++) {
            int e = tid + j * 256;
            int row = e >> 5, c4 = (e & 31) << 2;
            *(float4*)&ks[row * PAD + c4] =
                *(const float4*)(k + (size_t)(kk0 + row) * KVDIM + kvh * D + c4);
            *(float4*)&vs[row * PAD + c4] =
                *(const float4*)(v + (size_t)(kk0 + row) * KVDIM + kvh * D + c4);
        }
        __syncthreads();

        float sarr[4] = {0.f, 0.f, 0.f, 0.f};
        for (int d = 0; d < D; d += 4) {
            float4 qa = *(const float4*)&qs[r * PAD + d];
#pragma unroll
            for (int jj = 0; jj < 4; jj++) {
                float4 ka = *(const float4*)&ks[(g + jj * 8) * PAD + d];
                sarr[jj] += qa.x * ka.x + qa.y * ka.y + qa.z * ka.z + qa.w * ka.w;
            }
        }
        if (kt == bq) {
#pragma unroll
            for (int jj = 0; jj < 4; jj++)
                if (kk0 + g + jj * 8 > q0 + r) sarr[jj] = -1e30f;
        }
        float tmax = fmaxf(fmaxf(sarr[0], sarr[1]), fmaxf(sarr[2], sarr[3]));
#pragma unroll
        for (int off = 1; off < 8; off <<= 1)
            tmax = fmaxf(tmax, __shfl_xor_sync(0xffffffffu, tmax, off));
        float mnew = fmaxf(m, tmax);
        float corr = __expf(m - mnew);
        float psum = 0.f;
#pragma unroll
        for (int jj = 0; jj < 4; jj++) {
            float p = __expf(sarr[jj] - mnew);
            ps[r * 32 + g + jj * 8] = p;
            psum += p;
        }
#pragma unroll
        for (int off = 1; off < 8; off <<= 1)
            psum += __shfl_xor_sync(0xffffffffu, psum, off);
        l = l * corr + psum;
        m = mnew;
#pragma unroll
        for (int i = 0; i < 16; i++) acc[i] *= corr;
        __syncwarp();
        for (int kk = 0; kk < 32; kk++) {
            float pk = ps[r * 32 + kk];
#pragma unroll
            for (int jj = 0; jj < 4; jj++) {
                float4 vv = *(const float4*)&vs[kk * PAD + g * 4 + jj * 32];
                acc[jj * 4 + 0] += pk * vv.x;
                acc[jj * 4 + 1] += pk * vv.y;
                acc[jj * 4 + 2] += pk * vv.z;
                acc[jj * 4 + 3] += pk * vv.w;
            }
        }
    }
    float inv = 1.0f / l;
#pragma unroll
    for (int jj = 0; jj < 4; jj++) {
        float4 outv = {acc[jj * 4 + 0] * inv, acc[jj * 4 + 1] * inv,
                       acc[jj * 4 + 2] * inv, acc[jj * 4 + 3] * inv};
        *(float4*)(o + (size_t)(q0 + r) * QDIM + h * D + g * 4 + jj * 32) = outv;
    }
}

// ---------------- host launch ----------------
extern "C" void kernel_launch(void* const* d_in, const int* in_sizes, int n_in,
                              void* d_out, int out_size) {
    const float* hs   = (const float*)d_in[0];
    const float* cosp = (const float*)d_in[1];
    const float* sinp = (const float*)d_in[2];
    // d_in[3] attention_mask: implemented implicitly (causal, -1e9 => exp underflow to 0)
    const float* Wq = (const float*)d_in[4];
    const float* bq = (const float*)d_in[5];
    const float* Wk = (const float*)d_in[6];
    const float* bk = (const float*)d_in[7];
    const float* Wv = (const float*)d_in[8];
    const float* bv = (const float*)d_in[9];
    const float* Wo = (const float*)d_in[10];
    const float* Wg = (const float*)d_in[11];
    const float* Wu = (const float*)d_in[12];
    const float* Wd = (const float*)d_in[13];
    const float* ln1 = (const float*)d_in[14];
    const float* ln2 = (const float*)d_in[15];
    const float* fln = (const float*)d_in[16];

    float *p_x, *p_h, *p_q, *p_k, *p_v, *p_attn, *p_act;
    cudaGetSymbolAddress((void**)&p_x, g_x);
    cudaGetSymbolAddress((void**)&p_h, g_h);
    cudaGetSymbolAddress((void**)&p_q, g_q);
    cudaGetSymbolAddress((void**)&p_k, g_k);
    cudaGetSymbolAddress((void**)&p_v, g_v);
    cudaGetSymbolAddress((void**)&p_attn, g_attn);
    cudaGetSymbolAddress((void**)&p_act, g_act);

    const int attn_smem = (3 * 32 * PAD + 32 * 32) * 4;  // 54784 B
    cudaFuncSetAttribute(attn_kernel, cudaFuncAttributeMaxDynamicSharedMemorySize, attn_smem);

    // x = hidden_states
    {
        int n4 = S * H / 4;
        copy_kernel<<<(n4 + 255) / 256, 256>>>((const float4*)hs, (float4*)p_x, n4);
    }

    for (int i = 0; i < LAYERS; i++) {
        const float* Wq_i = Wq + (size_t)i * H * QDIM;
        const float* Wk_i = Wk + (size_t)i * H * KVDIM;
        const float* Wv_i = Wv + (size_t)i * H * KVDIM;
        const float* Wo_i = Wo + (size_t)i * QDIM * H;
        const float* Wg_i = Wg + (size_t)i * H * IFF;
        const float* Wu_i = Wu + (size_t)i * H * IFF;
        const float* Wd_i = Wd + (size_t)i * IFF * H;
        const float* bq_i = bq + (size_t)i * QDIM;
        const float* bk_i = bk + (size_t)i * KVDIM;
        const float* bv_i = bv + (size_t)i * KVDIM;

        rmsnorm_kernel<<<S, 256>>>(p_x, ln1 + (size_t)i * H, p_h);

        sgemm_kernel<0><<<dim3(QDIM / 64, S / 64), 256>>>(
            p_h, Wq_i, nullptr, bq_i, nullptr, p_q, H, H, QDIM, QDIM);
        sgemm_kernel<0><<<dim3(KVDIM / 64, S / 64), 256>>>(
            p_h, Wk_i, nullptr, bk_i, nullptr, p_k, H, H, KVDIM, KVDIM);
        sgemm_kernel<0><<<dim3(KVDIM / 64, S / 64), 256>>>(
            p_h, Wv_i, nullptr, bv_i, nullptr, p_v, H, H, KVDIM, KVDIM);

        rope_kernel<<<dim3(S, NQ + 2 * NKV), 128>>>(p_q, p_k, p_v, cosp, sinp);

        attn_kernel<<<dim3(S / 32, NQ), 256, attn_smem>>>(p_q, p_k, p_v, p_attn);

        sgemm_kernel<1><<<dim3(H / 64, S / 64), 256>>>(
            p_attn, Wo_i, nullptr, nullptr, p_x, p_x, QDIM, QDIM, H, H);

        rmsnorm_kernel<<<S, 256>>>(p_x, ln2 + (size_t)i * H, p_h);

        sgemm_kernel<2><<<dim3(IFF / 64, S / 64), 256>>>(
            p_h, Wg_i, Wu_i, nullptr, nullptr, p_act, H, H, IFF, IFF);

        sgemm_kernel<1><<<dim3(H / 64, S / 64), 256>>>(
            p_act, Wd_i, nullptr, nullptr, p_x, p_x, IFF, IFF, H, H);
    }

    rmsnorm_kernel<<<S, 256>>>(p_x, fln, (float*)d_out);
}

// round 3
// speedup vs baseline: 1.5929x; 1.5929x over previous
#include <cuda_runtime.h>
#include <cuda_fp16.h>
#include <cuda_bf16.h>
#include <math.h>
#include <stdint.h>

#define S 2048
#define H 1536
#define NQ 12
#define NKV 2
#define D 128
#define IFF 8960
#define LAYERS 4
#define QDIM (NQ*D)      // 1536
#define KVDIM (NKV*D)    // 256
#define QKVN 2048
#define GUN (2*IFF)      // 17920
#define EPS 1e-6f
#define SCALE 0.08838834764831845f

// ---------------- device scratch (allocation-free) ----------------
__device__ float g_x[S*H];
__device__ float g_h[S*H];
__device__ float g_qkv[S*QKVN];
__device__ float g_attn[S*QDIM];
__device__ float g_gu[(size_t)S*GUN];
__device__ float g_act[(size_t)S*IFF];
__device__ float g_biasq[QKVN];
__device__ __nv_bfloat16 g_thi[(size_t)GUN*H];
__device__ __nv_bfloat16 g_tlo[(size_t)GUN*H];

__device__ __forceinline__ uint32_t pack_bf2(__nv_bfloat16 a, __nv_bfloat16 b) {
    __nv_bfloat162 t; t.x = a; t.y = b;
    return *reinterpret_cast<uint32_t*>(&t);
}

__device__ __forceinline__ void mma_bf16(float* d, const uint32_t* a, uint32_t b0, uint32_t b1) {
    asm volatile(
        "mma.sync.aligned.m16n8k16.row.col.f32.bf16.bf16.f32 "
        "{%0,%1,%2,%3}, {%4,%5,%6,%7}, {%8,%9}, {%0,%1,%2,%3};"
        : "+f"(d[0]), "+f"(d[1]), "+f"(d[2]), "+f"(d[3])
        : "r"(a[0]), "r"(a[1]), "r"(a[2]), "r"(a[3]), "r"(b0), "r"(b1));
}

// ---------------- copy ----------------
__global__ void copy_kernel(const float4* __restrict__ src, float4* __restrict__ dst, int n) {
    int i = blockIdx.x * blockDim.x + threadIdx.x;
    if (i < n) dst[i] = src[i];
}

// ---------------- RMSNorm ----------------
__global__ void rmsnorm_kernel(const float* __restrict__ x, const float* __restrict__ w,
                               float* __restrict__ out) {
    int row = blockIdx.x;
    const float* xr = x + (size_t)row * H;
    float ss = 0.f;
    for (int c = threadIdx.x; c < H; c += 256) { float v = xr[c]; ss += v * v; }
    __shared__ float red[256];
    red[threadIdx.x] = ss;
    __syncthreads();
    for (int off = 128; off > 0; off >>= 1) {
        if (threadIdx.x < off) red[threadIdx.x] += red[threadIdx.x + off];
        __syncthreads();
    }
    float rs = 1.0f / sqrtf(red[0] / (float)H + EPS);
    float* orow = out + (size_t)row * H;
    for (int c = threadIdx.x; c < H; c += 256) orow[c] = xr[c] * rs * w[c];
}

// ---------------- transpose + bf16 split:  W[K,Nsrc] -> T[n_off+n][k] ----------------
__global__ void transpose_split_kernel(const float* __restrict__ W, int K, int Nsrc,
                                       __nv_bfloat16* __restrict__ Th,
                                       __nv_bfloat16* __restrict__ Tl,
                                       int n_off, int ldk) {
    __shared__ float t[32][33];
    int k0 = blockIdx.y * 32, n0 = blockIdx.x * 32;
    int tx = threadIdx.x, ty = threadIdx.y;  // 32 x 8
#pragma unroll
    for (int i = 0; i < 4; i++)
        t[ty + 8 * i][tx] = W[(size_t)(k0 + ty + 8 * i) * Nsrc + n0 + tx];
    __syncthreads();
    int nl = ty * 4 + (tx >> 3);
    int kp = tx & 7;
#pragma unroll
    for (int j = 0; j < 2; j++) {
        int k2 = (kp + 8 * j) * 2;
        float v0 = t[k2][nl], v1 = t[k2 + 1][nl];
        __nv_bfloat16 h0 = __float2bfloat16(v0), h1 = __float2bfloat16(v1);
        __nv_bfloat16 l0 = __float2bfloat16(v0 - __bfloat162float(h0));
        __nv_bfloat16 l1 = __float2bfloat16(v1 - __bfloat162float(h1));
        size_t o = (size_t)(n_off + n0 + nl) * ldk + k0 + k2;
        *(uint32_t*)(Th + o) = pack_bf2(h0, h1);
        *(uint32_t*)(Tl + o) = pack_bf2(l0, l1);
    }
}

// ---------------- bias concat for fused QKV ----------------
__global__ void concat_bias_kernel(const float* bq, const float* bk, const float* bv,
                                   float* out) {
    int i = blockIdx.x * 256 + threadIdx.x;
    if (i < QKVN)
        out[i] = (i < QDIM) ? bq[i] : ((i < QDIM + KVDIM) ? bk[i - QDIM] : bv[i - QDIM - KVDIM]);
}

// ---------------- warp-MMA split-bf16 GEMM ----------------
// C[M,N] = A[M,K](fp32) @ B^T, B given as [N,K] bf16 hi/lo. 3 MMA passes.
// EPI 0: += bias (if non-null); EPI 1: += R (may alias C)
// gridDim.x = M/128 (m-fastest raster), gridDim.y = N/128
#define APITCH 40
#define STG (128 * APITCH)                 // bf16 elems per array
#define GEMM_SMEM (2 * 4 * STG * 2)        // 81920 B

template <int EPI>
__global__ void __launch_bounds__(256, 1) wgemm_kernel(
    const float* __restrict__ A, const __nv_bfloat16* __restrict__ Bh,
    const __nv_bfloat16* __restrict__ Bl, const float* __restrict__ bias,
    const float* __restrict__ Rres, float* __restrict__ C, int K, int N)
{
    extern __shared__ __nv_bfloat16 sm[];
    int tid = threadIdx.x;
    int wid = tid >> 5, lane = tid & 31;
    int bm = blockIdx.x * 128, bn = blockIdx.y * 128;
    int mw = (wid & 3) * 32, nw = (wid >> 2) * 64;

    const int KS = K / 32;
    int lrow = tid >> 1;              // 0..127
    int lkp  = (tid & 1) * 16;        // 0 or 16

    const float* Ap = A + (size_t)(bm + lrow) * K + lkp;
    const __nv_bfloat16* Bhp = Bh + (size_t)(bn + lrow) * K + lkp;
    const __nv_bfloat16* Blp = Bl + (size_t)(bn + lrow) * K + lkp;

    float4 ar[4];
    uint4 bhr[2], blr[2];

    auto gload = [&](int k0) {
#pragma unroll
        for (int j = 0; j < 4; j++) ar[j] = *(const float4*)(Ap + k0 + j * 4);
        bhr[0] = *(const uint4*)(Bhp + k0);
        bhr[1] = *(const uint4*)(Bhp + k0 + 8);
        blr[0] = *(const uint4*)(Blp + k0);
        blr[1] = *(const uint4*)(Blp + k0 + 8);
    };
    auto sstore = [&](int st) {
        __nv_bfloat16* Ahs = sm + st * 4 * STG;
        __nv_bfloat16* Als = Ahs + STG;
        __nv_bfloat16* Bhs = Ahs + 2 * STG;
        __nv_bfloat16* Bls = Ahs + 3 * STG;
        int base = lrow * APITCH + lkp;
#pragma unroll
        for (int j = 0; j < 4; j++) {
            float v[4] = {ar[j].x, ar[j].y, ar[j].z, ar[j].w};
#pragma unroll
            for (int e = 0; e < 2; e++) {
                __nv_bfloat16 h0 = __float2bfloat16(v[e * 2]);
                __nv_bfloat16 h1 = __float2bfloat16(v[e * 2 + 1]);
                __nv_bfloat16 l0 = __float2bfloat16(v[e * 2] - __bfloat162float(h0));
                __nv_bfloat16 l1 = __float2bfloat16(v[e * 2 + 1] - __bfloat162float(h1));
                *(uint32_t*)(Ahs + base + j * 4 + e * 2) = pack_bf2(h0, h1);
                *(uint32_t*)(Als + base + j * 4 + e * 2) = pack_bf2(l0, l1);
            }
        }
        *(uint4*)(Bhs + base) = bhr[0];
        *(uint4*)(Bhs + base + 8) = bhr[1];
        *(uint4*)(Bls + base) = blr[0];
        *(uint4*)(Bls + base + 8) = blr[1];
    };

    float acc[2][8][4];
#pragma unroll
    for (int mt = 0; mt < 2; mt++)
#pragma unroll
        for (int nt = 0; nt < 8; nt++)
#pragma unroll
            for (int e = 0; e < 4; e++) acc[mt][nt][e] = 0.f;

    gload(0);

    for (int ks = 0; ks < KS; ks++) {
        int st = ks & 1;
        sstore(st);
        __syncthreads();
        if (ks + 1 < KS) gload((ks + 1) * 32);

        const __nv_bfloat16* Ahs = sm + st * 4 * STG;
        const __nv_bfloat16* Als = Ahs + STG;
        const __nv_bfloat16* Bhs = Ahs + 2 * STG;
        const __nv_bfloat16* Bls = Ahs + 3 * STG;

#pragma unroll
        for (int kk = 0; kk < 32; kk += 16) {
            int kc = kk + (lane & 3) * 2;
            uint32_t ah[2][4], al[2][4];
#pragma unroll
            for (int mt = 0; mt < 2; mt++) {
                int r0 = mw + mt * 16 + (lane >> 2);
                ah[mt][0] = *(const uint32_t*)(Ahs + r0 * APITCH + kc);
                ah[mt][1] = *(const uint32_t*)(Ahs + (r0 + 8) * APITCH + kc);
                ah[mt][2] = *(const uint32_t*)(Ahs + r0 * APITCH + kc + 8);
                ah[mt][3] = *(const uint32_t*)(Ahs + (r0 + 8) * APITCH + kc + 8);
                al[mt][0] = *(const uint32_t*)(Als + r0 * APITCH + kc);
                al[mt][1] = *(const uint32_t*)(Als + (r0 + 8) * APITCH + kc);
                al[mt][2] = *(const uint32_t*)(Als + r0 * APITCH + kc + 8);
                al[mt][3] = *(const uint32_t*)(Als + (r0 + 8) * APITCH + kc + 8);
            }
#pragma unroll
            for (int nt = 0; nt < 8; nt++) {
                int nb = nw + nt * 8 + (lane >> 2);
                uint32_t bh0 = *(const uint32_t*)(Bhs + nb * APITCH + kc);
                uint32_t bh1 = *(const uint32_t*)(Bhs + nb * APITCH + kc + 8);
                uint32_t bl0 = *(const uint32_t*)(Bls + nb * APITCH + kc);
                uint32_t bl1 = *(const uint32_t*)(Bls + nb * APITCH + kc + 8);
#pragma unroll
                for (int mt = 0; mt < 2; mt++) {
                    mma_bf16(acc[mt][nt], ah[mt], bh0, bh1);
                    mma_bf16(acc[mt][nt], ah[mt], bl0, bl1);
                    mma_bf16(acc[mt][nt], al[mt], bh0, bh1);
                }
            }
        }
        __syncthreads();
    }

    // epilogue
#pragma unroll
    for (int mt = 0; mt < 2; mt++) {
#pragma unroll
        for (int nt = 0; nt < 8; nt++) {
            int r0 = bm + mw + mt * 16 + (lane >> 2);
            int col = bn + nw + nt * 8 + (lane & 3) * 2;
            float2 v0 = {acc[mt][nt][0], acc[mt][nt][1]};
            float2 v1 = {acc[mt][nt][2], acc[mt][nt][3]};
            if (EPI == 0) {
                if (bias) {
                    float b0 = bias[col], b1 = bias[col + 1];
                    v0.x += b0; v0.y += b1; v1.x += b0; v1.y += b1;
                }
            } else {
                float2 r0v = *(const float2*)(Rres + (size_t)r0 * N + col);
                float2 r1v = *(const float2*)(Rres + (size_t)(r0 + 8) * N + col);
                v0.x += r0v.x; v0.y += r0v.y;
                v1.x += r1v.x; v1.y += r1v.y;
            }
            *(float2*)(C + (size_t)r0 * N + col) = v0;
            *(float2*)(C + (size_t)(r0 + 8) * N + col) = v1;
        }
    }
}

// ---------------- RoPE + fp16 round-trip on K,V (combined qkv buffer) ----------------
__global__ void rope_kernel(float* __restrict__ qkv,
                            const float* __restrict__ cp, const float* __restrict__ sp) {
    int s = blockIdx.x, slot = blockIdx.y, d = threadIdx.x;
    float c = cp[s * D + d], sn = sp[s * D + d];
    float* row;
    if (slot < NQ)            row = qkv + (size_t)s * QKVN + slot * D;
    else if (slot < NQ + NKV) row = qkv + (size_t)s * QKVN + QDIM + (slot - NQ) * D;
    else                      row = qkv + (size_t)s * QKVN + QDIM + KVDIM + (slot - NQ - NKV) * D;
    float a = row[d];
    float b = row[d ^ 64];
    float rot = (d < 64) ? -b : b;
    __syncthreads();
    float val;
    if (slot < NQ)            val = a * c + rot * sn;
    else if (slot < NQ + NKV) val = __half2float(__float2half_rn(a * c + rot * sn));
    else                      val = __half2float(__float2half_rn(a));
    row[d] = val;
}

// ---------------- causal flash attention ----------------
#define PAD 132
__global__ void attn_kernel(const float* __restrict__ qkv, float* __restrict__ o) {
    extern __shared__ float smf[];
    float* qs = smf;
    float* ks = smf + 32 * PAD;
    float* vs = smf + 2 * 32 * PAD;
    float* ps = smf + 3 * 32 * PAD;

    int bq = blockIdx.x, h = blockIdx.y;
    int kvh = h / (NQ / NKV);
    int tid = threadIdx.x;
    int r = tid >> 3, g = tid & 7;
    int q0 = bq * 32;

#pragma unroll
    for (int j = 0; j < 4; j++) {
        int e = tid + j * 256;
        int row = e >> 5, c4 = (e & 31) << 2;
        float4 t = *(const float4*)(qkv + (size_t)(q0 + row) * QKVN + h * D + c4);
        t.x *= SCALE; t.y *= SCALE; t.z *= SCALE; t.w *= SCALE;
        *(float4*)&qs[row * PAD + c4] = t;
    }

    float m = -1e30f, l = 0.f;
    float acc[16];
#pragma unroll
    for (int i = 0; i < 16; i++) acc[i] = 0.f;

    for (int kt = 0; kt <= bq; kt++) {
        int kk0 = kt * 32;
        __syncthreads();
#pragma unroll
        for (int j = 0; j < 4; j++) {
            int e = tid + j * 256;
            int row = e >> 5, c4 = (e & 31) << 2;
            *(float4*)&ks[row * PAD + c4] =
                *(const float4*)(qkv + (size_t)(kk0 + row) * QKVN + QDIM + kvh * D + c4);
            *(float4*)&vs[row * PAD + c4] =
                *(const float4*)(qkv + (size_t)(kk0 + row) * QKVN + QDIM + KVDIM + kvh * D + c4);
        }
        __syncthreads();

        float sarr[4] = {0.f, 0.f, 0.f, 0.f};
        for (int d = 0; d < D; d += 4) {
            float4 qa = *(const float4*)&qs[r * PAD + d];
#pragma unroll
            for (int jj = 0; jj < 4; jj++) {
                float4 ka = *(const float4*)&ks[(g + jj * 8) * PAD + d];
                sarr[jj] += qa.x * ka.x + qa.y * ka.y + qa.z * ka.z + qa.w * ka.w;
            }
        }
        if (kt == bq) {
#pragma unroll
            for (int jj = 0; jj < 4; jj++)
                if (kk0 + g + jj * 8 > q0 + r) sarr[jj] = -1e30f;
        }
        float tmax = fmaxf(fmaxf(sarr[0], sarr[1]), fmaxf(sarr[2], sarr[3]));
#pragma unroll
        for (int off = 1; off < 8; off <<= 1)
            tmax = fmaxf(tmax, __shfl_xor_sync(0xffffffffu, tmax, off));
        float mnew = fmaxf(m, tmax);
        float corr = __expf(m - mnew);
        float psum = 0.f;
#pragma unroll
        for (int jj = 0; jj < 4; jj++) {
            float p = __expf(sarr[jj] - mnew);
            ps[r * 32 + g + jj * 8] = p;
            psum += p;
        }
#pragma unroll
        for (int off = 1; off < 8; off <<= 1)
            psum += __shfl_xor_sync(0xffffffffu, psum, off);
        l = l * corr + psum;
        m = mnew;
#pragma unroll
        for (int i = 0; i < 16; i++) acc[i] *= corr;
        __syncwarp();
        for (int kk = 0; kk < 32; kk++) {
            float pk = ps[r * 32 + kk];
#pragma unroll
            for (int jj = 0; jj < 4; jj++) {
                float4 vv = *(const float4*)&vs[kk * PAD + g * 4 + jj * 32];
                acc[jj * 4 + 0] += pk * vv.x;
                acc[jj * 4 + 1] += pk * vv.y;
                acc[jj * 4 + 2] += pk * vv.z;
                acc[jj * 4 + 3] += pk * vv.w;
            }
        }
    }
    float inv = 1.0f / l;
#pragma unroll
    for (int jj = 0; jj < 4; jj++) {
        float4 outv = {acc[jj * 4 + 0] * inv, acc[jj * 4 + 1] * inv,
                       acc[jj * 4 + 2] * inv, acc[jj * 4 + 3] * inv};
        *(float4*)(o + (size_t)(q0 + r) * QDIM + h * D + g * 4 + jj * 32) = outv;
    }
}

// ---------------- silu(gate) * up ----------------
__global__ void silu_mul_kernel(const float* __restrict__ gu, float* __restrict__ out) {
    int i = blockIdx.x * 256 + threadIdx.x;
    if (i >= S * IFF / 4) return;
    int m = i / (IFF / 4);
    int c = i % (IFF / 4);
    float4 g = ((const float4*)(gu + (size_t)m * GUN))[c];
    float4 u = ((const float4*)(gu + (size_t)m * GUN + IFF))[c];
    float4 o;
    o.x = g.x / (1.f + __expf(-g.x)) * u.x;
    o.y = g.y / (1.f + __expf(-g.y)) * u.y;
    o.z = g.z / (1.f + __expf(-g.z)) * u.z;
    o.w = g.w / (1.f + __expf(-g.w)) * u.w;
    ((float4*)(out + (size_t)m * IFF))[c] = o;
}

// ---------------- host launch ----------------
extern "C" void kernel_launch(void* const* d_in, const int* in_sizes, int n_in,
                              void* d_out, int out_size) {
    const float* hs   = (const float*)d_in[0];
    const float* cosp = (const float*)d_in[1];
    const float* sinp = (const float*)d_in[2];
    const float* Wq = (const float*)d_in[4];
    const float* bq = (const float*)d_in[5];
    const float* Wk = (const float*)d_in[6];
    const float* bk = (const float*)d_in[7];
    const float* Wv = (const float*)d_in[8];
    const float* bv = (const float*)d_in[9];
    const float* Wo = (const float*)d_in[10];
    const float* Wg = (const float*)d_in[11];
    const float* Wu = (const float*)d_in[12];
    const float* Wd = (const float*)d_in[13];
    const float* ln1 = (const float*)d_in[14];
    const float* ln2 = (const float*)d_in[15];
    const float* fln = (const float*)d_in[16];

    float *p_x, *p_h, *p_qkv, *p_attn, *p_gu, *p_act, *p_bias;
    __nv_bfloat16 *p_thi, *p_tlo;
    cudaGetSymbolAddress((void**)&p_x, g_x);
    cudaGetSymbolAddress((void**)&p_h, g_h);
    cudaGetSymbolAddress((void**)&p_qkv, g_qkv);
    cudaGetSymbolAddress((void**)&p_attn, g_attn);
    cudaGetSymbolAddress((void**)&p_gu, g_gu);
    cudaGetSymbolAddress((void**)&p_act, g_act);
    cudaGetSymbolAddress((void**)&p_bias, g_biasq);
    cudaGetSymbolAddress((void**)&p_thi, g_thi);
    cudaGetSymbolAddress((void**)&p_tlo, g_tlo);

    const int attn_smem = (3 * 32 * PAD + 32 * 32) * 4;
    cudaFuncSetAttribute(attn_kernel, cudaFuncAttributeMaxDynamicSharedMemorySize, attn_smem);
    cudaFuncSetAttribute(wgemm_kernel<0>, cudaFuncAttributeMaxDynamicSharedMemorySize, GEMM_SMEM);
    cudaFuncSetAttribute(wgemm_kernel<1>, cudaFuncAttributeMaxDynamicSharedMemorySize, GEMM_SMEM);

    {
        int n4 = S * H / 4;
        copy_kernel<<<(n4 + 255) / 256, 256>>>((const float4*)hs, (float4*)p_x, n4);
    }

    dim3 tb(32, 8);
    for (int i = 0; i < LAYERS; i++) {
        const float* Wq_i = Wq + (size_t)i * H * QDIM;
        const float* Wk_i = Wk + (size_t)i * H * KVDIM;
        const float* Wv_i = Wv + (size_t)i * H * KVDIM;
        const float* Wo_i = Wo + (size_t)i * QDIM * H;
        const float* Wg_i = Wg + (size_t)i * H * IFF;
        const float* Wu_i = Wu + (size_t)i * H * IFF;
        const float* Wd_i = Wd + (size_t)i * IFF * H;

        rmsnorm_kernel<<<S, 256>>>(p_x, ln1 + (size_t)i * H, p_h);

        transpose_split_kernel<<<dim3(QDIM / 32, H / 32), tb>>>(Wq_i, H, QDIM, p_thi, p_tlo, 0, H);
        transpose_split_kernel<<<dim3(KVDIM / 32, H / 32), tb>>>(Wk_i, H, KVDIM, p_thi, p_tlo, QDIM, H);
        transpose_split_kernel<<<dim3(KVDIM / 32, H / 32), tb>>>(Wv_i, H, KVDIM, p_thi, p_tlo, QDIM + KVDIM, H);
        concat_bias_kernel<<<QKVN / 256, 256>>>(bq + (size_t)i * QDIM, bk + (size_t)i * KVDIM,
                                                bv + (size_t)i * KVDIM, p_bias);
        wgemm_kernel<0><<<dim3(S / 128, QKVN / 128), 256, GEMM_SMEM>>>(
            p_h, p_thi, p_tlo, p_bias, nullptr, p_qkv, H, QKVN);

        rope_kernel<<<dim3(S, NQ + 2 * NKV), 128>>>(p_qkv, cosp, sinp);
        attn_kernel<<<dim3(S / 32, NQ), 256, attn_smem>>>(p_qkv, p_attn);

        transpose_split_kernel<<<dim3(H / 32, QDIM / 32), tb>>>(Wo_i, QDIM, H, p_thi, p_tlo, 0, QDIM);
        wgemm_kernel<1><<<dim3(S / 128, H / 128), 256, GEMM_SMEM>>>(
            p_attn, p_thi, p_tlo, nullptr, p_x, p_x, QDIM, H);

        rmsnorm_kernel<<<S, 256>>>(p_x, ln2 + (size_t)i * H, p_h);

        transpose_split_kernel<<<dim3(IFF / 32, H / 32), tb>>>(Wg_i, H, IFF, p_thi, p_tlo, 0, H);
        transpose_split_kernel<<<dim3(IFF / 32, H / 32), tb>>>(Wu_i, H, IFF, p_thi, p_tlo, IFF, H);
        wgemm_kernel<0><<<dim3(S / 128, GUN / 128), 256, GEMM_SMEM>>>(
            p_h, p_thi, p_tlo, nullptr, nullptr, p_gu, H, GUN);

        silu_mul_kernel<<<(S * IFF / 4 + 255) / 256, 256>>>(p_gu, p_act);

        transpose_split_kernel<<<dim3(H / 32, IFF / 32), tb>>>(Wd_i, IFF, H, p_thi, p_tlo, 0, IFF);
        wgemm_kernel<1><<<dim3(S / 128, H / 128), 256, GEMM_SMEM>>>(
            p_act, p_thi, p_tlo, nullptr, p_x, p_x, IFF, H);
    }

    rmsnorm_kernel<<<S, 256>>>(p_x, fln, (float*)d_out);
}

// round 4
// speedup vs baseline: 1.6769x; 1.0527x over previous
#include <cuda_runtime.h>
#include <cuda_fp16.h>
#include <cuda_bf16.h>
#include <math.h>
#include <stdint.h>

#define S 2048
#define H 1536
#define NQ 12
#define NKV 2
#define D 128
#define IFF 8960
#define LAYERS 4
#define QDIM (NQ*D)      // 1536
#define KVDIM (NKV*D)    // 256
#define QKVN 2048
#define GUN (2*IFF)      // 17920
#define EPS 1e-6f
#define SCALE 0.08838834764831845f

// ---------------- device scratch (allocation-free) ----------------
__device__ float g_x[S*H];
__device__ float g_h[S*H];
__device__ float g_qkv[S*QKVN];
__device__ float g_attn[S*QDIM];
__device__ float g_gu[(size_t)S*GUN];
__device__ float g_act[(size_t)S*IFF];
__device__ float g_biasq[QKVN];
__device__ __nv_bfloat16 g_thi[(size_t)GUN*H];
__device__ __nv_bfloat16 g_tlo[(size_t)GUN*H];

__device__ __forceinline__ uint32_t pack_bf2(__nv_bfloat16 a, __nv_bfloat16 b) {
    __nv_bfloat162 t; t.x = a; t.y = b;
    return *reinterpret_cast<uint32_t*>(&t);
}
__device__ __forceinline__ uint32_t smem_u32(const void* p) {
    uint32_t a;
    asm("{ .reg .u64 t; cvta.to.shared.u64 t, %1; cvt.u32.u64 %0, t; }" : "=r"(a) : "l"(p));
    return a;
}
__device__ __forceinline__ void mma_bf16(float* d, const uint32_t* a, uint32_t b0, uint32_t b1) {
    asm volatile(
        "mma.sync.aligned.m16n8k16.row.col.f32.bf16.bf16.f32 "
        "{%0,%1,%2,%3}, {%4,%5,%6,%7}, {%8,%9}, {%0,%1,%2,%3};"
        : "+f"(d[0]), "+f"(d[1]), "+f"(d[2]), "+f"(d[3])
        : "r"(a[0]), "r"(a[1]), "r"(a[2]), "r"(a[3]), "r"(b0), "r"(b1));
}
__device__ __forceinline__ void ldsm_x4(uint32_t* r, uint32_t addr) {
    asm volatile("ldmatrix.sync.aligned.m8n8.x4.shared.b16 {%0,%1,%2,%3}, [%4];"
        : "=r"(r[0]), "=r"(r[1]), "=r"(r[2]), "=r"(r[3]) : "r"(addr));
}
#define CP_A16(dst, src) asm volatile("cp.async.ca.shared.global [%0], [%1], 16;" :: "r"(dst), "l"(src) : "memory")
#define CP_COMMIT()      asm volatile("cp.async.commit_group;" ::: "memory")
#define CP_WAIT0()       asm volatile("cp.async.wait_group 0;" ::: "memory")

// ---------------- copy ----------------
__global__ void copy_kernel(const float4* __restrict__ src, float4* __restrict__ dst, int n) {
    int i = blockIdx.x * blockDim.x + threadIdx.x;
    if (i < n) dst[i] = src[i];
}

// ---------------- RMSNorm ----------------
__global__ void rmsnorm_kernel(const float* __restrict__ x, const float* __restrict__ w,
                               float* __restrict__ out) {
    int row = blockIdx.x;
    const float* xr = x + (size_t)row * H;
    float ss = 0.f;
    for (int c = threadIdx.x; c < H; c += 256) { float v = xr[c]; ss += v * v; }
    __shared__ float red[256];
    red[threadIdx.x] = ss;
    __syncthreads();
    for (int off = 128; off > 0; off >>= 1) {
        if (threadIdx.x < off) red[threadIdx.x] += red[threadIdx.x + off];
        __syncthreads();
    }
    float rs = 1.0f / sqrtf(red[0] / (float)H + EPS);
    float* orow = out + (size_t)row * H;
    for (int c = threadIdx.x; c < H; c += 256) orow[c] = xr[c] * rs * w[c];
}

// ---------------- transpose + bf16 split ----------------
__global__ void transpose_split_kernel(const float* __restrict__ W, int K, int Nsrc,
                                       __nv_bfloat16* __restrict__ Th,
                                       __nv_bfloat16* __restrict__ Tl,
                                       int n_off, int ldk) {
    __shared__ float t[32][33];
    int k0 = blockIdx.y * 32, n0 = blockIdx.x * 32;
    int tx = threadIdx.x, ty = threadIdx.y;
#pragma unroll
    for (int i = 0; i < 4; i++)
        t[ty + 8 * i][tx] = W[(size_t)(k0 + ty + 8 * i) * Nsrc + n0 + tx];
    __syncthreads();
    int nl = ty * 4 + (tx >> 3);
    int kp = tx & 7;
#pragma unroll
    for (int j = 0; j < 2; j++) {
        int k2 = (kp + 8 * j) * 2;
        float v0 = t[k2][nl], v1 = t[k2 + 1][nl];
        __nv_bfloat16 h0 = __float2bfloat16(v0), h1 = __float2bfloat16(v1);
        __nv_bfloat16 l0 = __float2bfloat16(v0 - __bfloat162float(h0));
        __nv_bfloat16 l1 = __float2bfloat16(v1 - __bfloat162float(h1));
        size_t o = (size_t)(n_off + n0 + nl) * ldk + k0 + k2;
        *(uint32_t*)(Th + o) = pack_bf2(h0, h1);
        *(uint32_t*)(Tl + o) = pack_bf2(l0, l1);
    }
}

// ---------------- bias concat ----------------
__global__ void concat_bias_kernel(const float* bq, const float* bk, const float* bv,
                                   float* out) {
    int i = blockIdx.x * 256 + threadIdx.x;
    if (i < QKVN)
        out[i] = (i < QDIM) ? bq[i] : ((i < QDIM + KVDIM) ? bk[i - QDIM] : bv[i - QDIM - KVDIM]);
}

// ---------------- warp-MMA split-bf16 GEMM (ldmatrix + cp.async) ----------------
#define APITCH 40
#define STG (128 * APITCH)                 // bf16 elems per array
#define GEMM_SMEM (2 * 4 * STG * 2)        // 81920 B

template <int EPI>
__global__ void __launch_bounds__(256, 1) wgemm_kernel(
    const float* __restrict__ A, const __nv_bfloat16* __restrict__ Bh,
    const __nv_bfloat16* __restrict__ Bl, const float* __restrict__ bias,
    const float* __restrict__ Rres, float* __restrict__ C, int K, int N)
{
    extern __shared__ __nv_bfloat16 sm[];
    uint32_t smb = smem_u32(sm);
    int tid = threadIdx.x;
    int wid = tid >> 5, lane = tid & 31;
    int bm = blockIdx.x * 128, bn = blockIdx.y * 128;
    int mw = (wid & 3) * 32, nw = (wid >> 2) * 64;

    const int KS = K / 32;
    int lrow = tid >> 1;              // 0..127
    int lkp  = (tid & 1) * 16;        // 0 or 16

    const float* Ap = A + (size_t)(bm + lrow) * K + lkp;
    const __nv_bfloat16* Bhp = Bh + (size_t)(bn + lrow) * K + lkp;
    const __nv_bfloat16* Blp = Bl + (size_t)(bn + lrow) * K + lkp;

    // byte offset of this thread's row slot within one 128x40 array
    const uint32_t rowoff = (uint32_t)(lrow * APITCH + lkp) * 2;

    float4 ar[4];
    auto gloadA = [&](int k0) {
#pragma unroll
        for (int j = 0; j < 4; j++) ar[j] = *(const float4*)(Ap + k0 + j * 4);
    };
    auto cpasyncB = [&](int st, int k0) {
        uint32_t dsth = smb + (uint32_t)(st * 4 + 2) * STG * 2 + rowoff;
        uint32_t dstl = smb + (uint32_t)(st * 4 + 3) * STG * 2 + rowoff;
        CP_A16(dsth,      Bhp + k0);
        CP_A16(dsth + 16, Bhp + k0 + 8);
        CP_A16(dstl,      Blp + k0);
        CP_A16(dstl + 16, Blp + k0 + 8);
    };
    auto sstoreA = [&](int st) {
        __nv_bfloat16* Ahs = sm + st * 4 * STG;
        __nv_bfloat16* Als = Ahs + STG;
        int base = lrow * APITCH + lkp;
#pragma unroll
        for (int j = 0; j < 4; j++) {
            float v[4] = {ar[j].x, ar[j].y, ar[j].z, ar[j].w};
            uint32_t hp[2], lp[2];
#pragma unroll
            for (int e = 0; e < 2; e++) {
                __nv_bfloat16 h0 = __float2bfloat16(v[e * 2]);
                __nv_bfloat16 h1 = __float2bfloat16(v[e * 2 + 1]);
                __nv_bfloat16 l0 = __float2bfloat16(v[e * 2] - __bfloat162float(h0));
                __nv_bfloat16 l1 = __float2bfloat16(v[e * 2 + 1] - __bfloat162float(h1));
                hp[e] = pack_bf2(h0, h1);
                lp[e] = pack_bf2(l0, l1);
            }
            *(uint2*)(Ahs + base + j * 4) = make_uint2(hp[0], hp[1]);
            *(uint2*)(Als + base + j * 4) = make_uint2(lp[0], lp[1]);
        }
    };

    float acc[2][8][4];
#pragma unroll
    for (int mt = 0; mt < 2; mt++)
#pragma unroll
        for (int nt = 0; nt < 8; nt++)
#pragma unroll
            for (int e = 0; e < 4; e++) acc[mt][nt][e] = 0.f;

    // ldmatrix address pattern: lanes 0-15 -> rows, +8 k for lanes 16-31
    const int frow = lane & 15;
    const int fk   = (lane >> 4) << 3;

    gloadA(0);
    cpasyncB(0, 0);
    CP_COMMIT();

    for (int ks = 0; ks < KS; ks++) {
        int st = ks & 1;
        sstoreA(st);
        CP_WAIT0();
        __syncthreads();
        if (ks + 1 < KS) {
            cpasyncB(st ^ 1, (ks + 1) * 32);
            CP_COMMIT();
            gloadA((ks + 1) * 32);
        }

        uint32_t Ah32 = smb + (uint32_t)(st * 4 + 0) * STG * 2;
        uint32_t Al32 = smb + (uint32_t)(st * 4 + 1) * STG * 2;
        uint32_t Bh32 = smb + (uint32_t)(st * 4 + 2) * STG * 2;
        uint32_t Bl32 = smb + (uint32_t)(st * 4 + 3) * STG * 2;

#pragma unroll
        for (int kk = 0; kk < 32; kk += 16) {
            int ko = kk + fk;
            uint32_t ah[2][4], al[2][4];
#pragma unroll
            for (int mt = 0; mt < 2; mt++) {
                uint32_t off = (uint32_t)((mw + mt * 16 + frow) * APITCH + ko) * 2;
                ldsm_x4(ah[mt], Ah32 + off);
                ldsm_x4(al[mt], Al32 + off);
            }
            uint32_t bh[4][4], bl[4][4];
#pragma unroll
            for (int p = 0; p < 4; p++) {
                uint32_t off = (uint32_t)((nw + p * 16 + frow) * APITCH + ko) * 2;
                ldsm_x4(bh[p], Bh32 + off);
                ldsm_x4(bl[p], Bl32 + off);
            }
#pragma unroll
            for (int nt = 0; nt < 8; nt++) {
                int p = nt >> 1, o = nt & 1;
                uint32_t b0h = bh[p][o], b1h = bh[p][o + 2];
                uint32_t b0l = bl[p][o], b1l = bl[p][o + 2];
#pragma unroll
                for (int mt = 0; mt < 2; mt++) {
                    mma_bf16(acc[mt][nt], ah[mt], b0h, b1h);
                    mma_bf16(acc[mt][nt], ah[mt], b0l, b1l);
                    mma_bf16(acc[mt][nt], al[mt], b0h, b1h);
                }
            }
        }
        __syncthreads();
    }

    // epilogue
#pragma unroll
    for (int mt = 0; mt < 2; mt++) {
#pragma unroll
        for (int nt = 0; nt < 8; nt++) {
            int r0 = bm + mw + mt * 16 + (lane >> 2);
            int col = bn + nw + nt * 8 + (lane & 3) * 2;
            float2 v0 = {acc[mt][nt][0], acc[mt][nt][1]};
            float2 v1 = {acc[mt][nt][2], acc[mt][nt][3]};
            if (EPI == 0) {
                if (bias) {
                    float b0 = bias[col], b1 = bias[col + 1];
                    v0.x += b0; v0.y += b1; v1.x += b0; v1.y += b1;
                }
            } else {
                float2 r0v = *(const float2*)(Rres + (size_t)r0 * N + col);
                float2 r1v = *(const float2*)(Rres + (size_t)(r0 + 8) * N + col);
                v0.x += r0v.x; v0.y += r0v.y;
                v1.x += r1v.x; v1.y += r1v.y;
            }
            *(float2*)(C + (size_t)r0 * N + col) = v0;
            *(float2*)(C + (size_t)(r0 + 8) * N + col) = v1;
        }
    }
}

// ---------------- RoPE + fp16 round-trip ----------------
__global__ void rope_kernel(float* __restrict__ qkv,
                            const float* __restrict__ cp, const float* __restrict__ sp) {
    int s = blockIdx.x, slot = blockIdx.y, d = threadIdx.x;
    float c = cp[s * D + d], sn = sp[s * D + d];
    float* row;
    if (slot < NQ)            row = qkv + (size_t)s * QKVN + slot * D;
    else if (slot < NQ + NKV) row = qkv + (size_t)s * QKVN + QDIM + (slot - NQ) * D;
    else                      row = qkv + (size_t)s * QKVN + QDIM + KVDIM + (slot - NQ - NKV) * D;
    float a = row[d];
    float b = row[d ^ 64];
    float rot = (d < 64) ? -b : b;
    __syncthreads();
    float val;
    if (slot < NQ)            val = a * c + rot * sn;
    else if (slot < NQ + NKV) val = __half2float(__float2half_rn(a * c + rot * sn));
    else                      val = __half2float(__float2half_rn(a));
    row[d] = val;
}

// ---------------- causal flash attention (fp32) ----------------
#define PAD 132
__global__ void attn_kernel(const float* __restrict__ qkv, float* __restrict__ o) {
    extern __shared__ float smf[];
    float* qs = smf;
    float* ks = smf + 32 * PAD;
    float* vs = smf + 2 * 32 * PAD;
    float* ps = smf + 3 * 32 * PAD;

    int bq = blockIdx.x, h = blockIdx.y;
    int kvh = h / (NQ / NKV);
    int tid = threadIdx.x;
    int r = tid >> 3, g = tid & 7;
    int q0 = bq * 32;

#pragma unroll
    for (int j = 0; j < 4; j++) {
        int e = tid + j * 256;
        int row = e >> 5, c4 = (e & 31) << 2;
        float4 t = *(const float4*)(qkv + (size_t)(q0 + row) * QKVN + h * D + c4);
        t.x *= SCALE; t.y *= SCALE; t.z *= SCALE; t.w *= SCALE;
        *(float4*)&qs[row * PAD + c4] = t;
    }

    float m = -1e30f, l = 0.f;
    float acc[16];
#pragma unroll
    for (int i = 0; i < 16; i++) acc[i] = 0.f;

    for (int kt = 0; kt <= bq; kt++) {
        int kk0 = kt * 32;
        __syncthreads();
#pragma unroll
        for (int j = 0; j < 4; j++) {
            int e = tid + j * 256;
            int row = e >> 5, c4 = (e & 31) << 2;
            *(float4*)&ks[row * PAD + c4] =
                *(const float4*)(qkv + (size_t)(kk0 + row) * QKVN + QDIM + kvh * D + c4);
            *(float4*)&vs[row * PAD + c4] =
                *(const float4*)(qkv + (size_t)(kk0 + row) * QKVN + QDIM + KVDIM + kvh * D + c4);
        }
        __syncthreads();

        float sarr[4] = {0.f, 0.f, 0.f, 0.f};
        for (int d = 0; d < D; d += 4) {
            float4 qa = *(const float4*)&qs[r * PAD + d];
#pragma unroll
            for (int jj = 0; jj < 4; jj++) {
                float4 ka = *(const float4*)&ks[(g + jj * 8) * PAD + d];
                sarr[jj] += qa.x * ka.x + qa.y * ka.y + qa.z * ka.z + qa.w * ka.w;
            }
        }
        if (kt == bq) {
#pragma unroll
            for (int jj = 0; jj < 4; jj++)
                if (kk0 + g + jj * 8 > q0 + r) sarr[jj] = -1e30f;
        }
        float tmax = fmaxf(fmaxf(sarr[0], sarr[1]), fmaxf(sarr[2], sarr[3]));
#pragma unroll
        for (int off = 1; off < 8; off <<= 1)
            tmax = fmaxf(tmax, __shfl_xor_sync(0xffffffffu, tmax, off));
        float mnew = fmaxf(m, tmax);
        float corr = __expf(m - mnew);
        float psum = 0.f;
#pragma unroll
        for (int jj = 0; jj < 4; jj++) {
            float p = __expf(sarr[jj] - mnew);
            ps[r * 32 + g + jj * 8] = p;
            psum += p;
        }
#pragma unroll
        for (int off = 1; off < 8; off <<= 1)
            psum += __shfl_xor_sync(0xffffffffu, psum, off);
        l = l * corr + psum;
        m = mnew;
#pragma unroll
        for (int i = 0; i < 16; i++) acc[i] *= corr;
        __syncwarp();
        for (int kk = 0; kk < 32; kk++) {
            float pk = ps[r * 32 + kk];
#pragma unroll
            for (int jj = 0; jj < 4; jj++) {
                float4 vv = *(const float4*)&vs[kk * PAD + g * 4 + jj * 32];
                acc[jj * 4 + 0] += pk * vv.x;
                acc[jj * 4 + 1] += pk * vv.y;
                acc[jj * 4 + 2] += pk * vv.z;
                acc[jj * 4 + 3] += pk * vv.w;
            }
        }
    }
    float inv = 1.0f / l;
#pragma unroll
    for (int jj = 0; jj < 4; jj++) {
        float4 outv = {acc[jj * 4 + 0] * inv, acc[jj * 4 + 1] * inv,
                       acc[jj * 4 + 2] * inv, acc[jj * 4 + 3] * inv};
        *(float4*)(o + (size_t)(q0 + r) * QDIM + h * D + g * 4 + jj * 32) = outv;
    }
}

// ---------------- silu(gate) * up ----------------
__global__ void silu_mul_kernel(const float* __restrict__ gu, float* __restrict__ out) {
    int i = blockIdx.x * 256 + threadIdx.x;
    if (i >= S * IFF / 4) return;
    int m = i / (IFF / 4);
    int c = i % (IFF / 4);
    float4 g = ((const float4*)(gu + (size_t)m * GUN))[c];
    float4 u = ((const float4*)(gu + (size_t)m * GUN + IFF))[c];
    float4 o;
    o.x = g.x / (1.f + __expf(-g.x)) * u.x;
    o.y = g.y / (1.f + __expf(-g.y)) * u.y;
    o.z = g.z / (1.f + __expf(-g.z)) * u.z;
    o.w = g.w / (1.f + __expf(-g.w)) * u.w;
    ((float4*)(out + (size_t)m * IFF))[c] = o;
}

// ---------------- host launch ----------------
extern "C" void kernel_launch(void* const* d_in, const int* in_sizes, int n_in,
                              void* d_out, int out_size) {
    const float* hs   = (const float*)d_in[0];
    const float* cosp = (const float*)d_in[1];
    const float* sinp = (const float*)d_in[2];
    const float* Wq = (const float*)d_in[4];
    const float* bq = (const float*)d_in[5];
    const float* Wk = (const float*)d_in[6];
    const float* bk = (const float*)d_in[7];
    const float* Wv = (const float*)d_in[8];
    const float* bv = (const float*)d_in[9];
    const float* Wo = (const float*)d_in[10];
    const float* Wg = (const float*)d_in[11];
    const float* Wu = (const float*)d_in[12];
    const float* Wd = (const float*)d_in[13];
    const float* ln1 = (const float*)d_in[14];
    const float* ln2 = (const float*)d_in[15];
    const float* fln = (const float*)d_in[16];

    float *p_x, *p_h, *p_qkv, *p_attn, *p_gu, *p_act, *p_bias;
    __nv_bfloat16 *p_thi, *p_tlo;
    cudaGetSymbolAddress((void**)&p_x, g_x);
    cudaGetSymbolAddress((void**)&p_h, g_h);
    cudaGetSymbolAddress((void**)&p_qkv, g_qkv);
    cudaGetSymbolAddress((void**)&p_attn, g_attn);
    cudaGetSymbolAddress((void**)&p_gu, g_gu);
    cudaGetSymbolAddress((void**)&p_act, g_act);
    cudaGetSymbolAddress((void**)&p_bias, g_biasq);
    cudaGetSymbolAddress((void**)&p_thi, g_thi);
    cudaGetSymbolAddress((void**)&p_tlo, g_tlo);

    const int attn_smem = (3 * 32 * PAD + 32 * 32) * 4;
    cudaFuncSetAttribute(attn_kernel, cudaFuncAttributeMaxDynamicSharedMemorySize, attn_smem);
    cudaFuncSetAttribute(wgemm_kernel<0>, cudaFuncAttributeMaxDynamicSharedMemorySize, GEMM_SMEM);
    cudaFuncSetAttribute(wgemm_kernel<1>, cudaFuncAttributeMaxDynamicSharedMemorySize, GEMM_SMEM);

    {
        int n4 = S * H / 4;
        copy_kernel<<<(n4 + 255) / 256, 256>>>((const float4*)hs, (float4*)p_x, n4);
    }

    dim3 tb(32, 8);
    for (int i = 0; i < LAYERS; i++) {
        const float* Wq_i = Wq + (size_t)i * H * QDIM;
        const float* Wk_i = Wk + (size_t)i * H * KVDIM;
        const float* Wv_i = Wv + (size_t)i * H * KVDIM;
        const float* Wo_i = Wo + (size_t)i * QDIM * H;
        const float* Wg_i = Wg + (size_t)i * H * IFF;
        const float* Wu_i = Wu + (size_t)i * H * IFF;
        const float* Wd_i = Wd + (size_t)i * IFF * H;

        rmsnorm_kernel<<<S, 256>>>(p_x, ln1 + (size_t)i * H, p_h);

        transpose_split_kernel<<<dim3(QDIM / 32, H / 32), tb>>>(Wq_i, H, QDIM, p_thi, p_tlo, 0, H);
        transpose_split_kernel<<<dim3(KVDIM / 32, H / 32), tb>>>(Wk_i, H, KVDIM, p_thi, p_tlo, QDIM, H);
        transpose_split_kernel<<<dim3(KVDIM / 32, H / 32), tb>>>(Wv_i, H, KVDIM, p_thi, p_tlo, QDIM + KVDIM, H);
        concat_bias_kernel<<<QKVN / 256, 256>>>(bq + (size_t)i * QDIM, bk + (size_t)i * KVDIM,
                                                bv + (size_t)i * KVDIM, p_bias);
        wgemm_kernel<0><<<dim3(S / 128, QKVN / 128), 256, GEMM_SMEM>>>(
            p_h, p_thi, p_tlo, p_bias, nullptr, p_qkv, H, QKVN);

        rope_kernel<<<dim3(S, NQ + 2 * NKV), 128>>>(p_qkv, cosp, sinp);
        attn_kernel<<<dim3(S / 32, NQ), 256, attn_smem>>>(p_qkv, p_attn);

        transpose_split_kernel<<<dim3(H / 32, QDIM / 32), tb>>>(Wo_i, QDIM, H, p_thi, p_tlo, 0, QDIM);
        wgemm_kernel<1><<<dim3(S / 128, H / 128), 256, GEMM_SMEM>>>(
            p_attn, p_thi, p_tlo, nullptr, p_x, p_x, QDIM, H);

        rmsnorm_kernel<<<S, 256>>>(p_x, ln2 + (size_t)i * H, p_h);

        transpose_split_kernel<<<dim3(IFF / 32, H / 32), tb>>>(Wg_i, H, IFF, p_thi, p_tlo, 0, H);
        transpose_split_kernel<<<dim3(IFF / 32, H / 32), tb>>>(Wu_i, H, IFF, p_thi, p_tlo, IFF, H);
        wgemm_kernel<0><<<dim3(S / 128, GUN / 128), 256, GEMM_SMEM>>>(
            p_h, p_thi, p_tlo, nullptr, nullptr, p_gu, H, GUN);

        silu_mul_kernel<<<(S * IFF / 4 + 255) / 256, 256>>>(p_gu, p_act);

        transpose_split_kernel<<<dim3(H / 32, IFF / 32), tb>>>(Wd_i, IFF, H, p_thi, p_tlo, 0, IFF);
        wgemm_kernel<1><<<dim3(S / 128, H / 128), 256, GEMM_SMEM>>>(
            p_act, p_thi, p_tlo, nullptr, p_x, p_x, IFF, H);
    }

    rmsnorm_kernel<<<S, 256>>>(p_x, fln, (float*)d_out);
}

// round 5
// speedup vs baseline: 1.6782x; 1.0008x over previous
#include <cuda_runtime.h>
#include <cuda_fp16.h>
#include <cuda_bf16.h>
#include <math.h>
#include <stdint.h>

#define S 2048
#define H 1536
#define NQ 12
#define NKV 2
#define D 128
#define IFF 8960
#define LAYERS 4
#define QDIM (NQ*D)      // 1536
#define KVDIM (NKV*D)    // 256
#define QKVN 2048
#define GUN (2*IFF)      // 17920
#define EPS 1e-6f
#define SCALE 0.08838834764831845f

// ---------------- device scratch (allocation-free) ----------------
__device__ float g_x[S*H];
__device__ float g_h[S*H];
__device__ float g_qkv[S*QKVN];
__device__ float g_attn[S*QDIM];
__device__ float g_gu[(size_t)S*GUN];
__device__ float g_act[(size_t)S*IFF];
__device__ float g_biasq[QKVN];
__device__ __nv_bfloat16 g_thi[(size_t)GUN*H];
__device__ __nv_bfloat16 g_tlo[(size_t)GUN*H];

__device__ __forceinline__ uint32_t pack_bf2(__nv_bfloat16 a, __nv_bfloat16 b) {
    __nv_bfloat162 t; t.x = a; t.y = b;
    return *reinterpret_cast<uint32_t*>(&t);
}
__device__ __forceinline__ uint32_t smem_u32(const void* p) {
    uint32_t a;
    asm("{ .reg .u64 t; cvta.to.shared.u64 t, %1; cvt.u32.u64 %0, t; }" : "=r"(a) : "l"(p));
    return a;
}
__device__ __forceinline__ void mma_bf16(float* d, const uint32_t* a, uint32_t b0, uint32_t b1) {
    asm volatile(
        "mma.sync.aligned.m16n8k16.row.col.f32.bf16.bf16.f32 "
        "{%0,%1,%2,%3}, {%4,%5,%6,%7}, {%8,%9}, {%0,%1,%2,%3};"
        : "+f"(d[0]), "+f"(d[1]), "+f"(d[2]), "+f"(d[3])
        : "r"(a[0]), "r"(a[1]), "r"(a[2]), "r"(a[3]), "r"(b0), "r"(b1));
}
__device__ __forceinline__ void ldsm_x4(uint32_t* r, uint32_t addr) {
    asm volatile("ldmatrix.sync.aligned.m8n8.x4.shared.b16 {%0,%1,%2,%3}, [%4];"
        : "=r"(r[0]), "=r"(r[1]), "=r"(r[2]), "=r"(r[3]) : "r"(addr));
}
#define CP_A16(dst, src) asm volatile("cp.async.ca.shared.global [%0], [%1], 16;" :: "r"(dst), "l"(src) : "memory")
#define CP_COMMIT()      asm volatile("cp.async.commit_group;" ::: "memory")
#define CP_WAIT0()       asm volatile("cp.async.wait_group 0;" ::: "memory")

// ---------------- copy ----------------
__global__ void copy_kernel(const float4* __restrict__ src, float4* __restrict__ dst, int n) {
    int i = blockIdx.x * blockDim.x + threadIdx.x;
    if (i < n) dst[i] = src[i];
}

// ---------------- RMSNorm ----------------
__global__ void rmsnorm_kernel(const float* __restrict__ x, const float* __restrict__ w,
                               float* __restrict__ out) {
    int row = blockIdx.x;
    const float* xr = x + (size_t)row * H;
    float ss = 0.f;
    for (int c = threadIdx.x; c < H; c += 256) { float v = xr[c]; ss += v * v; }
    __shared__ float red[256];
    red[threadIdx.x] = ss;
    __syncthreads();
    for (int off = 128; off > 0; off >>= 1) {
        if (threadIdx.x < off) red[threadIdx.x] += red[threadIdx.x + off];
        __syncthreads();
    }
    float rs = 1.0f / sqrtf(red[0] / (float)H + EPS);
    float* orow = out + (size_t)row * H;
    for (int c = threadIdx.x; c < H; c += 256) orow[c] = xr[c] * rs * w[c];
}

// ---------------- transpose + bf16 split (coalesced uint4 writes) ----------------
// W[K,Nsrc] fp32 -> Th/Tl[(n_off+n)*ldk + k] bf16. 32x32 tile, 256 threads.
__global__ void transpose_split_kernel(const float* __restrict__ W, int K, int Nsrc,
                                       __nv_bfloat16* __restrict__ Th,
                                       __nv_bfloat16* __restrict__ Tl,
                                       int n_off, int ldk) {
    __shared__ float t[32][33];
    int k0 = blockIdx.y * 32, n0 = blockIdx.x * 32;
    int tid = threadIdx.x;
    // coalesced read: 8 threads x float4 per k-row
    {
        int rk = tid >> 3, cn = (tid & 7) << 2;
        float4 v = *(const float4*)(W + (size_t)(k0 + rk) * Nsrc + n0 + cn);
        t[rk][cn] = v.x; t[rk][cn + 1] = v.y; t[rk][cn + 2] = v.z; t[rk][cn + 3] = v.w;
    }
    __syncthreads();
    // write: each thread emits one uint4 (8 bf16 contiguous in k) to hi or lo
    int idx = tid >> 1, arr = tid & 1;
    int n = idx >> 2, seg = (idx & 3) << 3;
    __nv_bfloat16 outv[8];
#pragma unroll
    for (int j = 0; j < 8; j++) {
        float v = t[seg + j][n];
        __nv_bfloat16 h = __float2bfloat16(v);
        outv[j] = arr ? __float2bfloat16(v - __bfloat162float(h)) : h;
    }
    __nv_bfloat16* dst = arr ? Tl : Th;
    *(uint4*)(dst + (size_t)(n_off + n0 + n) * ldk + k0 + seg) = *(uint4*)outv;
}

// ---------------- bias concat ----------------
__global__ void concat_bias_kernel(const float* bq, const float* bk, const float* bv,
                                   float* out) {
    int i = blockIdx.x * 256 + threadIdx.x;
    if (i < QKVN)
        out[i] = (i < QDIM) ? bq[i] : ((i < QDIM + KVDIM) ? bk[i - QDIM] : bv[i - QDIM - KVDIM]);
}

// ---------------- warp-MMA split-bf16 GEMM (ldmatrix + cp.async) ----------------
#define APITCH 40
#define STG (128 * APITCH)                 // bf16 elems per array
#define GEMM_SMEM (2 * 4 * STG * 2)        // 81920 B

template <int EPI>
__global__ void __launch_bounds__(256, 1) wgemm_kernel(
    const float* __restrict__ A, const __nv_bfloat16* __restrict__ Bh,
    const __nv_bfloat16* __restrict__ Bl, const float* __restrict__ bias,
    const float* __restrict__ Rres, float* __restrict__ C, int K, int N)
{
    extern __shared__ __nv_bfloat16 sm[];
    uint32_t smb = smem_u32(sm);
    int tid = threadIdx.x;
    int wid = tid >> 5, lane = tid & 31;
    int bm = blockIdx.x * 128, bn = blockIdx.y * 128;
    int mw = (wid & 3) * 32, nw = (wid >> 2) * 64;

    const int KS = K / 32;
    int lrow = tid >> 1;
    int lkp  = (tid & 1) * 16;

    const float* Ap = A + (size_t)(bm + lrow) * K + lkp;
    const __nv_bfloat16* Bhp = Bh + (size_t)(bn + lrow) * K + lkp;
    const __nv_bfloat16* Blp = Bl + (size_t)(bn + lrow) * K + lkp;

    const uint32_t rowoff = (uint32_t)(lrow * APITCH + lkp) * 2;

    float4 ar[4];
    auto gloadA = [&](int k0) {
#pragma unroll
        for (int j = 0; j < 4; j++) ar[j] = *(const float4*)(Ap + k0 + j * 4);
    };
    auto cpasyncB = [&](int st, int k0) {
        uint32_t dsth = smb + (uint32_t)(st * 4 + 2) * STG * 2 + rowoff;
        uint32_t dstl = smb + (uint32_t)(st * 4 + 3) * STG * 2 + rowoff;
        CP_A16(dsth,      Bhp + k0);
        CP_A16(dsth + 16, Bhp + k0 + 8);
        CP_A16(dstl,      Blp + k0);
        CP_A16(dstl + 16, Blp + k0 + 8);
    };
    auto sstoreA = [&](int st) {
        __nv_bfloat16* Ahs = sm + st * 4 * STG;
        __nv_bfloat16* Als = Ahs + STG;
        int base = lrow * APITCH + lkp;
#pragma unroll
        for (int j = 0; j < 4; j++) {
            float v[4] = {ar[j].x, ar[j].y, ar[j].z, ar[j].w};
            uint32_t hp[2], lp[2];
#pragma unroll
            for (int e = 0; e < 2; e++) {
                __nv_bfloat16 h0 = __float2bfloat16(v[e * 2]);
                __nv_bfloat16 h1 = __float2bfloat16(v[e * 2 + 1]);
                __nv_bfloat16 l0 = __float2bfloat16(v[e * 2] - __bfloat162float(h0));
                __nv_bfloat16 l1 = __float2bfloat16(v[e * 2 + 1] - __bfloat162float(h1));
                hp[e] = pack_bf2(h0, h1);
                lp[e] = pack_bf2(l0, l1);
            }
            *(uint2*)(Ahs + base + j * 4) = make_uint2(hp[0], hp[1]);
            *(uint2*)(Als + base + j * 4) = make_uint2(lp[0], lp[1]);
        }
    };

    float acc[2][8][4];
#pragma unroll
    for (int mt = 0; mt < 2; mt++)
#pragma unroll
        for (int nt = 0; nt < 8; nt++)
#pragma unroll
            for (int e = 0; e < 4; e++) acc[mt][nt][e] = 0.f;

    const int frow = lane & 15;
    const int fk   = (lane >> 4) << 3;

    gloadA(0);
    cpasyncB(0, 0);
    CP_COMMIT();

    for (int ks = 0; ks < KS; ks++) {
        int st = ks & 1;
        sstoreA(st);
        CP_WAIT0();
        __syncthreads();
        if (ks + 1 < KS) {
            cpasyncB(st ^ 1, (ks + 1) * 32);
            CP_COMMIT();
            gloadA((ks + 1) * 32);
        }

        uint32_t Ah32 = smb + (uint32_t)(st * 4 + 0) * STG * 2;
        uint32_t Al32 = smb + (uint32_t)(st * 4 + 1) * STG * 2;
        uint32_t Bh32 = smb + (uint32_t)(st * 4 + 2) * STG * 2;
        uint32_t Bl32 = smb + (uint32_t)(st * 4 + 3) * STG * 2;

#pragma unroll
        for (int kk = 0; kk < 32; kk += 16) {
            int ko = kk + fk;
            uint32_t ah[2][4], al[2][4];
#pragma unroll
            for (int mt = 0; mt < 2; mt++) {
                uint32_t off = (uint32_t)((mw + mt * 16 + frow) * APITCH + ko) * 2;
                ldsm_x4(ah[mt], Ah32 + off);
                ldsm_x4(al[mt], Al32 + off);
            }
            uint32_t bh[4][4], bl[4][4];
#pragma unroll
            for (int p = 0; p < 4; p++) {
                uint32_t off = (uint32_t)((nw + p * 16 + frow) * APITCH + ko) * 2;
                ldsm_x4(bh[p], Bh32 + off);
                ldsm_x4(bl[p], Bl32 + off);
            }
#pragma unroll
            for (int nt = 0; nt < 8; nt++) {
                int p = nt >> 1, o = nt & 1;
                uint32_t b0h = bh[p][o], b1h = bh[p][o + 2];
                uint32_t b0l = bl[p][o], b1l = bl[p][o + 2];
#pragma unroll
                for (int mt = 0; mt < 2; mt++) {
                    mma_bf16(acc[mt][nt], ah[mt], b0h, b1h);
                    mma_bf16(acc[mt][nt], ah[mt], b0l, b1l);
                    mma_bf16(acc[mt][nt], al[mt], b0h, b1h);
                }
            }
        }
        __syncthreads();
    }

#pragma unroll
    for (int mt = 0; mt < 2; mt++) {
#pragma unroll
        for (int nt = 0; nt < 8; nt++) {
            int r0 = bm + mw + mt * 16 + (lane >> 2);
            int col = bn + nw + nt * 8 + (lane & 3) * 2;
            float2 v0 = {acc[mt][nt][0], acc[mt][nt][1]};
            float2 v1 = {acc[mt][nt][2], acc[mt][nt][3]};
            if (EPI == 0) {
                if (bias) {
                    float b0 = bias[col], b1 = bias[col + 1];
                    v0.x += b0; v0.y += b1; v1.x += b0; v1.y += b1;
                }
            } else {
                float2 r0v = *(const float2*)(Rres + (size_t)r0 * N + col);
                float2 r1v = *(const float2*)(Rres + (size_t)(r0 + 8) * N + col);
                v0.x += r0v.x; v0.y += r0v.y;
                v1.x += r1v.x; v1.y += r1v.y;
            }
            *(float2*)(C + (size_t)r0 * N + col) = v0;
            *(float2*)(C + (size_t)(r0 + 8) * N + col) = v1;
        }
    }
}

// ---------------- RoPE + fp16 round-trip ----------------
__global__ void rope_kernel(float* __restrict__ qkv,
                            const float* __restrict__ cp, const float* __restrict__ sp) {
    int s = blockIdx.x, slot = blockIdx.y, d = threadIdx.x;
    float c = cp[s * D + d], sn = sp[s * D + d];
    float* row;
    if (slot < NQ)            row = qkv + (size_t)s * QKVN + slot * D;
    else if (slot < NQ + NKV) row = qkv + (size_t)s * QKVN + QDIM + (slot - NQ) * D;
    else                      row = qkv + (size_t)s * QKVN + QDIM + KVDIM + (slot - NQ - NKV) * D;
    float a = row[d];
    float b = row[d ^ 64];
    float rot = (d < 64) ? -b : b;
    __syncthreads();
    float val;
    if (slot < NQ)            val = a * c + rot * sn;
    else if (slot < NQ + NKV) val = __half2float(__float2half_rn(a * c + rot * sn));
    else                      val = __half2float(__float2half_rn(a));
    row[d] = val;
}

// ---------------- causal flash attention (fp32) ----------------
#define PAD 132
__global__ void attn_kernel(const float* __restrict__ qkv, float* __restrict__ o) {
    extern __shared__ float smf[];
    float* qs = smf;
    float* ks = smf + 32 * PAD;
    float* vs = smf + 2 * 32 * PAD;
    float* ps = smf + 3 * 32 * PAD;

    int bq = blockIdx.x, h = blockIdx.y;
    int kvh = h / (NQ / NKV);
    int tid = threadIdx.x;
    int r = tid >> 3, g = tid & 7;
    int q0 = bq * 32;

#pragma unroll
    for (int j = 0; j < 4; j++) {
        int e = tid + j * 256;
        int row = e >> 5, c4 = (e & 31) << 2;
        float4 t = *(const float4*)(qkv + (size_t)(q0 + row) * QKVN + h * D + c4);
        t.x *= SCALE; t.y *= SCALE; t.z *= SCALE; t.w *= SCALE;
        *(float4*)&qs[row * PAD + c4] = t;
    }

    float m = -1e30f, l = 0.f;
    float acc[16];
#pragma unroll
    for (int i = 0; i < 16; i++) acc[i] = 0.f;

    for (int kt = 0; kt <= bq; kt++) {
        int kk0 = kt * 32;
        __syncthreads();
#pragma unroll
        for (int j = 0; j < 4; j++) {
            int e = tid + j * 256;
            int row = e >> 5, c4 = (e & 31) << 2;
            *(float4*)&ks[row * PAD + c4] =
                *(const float4*)(qkv + (size_t)(kk0 + row) * QKVN + QDIM + kvh * D + c4);
            *(float4*)&vs[row * PAD + c4] =
                *(const float4*)(qkv + (size_t)(kk0 + row) * QKVN + QDIM + KVDIM + kvh * D + c4);
        }
        __syncthreads();

        float sarr[4] = {0.f, 0.f, 0.f, 0.f};
        for (int d = 0; d < D; d += 4) {
            float4 qa = *(const float4*)&qs[r * PAD + d];
#pragma unroll
            for (int jj = 0; jj < 4; jj++) {
                float4 ka = *(const float4*)&ks[(g + jj * 8) * PAD + d];
                sarr[jj] += qa.x * ka.x + qa.y * ka.y + qa.z * ka.z + qa.w * ka.w;
            }
        }
        if (kt == bq) {
#pragma unroll
            for (int jj = 0; jj < 4; jj++)
                if (kk0 + g + jj * 8 > q0 + r) sarr[jj] = -1e30f;
        }
        float tmax = fmaxf(fmaxf(sarr[0], sarr[1]), fmaxf(sarr[2], sarr[3]));
#pragma unroll
        for (int off = 1; off < 8; off <<= 1)
            tmax = fmaxf(tmax, __shfl_xor_sync(0xffffffffu, tmax, off));
        float mnew = fmaxf(m, tmax);
        float corr = __expf(m - mnew);
        float psum = 0.f;
#pragma unroll
        for (int jj = 0; jj < 4; jj++) {
            float p = __expf(sarr[jj] - mnew);
            ps[r * 32 + g + jj * 8] = p;
            psum += p;
        }
#pragma unroll
        for (int off = 1; off < 8; off <<= 1)
            psum += __shfl_xor_sync(0xffffffffu, psum, off);
        l = l * corr + psum;
        m = mnew;
#pragma unroll
        for (int i = 0; i < 16; i++) acc[i] *= corr;
        __syncwarp();
        for (int kk = 0; kk < 32; kk++) {
            float pk = ps[r * 32 + kk];
#pragma unroll
            for (int jj = 0; jj < 4; jj++) {
                float4 vv = *(const float4*)&vs[kk * PAD + g * 4 + jj * 32];
                acc[jj * 4 + 0] += pk * vv.x;
                acc[jj * 4 + 1] += pk * vv.y;
                acc[jj * 4 + 2] += pk * vv.z;
                acc[jj * 4 + 3] += pk * vv.w;
            }
        }
    }
    float inv = 1.0f / l;
#pragma unroll
    for (int jj = 0; jj < 4; jj++) {
        float4 outv = {acc[jj * 4 + 0] * inv, acc[jj * 4 + 1] * inv,
                       acc[jj * 4 + 2] * inv, acc[jj * 4 + 3] * inv};
        *(float4*)(o + (size_t)(q0 + r) * QDIM + h * D + g * 4 + jj * 32) = outv;
    }
}

// ---------------- silu(gate) * up ----------------
__global__ void silu_mul_kernel(const float* __restrict__ gu, float* __restrict__ out) {
    int i = blockIdx.x * 256 + threadIdx.x;
    if (i >= S * IFF / 4) return;
    int m = i / (IFF / 4);
    int c = i % (IFF / 4);
    float4 g = ((const float4*)(gu + (size_t)m * GUN))[c];
    float4 u = ((const float4*)(gu + (size_t)m * GUN + IFF))[c];
    float4 o;
    o.x = g.x / (1.f + __expf(-g.x)) * u.x;
    o.y = g.y / (1.f + __expf(-g.y)) * u.y;
    o.z = g.z / (1.f + __expf(-g.z)) * u.z;
    o.w = g.w / (1.f + __expf(-g.w)) * u.w;
    ((float4*)(out + (size_t)m * IFF))[c] = o;
}

// ---------------- host launch ----------------
extern "C" void kernel_launch(void* const* d_in, const int* in_sizes, int n_in,
                              void* d_out, int out_size) {
    const float* hs   = (const float*)d_in[0];
    const float* cosp = (const float*)d_in[1];
    const float* sinp = (const float*)d_in[2];
    const float* Wq = (const float*)d_in[4];
    const float* bq = (const float*)d_in[5];
    const float* Wk = (const float*)d_in[6];
    const float* bk = (const float*)d_in[7];
    const float* Wv = (const float*)d_in[8];
    const float* bv = (const float*)d_in[9];
    const float* Wo = (const float*)d_in[10];
    const float* Wg = (const float*)d_in[11];
    const float* Wu = (const float*)d_in[12];
    const float* Wd = (const float*)d_in[13];
    const float* ln1 = (const float*)d_in[14];
    const float* ln2 = (const float*)d_in[15];
    const float* fln = (const float*)d_in[16];

    float *p_x, *p_h, *p_qkv, *p_attn, *p_gu, *p_act, *p_bias;
    __nv_bfloat16 *p_thi, *p_tlo;
    cudaGetSymbolAddress((void**)&p_x, g_x);
    cudaGetSymbolAddress((void**)&p_h, g_h);
    cudaGetSymbolAddress((void**)&p_qkv, g_qkv);
    cudaGetSymbolAddress((void**)&p_attn, g_attn);
    cudaGetSymbolAddress((void**)&p_gu, g_gu);
    cudaGetSymbolAddress((void**)&p_act, g_act);
    cudaGetSymbolAddress((void**)&p_bias, g_biasq);
    cudaGetSymbolAddress((void**)&p_thi, g_thi);
    cudaGetSymbolAddress((void**)&p_tlo, g_tlo);

    const int attn_smem = (3 * 32 * PAD + 32 * 32) * 4;
    cudaFuncSetAttribute(attn_kernel, cudaFuncAttributeMaxDynamicSharedMemorySize, attn_smem);
    cudaFuncSetAttribute(wgemm_kernel<0>, cudaFuncAttributeMaxDynamicSharedMemorySize, GEMM_SMEM);
    cudaFuncSetAttribute(wgemm_kernel<1>, cudaFuncAttributeMaxDynamicSharedMemorySize, GEMM_SMEM);

    {
        int n4 = S * H / 4;
        copy_kernel<<<(n4 + 255) / 256, 256>>>((const float4*)hs, (float4*)p_x, n4);
    }

    for (int i = 0; i < LAYERS; i++) {
        const float* Wq_i = Wq + (size_t)i * H * QDIM;
        const float* Wk_i = Wk + (size_t)i * H * KVDIM;
        const float* Wv_i = Wv + (size_t)i * H * KVDIM;
        const float* Wo_i = Wo + (size_t)i * QDIM * H;
        const float* Wg_i = Wg + (size_t)i * H * IFF;
        const float* Wu_i = Wu + (size_t)i * H * IFF;
        const float* Wd_i = Wd + (size_t)i * IFF * H;

        rmsnorm_kernel<<<S, 256>>>(p_x, ln1 + (size_t)i * H, p_h);

        transpose_split_kernel<<<dim3(QDIM / 32, H / 32), 256>>>(Wq_i, H, QDIM, p_thi, p_tlo, 0, H);
        transpose_split_kernel<<<dim3(KVDIM / 32, H / 32), 256>>>(Wk_i, H, KVDIM, p_thi, p_tlo, QDIM, H);
        transpose_split_kernel<<<dim3(KVDIM / 32, H / 32), 256>>>(Wv_i, H, KVDIM, p_thi, p_tlo, QDIM + KVDIM, H);
        concat_bias_kernel<<<QKVN / 256, 256>>>(bq + (size_t)i * QDIM, bk + (size_t)i * KVDIM,
                                                bv + (size_t)i * KVDIM, p_bias);
        wgemm_kernel<0><<<dim3(S / 128, QKVN / 128), 256, GEMM_SMEM>>>(
            p_h, p_thi, p_tlo, p_bias, nullptr, p_qkv, H, QKVN);

        rope_kernel<<<dim3(S, NQ + 2 * NKV), 128>>>(p_qkv, cosp, sinp);
        attn_kernel<<<dim3(S / 32, NQ), 256, attn_smem>>>(p_qkv, p_attn);

        transpose_split_kernel<<<dim3(H / 32, QDIM / 32), 256>>>(Wo_i, QDIM, H, p_thi, p_tlo, 0, QDIM);
        wgemm_kernel<1><<<dim3(S / 128, H / 128), 256, GEMM_SMEM>>>(
            p_attn, p_thi, p_tlo, nullptr, p_x, p_x, QDIM, H);

        rmsnorm_kernel<<<S, 256>>>(p_x, ln2 + (size_t)i * H, p_h);

        transpose_split_kernel<<<dim3(IFF / 32, H / 32), 256>>>(Wg_i, H, IFF, p_thi, p_tlo, 0, H);
        transpose_split_kernel<<<dim3(IFF / 32, H / 32), 256>>>(Wu_i, H, IFF, p_thi, p_tlo, IFF, H);
        wgemm_kernel<0><<<dim3(S / 128, GUN / 128), 256, GEMM_SMEM>>>(
            p_h, p_thi, p_tlo, nullptr, nullptr, p_gu, H, GUN);

        silu_mul_kernel<<<(S * IFF / 4 + 255) / 256, 256>>>(p_gu, p_act);

        transpose_split_kernel<<<dim3(H / 32, IFF / 32), 256>>>(Wd_i, IFF, H, p_thi, p_tlo, 0, IFF);
        wgemm_kernel<1><<<dim3(S / 128, H / 128), 256, GEMM_SMEM>>>(
            p_act, p_thi, p_tlo, nullptr, p_x, p_x, IFF, H);
    }

    rmsnorm_kernel<<<S, 256>>>(p_x, fln, (float*)d_out);
}

// round 6
// speedup vs baseline: 2.5531x; 1.5214x over previous
#include <cuda_runtime.h>
#include <cuda_fp16.h>
#include <cuda_bf16.h>
#include <math.h>
#include <stdint.h>

#define S 2048
#define H 1536
#define NQ 12
#define NKV 2
#define D 128
#define IFF 8960
#define LAYERS 4
#define QDIM (NQ*D)      // 1536
#define KVDIM (NKV*D)    // 256
#define QKVN 2048
#define GUN (2*IFF)      // 17920
#define EPS 1e-6f
#define SCALE 0.08838834764831845f

// ---------------- device scratch (allocation-free) ----------------
__device__ float g_x[S*H];
__device__ float g_h[S*H];
__device__ float g_qkv[S*QKVN];
__device__ float g_attn[S*QDIM];
__device__ float g_gu[(size_t)S*GUN];
__device__ float g_act[(size_t)S*IFF];
__device__ float g_biasq[QKVN];
__device__ __nv_bfloat16 g_thi[(size_t)GUN*H];
__device__ __nv_bfloat16 g_tlo[(size_t)GUN*H];
__device__ __nv_bfloat16 g_ahi[(size_t)S*IFF];
__device__ __nv_bfloat16 g_alo[(size_t)S*IFF];
__device__ __half g_q16h[(size_t)NQ*S*D];
__device__ __half g_q16l[(size_t)NQ*S*D];
__device__ __half g_k16[(size_t)NKV*S*D];
__device__ __half g_v16[(size_t)NKV*S*D];

__device__ __forceinline__ uint32_t pack_bf2(__nv_bfloat16 a, __nv_bfloat16 b) {
    __nv_bfloat162 t; t.x = a; t.y = b;
    return *reinterpret_cast<uint32_t*>(&t);
}
__device__ __forceinline__ uint32_t pack_h2(__half a, __half b) {
    __half2 t; t.x = a; t.y = b;
    return *reinterpret_cast<uint32_t*>(&t);
}
__device__ __forceinline__ uint32_t smem_u32(const void* p) {
    uint32_t a;
    asm("{ .reg .u64 t; cvta.to.shared.u64 t, %1; cvt.u32.u64 %0, t; }" : "=r"(a) : "l"(p));
    return a;
}
__device__ __forceinline__ void mma_bf16(float* d, const uint32_t* a, uint32_t b0, uint32_t b1) {
    asm volatile(
        "mma.sync.aligned.m16n8k16.row.col.f32.bf16.bf16.f32 "
        "{%0,%1,%2,%3}, {%4,%5,%6,%7}, {%8,%9}, {%0,%1,%2,%3};"
        : "+f"(d[0]), "+f"(d[1]), "+f"(d[2]), "+f"(d[3])
        : "r"(a[0]), "r"(a[1]), "r"(a[2]), "r"(a[3]), "r"(b0), "r"(b1));
}
__device__ __forceinline__ void mma_fp16(float* d, const uint32_t* a, uint32_t b0, uint32_t b1) {
    asm volatile(
        "mma.sync.aligned.m16n8k16.row.col.f32.f16.f16.f32 "
        "{%0,%1,%2,%3}, {%4,%5,%6,%7}, {%8,%9}, {%0,%1,%2,%3};"
        : "+f"(d[0]), "+f"(d[1]), "+f"(d[2]), "+f"(d[3])
        : "r"(a[0]), "r"(a[1]), "r"(a[2]), "r"(a[3]), "r"(b0), "r"(b1));
}
__device__ __forceinline__ void ldsm_x4(uint32_t* r, uint32_t addr) {
    asm volatile("ldmatrix.sync.aligned.m8n8.x4.shared.b16 {%0,%1,%2,%3}, [%4];"
        : "=r"(r[0]), "=r"(r[1]), "=r"(r[2]), "=r"(r[3]) : "r"(addr));
}
__device__ __forceinline__ void ldsm_x4t(uint32_t* r, uint32_t addr) {
    asm volatile("ldmatrix.sync.aligned.m8n8.x4.trans.shared.b16 {%0,%1,%2,%3}, [%4];"
        : "=r"(r[0]), "=r"(r[1]), "=r"(r[2]), "=r"(r[3]) : "r"(addr));
}
#define CP_A16(dst, src) asm volatile("cp.async.ca.shared.global [%0], [%1], 16;" :: "r"(dst), "l"(src) : "memory")
#define CP_COMMIT()      asm volatile("cp.async.commit_group;" ::: "memory")
#define CP_WAIT(n)       asm volatile("cp.async.wait_group %0;" :: "n"(n) : "memory")

// ---------------- copy ----------------
__global__ void copy_kernel(const float4* __restrict__ src, float4* __restrict__ dst, int n) {
    int i = blockIdx.x * blockDim.x + threadIdx.x;
    if (i < n) dst[i] = src[i];
}

// ---------------- RMSNorm ----------------
__global__ void rmsnorm_kernel(const float* __restrict__ x, const float* __restrict__ w,
                               float* __restrict__ out) {
    int row = blockIdx.x;
    const float* xr = x + (size_t)row * H;
    float ss = 0.f;
    for (int c = threadIdx.x; c < H; c += 256) { float v = xr[c]; ss += v * v; }
    __shared__ float red[256];
    red[threadIdx.x] = ss;
    __syncthreads();
    for (int off = 128; off > 0; off >>= 1) {
        if (threadIdx.x < off) red[threadIdx.x] += red[threadIdx.x + off];
        __syncthreads();
    }
    float rs = 1.0f / sqrtf(red[0] / (float)H + EPS);
    float* orow = out + (size_t)row * H;
    for (int c = threadIdx.x; c < H; c += 256) orow[c] = xr[c] * rs * w[c];
}

// ---------------- transpose + bf16 split ----------------
__global__ void transpose_split_kernel(const float* __restrict__ W, int K, int Nsrc,
                                       __nv_bfloat16* __restrict__ Th,
                                       __nv_bfloat16* __restrict__ Tl,
                                       int n_off, int ldk) {
    __shared__ float t[32][33];
    int k0 = blockIdx.y * 32, n0 = blockIdx.x * 32;
    int tid = threadIdx.x;
    {
        int rk = tid >> 3, cn = (tid & 7) << 2;
        float4 v = *(const float4*)(W + (size_t)(k0 + rk) * Nsrc + n0 + cn);
        t[rk][cn] = v.x; t[rk][cn + 1] = v.y; t[rk][cn + 2] = v.z; t[rk][cn + 3] = v.w;
    }
    __syncthreads();
    int idx = tid >> 1, arr = tid & 1;
    int n = idx >> 2, seg = (idx & 3) << 3;
    __nv_bfloat16 outv[8];
#pragma unroll
    for (int j = 0; j < 8; j++) {
        float v = t[seg + j][n];
        __nv_bfloat16 h = __float2bfloat16(v);
        outv[j] = arr ? __float2bfloat16(v - __bfloat162float(h)) : h;
    }
    __nv_bfloat16* dst = arr ? Tl : Th;
    *(uint4*)(dst + (size_t)(n_off + n0 + n) * ldk + k0 + seg) = *(uint4*)outv;
}

// ---------------- A split: fp32 -> bf16 hi/lo (coalesced, no transpose) ----------------
__global__ void split_kernel(const float4* __restrict__ X, uint2* __restrict__ Xh,
                             uint2* __restrict__ Xl, int n4) {
    int i = blockIdx.x * 256 + threadIdx.x;
    if (i >= n4) return;
    float4 v = X[i];
    __nv_bfloat16 h0 = __float2bfloat16(v.x), h1 = __float2bfloat16(v.y);
    __nv_bfloat16 h2 = __float2bfloat16(v.z), h3 = __float2bfloat16(v.w);
    __nv_bfloat16 l0 = __float2bfloat16(v.x - __bfloat162float(h0));
    __nv_bfloat16 l1 = __float2bfloat16(v.y - __bfloat162float(h1));
    __nv_bfloat16 l2 = __float2bfloat16(v.z - __bfloat162float(h2));
    __nv_bfloat16 l3 = __float2bfloat16(v.w - __bfloat162float(h3));
    Xh[i] = make_uint2(pack_bf2(h0, h1), pack_bf2(h2, h3));
    Xl[i] = make_uint2(pack_bf2(l0, l1), pack_bf2(l2, l3));
}

// ---------------- bias concat ----------------
__global__ void concat_bias_kernel(const float* bq, const float* bk, const float* bv,
                                   float* out) {
    int i = blockIdx.x * 256 + threadIdx.x;
    if (i < QKVN)
        out[i] = (i < QDIM) ? bq[i] : ((i < QDIM + KVDIM) ? bk[i - QDIM] : bv[i - QDIM - KVDIM]);
}

// ---------------- warp-MMA split-bf16 GEMM (all cp.async + ldmatrix) ----------------
#define APITCH 40
#define STG (128 * APITCH)
#define GEMM_SMEM (2 * 4 * STG * 2)        // 81920 B

template <int EPI>
__global__ void __launch_bounds__(256, 1) wgemm_kernel(
    const __nv_bfloat16* __restrict__ Ah, const __nv_bfloat16* __restrict__ Al,
    const __nv_bfloat16* __restrict__ Bh, const __nv_bfloat16* __restrict__ Bl,
    const float* __restrict__ bias, const float* __restrict__ Rres,
    float* __restrict__ C, int K, int N)
{
    extern __shared__ __nv_bfloat16 sm[];
    uint32_t smb = smem_u32(sm);
    int tid = threadIdx.x;
    int wid = tid >> 5, lane = tid & 31;
    int bm = blockIdx.x * 128, bn = blockIdx.y * 128;
    int mw = (wid & 3) * 32, nw = (wid >> 2) * 64;

    const int KS = K / 32;
    int lrow = tid >> 1;
    int lkp  = (tid & 1) * 16;

    const __nv_bfloat16* Ahp = Ah + (size_t)(bm + lrow) * K + lkp;
    const __nv_bfloat16* Alp = Al + (size_t)(bm + lrow) * K + lkp;
    const __nv_bfloat16* Bhp = Bh + (size_t)(bn + lrow) * K + lkp;
    const __nv_bfloat16* Blp = Bl + (size_t)(bn + lrow) * K + lkp;

    const uint32_t rowoff = (uint32_t)(lrow * APITCH + lkp) * 2;

    auto cpstage = [&](int st, int k0) {
        uint32_t b0 = smb + (uint32_t)(st * 4) * STG * 2 + rowoff;
        CP_A16(b0,                    Ahp + k0);
        CP_A16(b0 + 16,               Ahp + k0 + 8);
        CP_A16(b0 + STG * 2,          Alp + k0);
        CP_A16(b0 + STG * 2 + 16,     Alp + k0 + 8);
        CP_A16(b0 + 2 * STG * 2,      Bhp + k0);
        CP_A16(b0 + 2 * STG * 2 + 16, Bhp + k0 + 8);
        CP_A16(b0 + 3 * STG * 2,      Blp + k0);
        CP_A16(b0 + 3 * STG * 2 + 16, Blp + k0 + 8);
    };

    float acc[2][8][4];
#pragma unroll
    for (int mt = 0; mt < 2; mt++)
#pragma unroll
        for (int nt = 0; nt < 8; nt++)
#pragma unroll
            for (int e = 0; e < 4; e++) acc[mt][nt][e] = 0.f;

    const int frow = lane & 15;
    const int fk   = (lane >> 4) << 3;

    cpstage(0, 0);
    CP_COMMIT();

    for (int ks = 0; ks < KS; ks++) {
        int st = ks & 1;
        if (ks + 1 < KS) {
            cpstage(st ^ 1, (ks + 1) * 32);
            CP_COMMIT();
            CP_WAIT(1);
        } else {
            CP_WAIT(0);
        }
        __syncthreads();

        uint32_t Ah32 = smb + (uint32_t)(st * 4 + 0) * STG * 2;
        uint32_t Al32 = smb + (uint32_t)(st * 4 + 1) * STG * 2;
        uint32_t Bh32 = smb + (uint32_t)(st * 4 + 2) * STG * 2;
        uint32_t Bl32 = smb + (uint32_t)(st * 4 + 3) * STG * 2;

#pragma unroll
        for (int kk = 0; kk < 32; kk += 16) {
            int ko = kk + fk;
            uint32_t ah[2][4], al[2][4];
#pragma unroll
            for (int mt = 0; mt < 2; mt++) {
                uint32_t off = (uint32_t)((mw + mt * 16 + frow) * APITCH + ko) * 2;
                ldsm_x4(ah[mt], Ah32 + off);
                ldsm_x4(al[mt], Al32 + off);
            }
            uint32_t bh[4][4], bl[4][4];
#pragma unroll
            for (int p = 0; p < 4; p++) {
                uint32_t off = (uint32_t)((nw + p * 16 + frow) * APITCH + ko) * 2;
                ldsm_x4(bh[p], Bh32 + off);
                ldsm_x4(bl[p], Bl32 + off);
            }
#pragma unroll
            for (int nt = 0; nt < 8; nt++) {
                int p = nt >> 1, o = nt & 1;
                uint32_t b0h = bh[p][o], b1h = bh[p][o + 2];
                uint32_t b0l = bl[p][o], b1l = bl[p][o + 2];
#pragma unroll
                for (int mt = 0; mt < 2; mt++) {
                    mma_bf16(acc[mt][nt], ah[mt], b0h, b1h);
                    mma_bf16(acc[mt][nt], ah[mt], b0l, b1l);
                    mma_bf16(acc[mt][nt], al[mt], b0h, b1h);
                }
            }
        }
        __syncthreads();
    }

#pragma unroll
    for (int mt = 0; mt < 2; mt++) {
#pragma unroll
        for (int nt = 0; nt < 8; nt++) {
            int r0 = bm + mw + mt * 16 + (lane >> 2);
            int col = bn + nw + nt * 8 + (lane & 3) * 2;
            float2 v0 = {acc[mt][nt][0], acc[mt][nt][1]};
            float2 v1 = {acc[mt][nt][2], acc[mt][nt][3]};
            if (EPI == 0) {
                if (bias) {
                    float b0 = bias[col], b1 = bias[col + 1];
                    v0.x += b0; v0.y += b1; v1.x += b0; v1.y += b1;
                }
            } else {
                float2 r0v = *(const float2*)(Rres + (size_t)r0 * N + col);
                float2 r1v = *(const float2*)(Rres + (size_t)(r0 + 8) * N + col);
                v0.x += r0v.x; v0.y += r0v.y;
                v1.x += r1v.x; v1.y += r1v.y;
            }
            *(float2*)(C + (size_t)r0 * N + col) = v0;
            *(float2*)(C + (size_t)(r0 + 8) * N + col) = v1;
        }
    }
}

// ---------------- RoPE -> fp16 Q split + fp16 K/V ----------------
__global__ void rope16_kernel(const float* __restrict__ qkv,
                              const float* __restrict__ cp, const float* __restrict__ sp,
                              __half* __restrict__ qh, __half* __restrict__ ql,
                              __half* __restrict__ k16, __half* __restrict__ v16) {
    int s = blockIdx.x, slot = blockIdx.y, d = threadIdx.x;
    float c = cp[s * D + d], sn = sp[s * D + d];
    const float* row;
    if (slot < NQ)            row = qkv + (size_t)s * QKVN + slot * D;
    else if (slot < NQ + NKV) row = qkv + (size_t)s * QKVN + QDIM + (slot - NQ) * D;
    else                      row = qkv + (size_t)s * QKVN + QDIM + KVDIM + (slot - NQ - NKV) * D;
    float a = row[d];
    float b = row[d ^ 64];
    float rot = (d < 64) ? -b : b;
    if (slot < NQ) {
        float val = a * c + rot * sn;
        __half hv = __float2half_rn(val);
        __half lv = __float2half_rn(val - __half2float(hv));
        size_t o = ((size_t)slot * S + s) * D + d;
        qh[o] = hv; ql[o] = lv;
    } else if (slot < NQ + NKV) {
        float val = a * c + rot * sn;
        k16[((size_t)(slot - NQ) * S + s) * D + d] = __float2half_rn(val);
    } else {
        v16[((size_t)(slot - NQ - NKV) * S + s) * D + d] = __float2half_rn(a);
    }
}

// ---------------- tensor-core causal flash attention ----------------
// BM=128 queries, BN=32 keys, 8 warps (16 q rows each), fp16 MMA.
#define PKV 136
#define ATT_SMEM (128 * PKV * 2)   // 34816 B (Q staging reused as K/V double buffers)

__global__ void __launch_bounds__(256, 1) attn_kernel(
    const __half* __restrict__ qh, const __half* __restrict__ ql,
    const __half* __restrict__ k16, const __half* __restrict__ v16,
    float* __restrict__ o)
{
    extern __shared__ __half sma[];
    uint32_t smb = smem_u32(sma);
    int tid = threadIdx.x, wid = tid >> 5, lane = tid & 31;
    int bq = (int)gridDim.x - 1 - (int)blockIdx.x;   // big blocks first
    int h = blockIdx.y;
    int kvh = h / (NQ / NKV);
    int q0 = bq * 128;
    int wq0 = wid * 16;

    const int frow = lane & 15, fk8 = (lane >> 4) << 3;

    // ---- stage Qh, Ql; hold fragments in registers ----
    uint32_t qfh[8][4], qfl[8][4];
    {
        int row = tid >> 1, coff = (tid & 1) * 64;
        __half* dst = sma + row * PKV + coff;
        const __half* src = qh + ((size_t)h * S + q0 + row) * D + coff;
#pragma unroll
        for (int j = 0; j < 8; j++) *(uint4*)(dst + j * 8) = *(const uint4*)(src + j * 8);
        __syncthreads();
#pragma unroll
        for (int kd = 0; kd < 8; kd++)
            ldsm_x4(qfh[kd], smb + (uint32_t)((wq0 + frow) * PKV + kd * 16 + fk8) * 2);
        __syncthreads();
        const __half* src2 = ql + ((size_t)h * S + q0 + row) * D + coff;
#pragma unroll
        for (int j = 0; j < 8; j++) *(uint4*)(dst + j * 8) = *(const uint4*)(src2 + j * 8);
        __syncthreads();
#pragma unroll
        for (int kd = 0; kd < 8; kd++)
            ldsm_x4(qfl[kd], smb + (uint32_t)((wq0 + frow) * PKV + kd * 16 + fk8) * 2);
        __syncthreads();
    }

    // K/V double buffers in the same smem: K st: rows [st*32, ..), V: rows [64+st*32, ..)
    auto cp_kv = [&](int st, int kt) {
        int row = tid >> 3, c16 = (tid & 7) * 16;
        const __half* ksrc = k16 + ((size_t)kvh * S + kt * 32 + row) * D + c16;
        const __half* vsrc = v16 + ((size_t)kvh * S + kt * 32 + row) * D + c16;
        uint32_t kdst = smb + (uint32_t)((st * 32 + row) * PKV + c16) * 2;
        uint32_t vdst = smb + (uint32_t)((64 + st * 32 + row) * PKV + c16) * 2;
        CP_A16(kdst, ksrc); CP_A16(kdst + 16, ksrc + 8);
        CP_A16(vdst, vsrc); CP_A16(vdst + 16, vsrc + 8);
    };

    float oacc[16][4];
#pragma unroll
    for (int nt = 0; nt < 16; nt++)
#pragma unroll
        for (int e = 0; e < 4; e++) oacc[nt][e] = 0.f;
    float mrow0 = -1e30f, mrow1 = -1e30f, lrow0 = 0.f, lrow1 = 0.f;

    const int nk = 4 * bq + 4;
    cp_kv(0, 0);
    CP_COMMIT();

    for (int kt = 0; kt < nk; kt++) {
        int st = kt & 1;
        if (kt + 1 < nk) {
            cp_kv(st ^ 1, kt + 1);
            CP_COMMIT();
            CP_WAIT(1);
        } else {
            CP_WAIT(0);
        }
        __syncthreads();

        // ---- QK: scores for 16 rows x 32 keys (2 passes) ----
        float sc[4][4];
#pragma unroll
        for (int nt = 0; nt < 4; nt++)
#pragma unroll
            for (int e = 0; e < 4; e++) sc[nt][e] = 0.f;
        uint32_t kbase = smb + (uint32_t)(st * 32 * PKV) * 2;
#pragma unroll
        for (int kd = 0; kd < 8; kd++) {
            uint32_t bf0[4], bf1[4];
            ldsm_x4(bf0, kbase + (uint32_t)(frow * PKV + kd * 16 + fk8) * 2);
            ldsm_x4(bf1, kbase + (uint32_t)((16 + frow) * PKV + kd * 16 + fk8) * 2);
            mma_fp16(sc[0], qfh[kd], bf0[0], bf0[2]);
            mma_fp16(sc[1], qfh[kd], bf0[1], bf0[3]);
            mma_fp16(sc[2], qfh[kd], bf1[0], bf1[2]);
            mma_fp16(sc[3], qfh[kd], bf1[1], bf1[3]);
            mma_fp16(sc[0], qfl[kd], bf0[0], bf0[2]);
            mma_fp16(sc[1], qfl[kd], bf0[1], bf0[3]);
            mma_fp16(sc[2], qfl[kd], bf1[0], bf1[2]);
            mma_fp16(sc[3], qfl[kd], bf1[1], bf1[3]);
        }
        // scale + causal mask
        int r_lo = q0 + wq0 + (lane >> 2);
        if (kt >= 4 * bq) {
            int kk0 = kt * 32;
#pragma unroll
            for (int nt = 0; nt < 4; nt++) {
                int kc = kk0 + nt * 8 + (lane & 3) * 2;
#pragma unroll
                for (int e = 0; e < 4; e++) {
                    int key = kc + (e & 1);
                    int row = r_lo + ((e >> 1) << 3);
                    sc[nt][e] = (key > row) ? -1e30f : sc[nt][e] * SCALE;
                }
            }
        } else {
#pragma unroll
            for (int nt = 0; nt < 4; nt++)
#pragma unroll
                for (int e = 0; e < 4; e++) sc[nt][e] *= SCALE;
        }
        // row max (2 row groups), reduce across 4 lanes of the quad
        float mx0 = -1e30f, mx1 = -1e30f;
#pragma unroll
        for (int nt = 0; nt < 4; nt++) {
            mx0 = fmaxf(mx0, fmaxf(sc[nt][0], sc[nt][1]));
            mx1 = fmaxf(mx1, fmaxf(sc[nt][2], sc[nt][3]));
        }
        mx0 = fmaxf(mx0, __shfl_xor_sync(0xffffffffu, mx0, 1));
        mx0 = fmaxf(mx0, __shfl_xor_sync(0xffffffffu, mx0, 2));
        mx1 = fmaxf(mx1, __shfl_xor_sync(0xffffffffu, mx1, 1));
        mx1 = fmaxf(mx1, __shfl_xor_sync(0xffffffffu, mx1, 2));
        float mn0 = fmaxf(mrow0, mx0), mn1 = fmaxf(mrow1, mx1);
        float c0 = __expf(mrow0 - mn0), c1 = __expf(mrow1 - mn1);
        mrow0 = mn0; mrow1 = mn1;
        // probabilities + fp16 hi/lo split
        uint32_t pah[2][4], pal[2][4];
        float ps0 = 0.f, ps1 = 0.f;
#pragma unroll
        for (int b = 0; b < 2; b++) {
            float p00, p01, p10, p11, q00, q01, q10, q11;
            {
                int t0 = b * 2, t1 = b * 2 + 1;
                p00 = __expf(sc[t0][0] - mn0); p01 = __expf(sc[t0][1] - mn0);
                p10 = __expf(sc[t0][2] - mn1); p11 = __expf(sc[t0][3] - mn1);
                q00 = __expf(sc[t1][0] - mn0); q01 = __expf(sc[t1][1] - mn0);
                q10 = __expf(sc[t1][2] - mn1); q11 = __expf(sc[t1][3] - mn1);
            }
            ps0 += p00 + p01 + q00 + q01;
            ps1 += p10 + p11 + q10 + q11;
            __half h00 = __float2half_rn(p00), h01 = __float2half_rn(p01);
            __half h10 = __float2half_rn(p10), h11 = __float2half_rn(p11);
            __half g00 = __float2half_rn(q00), g01 = __float2half_rn(q01);
            __half g10 = __float2half_rn(q10), g11 = __float2half_rn(q11);
            pah[b][0] = pack_h2(h00, h01);
            pah[b][1] = pack_h2(h10, h11);
            pah[b][2] = pack_h2(g00, g01);
            pah[b][3] = pack_h2(g10, g11);
            pal[b][0] = pack_h2(__float2half_rn(p00 - __half2float(h00)),
                                __float2half_rn(p01 - __half2float(h01)));
            pal[b][1] = pack_h2(__float2half_rn(p10 - __half2float(h10)),
                                __float2half_rn(p11 - __half2float(h11)));
            pal[b][2] = pack_h2(__float2half_rn(q00 - __half2float(g00)),
                                __float2half_rn(q01 - __half2float(g01)));
            pal[b][3] = pack_h2(__float2half_rn(q10 - __half2float(g10)),
                                __float2half_rn(q11 - __half2float(g11)));
        }
        ps0 += __shfl_xor_sync(0xffffffffu, ps0, 1);
        ps0 += __shfl_xor_sync(0xffffffffu, ps0, 2);
        ps1 += __shfl_xor_sync(0xffffffffu, ps1, 1);
        ps1 += __shfl_xor_sync(0xffffffffu, ps1, 2);
        lrow0 = lrow0 * c0 + ps0;
        lrow1 = lrow1 * c1 + ps1;
        // rescale output accumulators
#pragma unroll
        for (int nt = 0; nt < 16; nt++) {
            oacc[nt][0] *= c0; oacc[nt][1] *= c0;
            oacc[nt][2] *= c1; oacc[nt][3] *= c1;
        }
        // ---- PV (2 passes: P_hi, P_lo) ----
        uint32_t vbase = smb + (uint32_t)((64 + st * 32) * PKV) * 2;
        int loc = lane & 7, li = lane >> 3;
#pragma unroll
        for (int dp = 0; dp < 8; dp++) {
            uint32_t vf0[4], vf1[4];
            uint32_t col = dp * 16 + (li >> 1) * 8;
            ldsm_x4t(vf0, vbase + (uint32_t)(((li & 1) * 8 + loc) * PKV + col) * 2);
            ldsm_x4t(vf1, vbase + (uint32_t)((16 + (li & 1) * 8 + loc) * PKV + col) * 2);
            mma_fp16(oacc[dp * 2],     pah[0], vf0[0], vf0[1]);
            mma_fp16(oacc[dp * 2 + 1], pah[0], vf0[2], vf0[3]);
            mma_fp16(oacc[dp * 2],     pah[1], vf1[0], vf1[1]);
            mma_fp16(oacc[dp * 2 + 1], pah[1], vf1[2], vf1[3]);
            mma_fp16(oacc[dp * 2],     pal[0], vf0[0], vf0[1]);
            mma_fp16(oacc[dp * 2 + 1], pal[0], vf0[2], vf0[3]);
            mma_fp16(oacc[dp * 2],     pal[1], vf1[0], vf1[1]);
            mma_fp16(oacc[dp * 2 + 1], pal[1], vf1[2], vf1[3]);
        }
        __syncthreads();
    }

    float inv0 = 1.0f / lrow0, inv1 = 1.0f / lrow1;
    int r = q0 + wq0 + (lane >> 2);
    int cbase = h * D + (lane & 3) * 2;
#pragma unroll
    for (int nt = 0; nt < 16; nt++) {
        int c = cbase + nt * 8;
        float2 v0 = {oacc[nt][0] * inv0, oacc[nt][1] * inv0};
        float2 v1 = {oacc[nt][2] * inv1, oacc[nt][3] * inv1};
        *(float2*)&o[(size_t)r * QDIM + c] = v0;
        *(float2*)&o[(size_t)(r + 8) * QDIM + c] = v1;
    }
}

// ---------------- silu(gate) * up ----------------
__global__ void silu_mul_kernel(const float* __restrict__ gu, float* __restrict__ out) {
    int i = blockIdx.x * 256 + threadIdx.x;
    if (i >= S * IFF / 4) return;
    int m = i / (IFF / 4);
    int c = i % (IFF / 4);
    float4 g = ((const float4*)(gu + (size_t)m * GUN))[c];
    float4 u = ((const float4*)(gu + (size_t)m * GUN + IFF))[c];
    float4 o;
    o.x = g.x / (1.f + __expf(-g.x)) * u.x;
    o.y = g.y / (1.f + __expf(-g.y)) * u.y;
    o.z = g.z / (1.f + __expf(-g.z)) * u.z;
    o.w = g.w / (1.f + __expf(-g.w)) * u.w;
    ((float4*)(out + (size_t)m * IFF))[c] = o;
}

// ---------------- host launch ----------------
extern "C" void kernel_launch(void* const* d_in, const int* in_sizes, int n_in,
                              void* d_out, int out_size) {
    const float* hs   = (const float*)d_in[0];
    const float* cosp = (const float*)d_in[1];
    const float* sinp = (const float*)d_in[2];
    const float* Wq = (const float*)d_in[4];
    const float* bq = (const float*)d_in[5];
    const float* Wk = (const float*)d_in[6];
    const float* bk = (const float*)d_in[7];
    const float* Wv = (const float*)d_in[8];
    const float* bv = (const float*)d_in[9];
    const float* Wo = (const float*)d_in[10];
    const float* Wg = (const float*)d_in[11];
    const float* Wu = (const float*)d_in[12];
    const float* Wd = (const float*)d_in[13];
    const float* ln1 = (const float*)d_in[14];
    const float* ln2 = (const float*)d_in[15];
    const float* fln = (const float*)d_in[16];

    float *p_x, *p_h, *p_qkv, *p_attn, *p_gu, *p_act, *p_bias;
    __nv_bfloat16 *p_thi, *p_tlo, *p_ahi, *p_alo;
    __half *p_qh, *p_ql, *p_k16, *p_v16;
    cudaGetSymbolAddress((void**)&p_x, g_x);
    cudaGetSymbolAddress((void**)&p_h, g_h);
    cudaGetSymbolAddress((void**)&p_qkv, g_qkv);
    cudaGetSymbolAddress((void**)&p_attn, g_attn);
    cudaGetSymbolAddress((void**)&p_gu, g_gu);
    cudaGetSymbolAddress((void**)&p_act, g_act);
    cudaGetSymbolAddress((void**)&p_bias, g_biasq);
    cudaGetSymbolAddress((void**)&p_thi, g_thi);
    cudaGetSymbolAddress((void**)&p_tlo, g_tlo);
    cudaGetSymbolAddress((void**)&p_ahi, g_ahi);
    cudaGetSymbolAddress((void**)&p_alo, g_alo);
    cudaGetSymbolAddress((void**)&p_qh, g_q16h);
    cudaGetSymbolAddress((void**)&p_ql, g_q16l);
    cudaGetSymbolAddress((void**)&p_k16, g_k16);
    cudaGetSymbolAddress((void**)&p_v16, g_v16);

    cudaFuncSetAttribute(attn_kernel, cudaFuncAttributeMaxDynamicSharedMemorySize, ATT_SMEM);
    cudaFuncSetAttribute(wgemm_kernel<0>, cudaFuncAttributeMaxDynamicSharedMemorySize, GEMM_SMEM);
    cudaFuncSetAttribute(wgemm_kernel<1>, cudaFuncAttributeMaxDynamicSharedMemorySize, GEMM_SMEM);

    {
        int n4 = S * H / 4;
        copy_kernel<<<(n4 + 255) / 256, 256>>>((const float4*)hs, (float4*)p_x, n4);
    }

    for (int i = 0; i < LAYERS; i++) {
        const float* Wq_i = Wq + (size_t)i * H * QDIM;
        const float* Wk_i = Wk + (size_t)i * H * KVDIM;
        const float* Wv_i = Wv + (size_t)i * H * KVDIM;
        const float* Wo_i = Wo + (size_t)i * QDIM * H;
        const float* Wg_i = Wg + (size_t)i * H * IFF;
        const float* Wu_i = Wu + (size_t)i * H * IFF;
        const float* Wd_i = Wd + (size_t)i * IFF * H;

        rmsnorm_kernel<<<S, 256>>>(p_x, ln1 + (size_t)i * H, p_h);
        split_kernel<<<(S * H / 4 + 255) / 256, 256>>>(
            (const float4*)p_h, (uint2*)p_ahi, (uint2*)p_alo, S * H / 4);

        transpose_split_kernel<<<dim3(QDIM / 32, H / 32), 256>>>(Wq_i, H, QDIM, p_thi, p_tlo, 0, H);
        transpose_split_kernel<<<dim3(KVDIM / 32, H / 32), 256>>>(Wk_i, H, KVDIM, p_thi, p_tlo, QDIM, H);
        transpose_split_kernel<<<dim3(KVDIM / 32, H / 32), 256>>>(Wv_i, H, KVDIM, p_thi, p_tlo, QDIM + KVDIM, H);
        concat_bias_kernel<<<QKVN / 256, 256>>>(bq + (size_t)i * QDIM, bk + (size_t)i * KVDIM,
                                                bv + (size_t)i * KVDIM, p_bias);
        wgemm_kernel<0><<<dim3(S / 128, QKVN / 128), 256, GEMM_SMEM>>>(
            p_ahi, p_alo, p_thi, p_tlo, p_bias, nullptr, p_qkv, H, QKVN);

        rope16_kernel<<<dim3(S, NQ + 2 * NKV), 128>>>(p_qkv, cosp, sinp, p_qh, p_ql, p_k16, p_v16);
        attn_kernel<<<dim3(S / 128, NQ), 256, ATT_SMEM>>>(p_qh, p_ql, p_k16, p_v16, p_attn);

        transpose_split_kernel<<<dim3(H / 32, QDIM / 32), 256>>>(Wo_i, QDIM, H, p_thi, p_tlo, 0, QDIM);
        split_kernel<<<(S * QDIM / 4 + 255) / 256, 256>>>(
            (const float4*)p_attn, (uint2*)p_ahi, (uint2*)p_alo, S * QDIM / 4);
        wgemm_kernel<1><<<dim3(S / 128, H / 128), 256, GEMM_SMEM>>>(
            p_ahi, p_alo, p_thi, p_tlo, nullptr, p_x, p_x, QDIM, H);

        rmsnorm_kernel<<<S, 256>>>(p_x, ln2 + (size_t)i * H, p_h);
        split_kernel<<<(S * H / 4 + 255) / 256, 256>>>(
            (const float4*)p_h, (uint2*)p_ahi, (uint2*)p_alo, S * H / 4);

        transpose_split_kernel<<<dim3(IFF / 32, H / 32), 256>>>(Wg_i, H, IFF, p_thi, p_tlo, 0, H);
        transpose_split_kernel<<<dim3(IFF / 32, H / 32), 256>>>(Wu_i, H, IFF, p_thi, p_tlo, IFF, H);
        wgemm_kernel<0><<<dim3(S / 128, GUN / 128), 256, GEMM_SMEM>>>(
            p_ahi, p_alo, p_thi, p_tlo, nullptr, nullptr, p_gu, H, GUN);

        silu_mul_kernel<<<(S * IFF / 4 + 255) / 256, 256>>>(p_gu, p_act);
        split_kernel<<<(S * IFF / 4 + 255) / 256, 256>>>(
            (const float4*)p_act, (uint2*)p_ahi, (uint2*)p_alo, S * IFF / 4);

        transpose_split_kernel<<<dim3(H / 32, IFF / 32), 256>>>(Wd_i, IFF, H, p_thi, p_tlo, 0, IFF);
        wgemm_kernel<1><<<dim3(S / 128, H / 128), 256, GEMM_SMEM>>>(
            p_ahi, p_alo, p_thi, p_tlo, nullptr, p_x, p_x, IFF, H);
    }

    rmsnorm_kernel<<<S, 256>>>(p_x, fln, (float*)d_out);
}

// round 7
// speedup vs baseline: 2.8844x; 1.1297x over previous
#include <cuda_runtime.h>
#include <cuda_fp16.h>
#include <cuda_bf16.h>
#include <math.h>
#include <stdint.h>

#define S 2048
#define H 1536
#define NQ 12
#define NKV 2
#define D 128
#define IFF 8960
#define LAYERS 4
#define QDIM (NQ*D)      // 1536
#define KVDIM (NKV*D)    // 256
#define QKVN 2048
#define GUN (2*IFF)      // 17920
#define EPS 1e-6f
#define SCALE 0.08838834764831845f

// ---------------- device scratch (allocation-free) ----------------
__device__ float g_x[S*H];
__device__ float g_qkv[S*QKVN];
__device__ float g_biasq[QKVN];
__device__ __nv_bfloat16 g_whi[(size_t)H*GUN];
__device__ __nv_bfloat16 g_wlo[(size_t)H*GUN];
__device__ __nv_bfloat16 g_ahi[(size_t)S*H];
__device__ __nv_bfloat16 g_alo[(size_t)S*H];
__device__ __nv_bfloat16 g_bhi[(size_t)S*IFF];
__device__ __nv_bfloat16 g_blo[(size_t)S*IFF];
__device__ __half g_q16h[(size_t)NQ*S*D];
__device__ __half g_q16l[(size_t)NQ*S*D];
__device__ __half g_k16[(size_t)NKV*S*D];
__device__ __half g_v16[(size_t)NKV*S*D];

__device__ __forceinline__ uint32_t pack_bf2(__nv_bfloat16 a, __nv_bfloat16 b) {
    __nv_bfloat162 t; t.x = a; t.y = b;
    return *reinterpret_cast<uint32_t*>(&t);
}
__device__ __forceinline__ uint32_t pack_h2(__half a, __half b) {
    __half2 t; t.x = a; t.y = b;
    return *reinterpret_cast<uint32_t*>(&t);
}
__device__ __forceinline__ uint32_t smem_u32(const void* p) {
    uint32_t a;
    asm("{ .reg .u64 t; cvta.to.shared.u64 t, %1; cvt.u32.u64 %0, t; }" : "=r"(a) : "l"(p));
    return a;
}
__device__ __forceinline__ void mma_bf16(float* d, const uint32_t* a, uint32_t b0, uint32_t b1) {
    asm volatile(
        "mma.sync.aligned.m16n8k16.row.col.f32.bf16.bf16.f32 "
        "{%0,%1,%2,%3}, {%4,%5,%6,%7}, {%8,%9}, {%0,%1,%2,%3};"
        : "+f"(d[0]), "+f"(d[1]), "+f"(d[2]), "+f"(d[3])
        : "r"(a[0]), "r"(a[1]), "r"(a[2]), "r"(a[3]), "r"(b0), "r"(b1));
}
__device__ __forceinline__ void mma_fp16(float* d, const uint32_t* a, uint32_t b0, uint32_t b1) {
    asm volatile(
        "mma.sync.aligned.m16n8k16.row.col.f32.f16.f16.f32 "
        "{%0,%1,%2,%3}, {%4,%5,%6,%7}, {%8,%9}, {%0,%1,%2,%3};"
        : "+f"(d[0]), "+f"(d[1]), "+f"(d[2]), "+f"(d[3])
        : "r"(a[0]), "r"(a[1]), "r"(a[2]), "r"(a[3]), "r"(b0), "r"(b1));
}
__device__ __forceinline__ void ldsm_x4(uint32_t* r, uint32_t addr) {
    asm volatile("ldmatrix.sync.aligned.m8n8.x4.shared.b16 {%0,%1,%2,%3}, [%4];"
        : "=r"(r[0]), "=r"(r[1]), "=r"(r[2]), "=r"(r[3]) : "r"(addr));
}
__device__ __forceinline__ void ldsm_x4t(uint32_t* r, uint32_t addr) {
    asm volatile("ldmatrix.sync.aligned.m8n8.x4.trans.shared.b16 {%0,%1,%2,%3}, [%4];"
        : "=r"(r[0]), "=r"(r[1]), "=r"(r[2]), "=r"(r[3]) : "r"(addr));
}
#define CP_A16(dst, src) asm volatile("cp.async.ca.shared.global [%0], [%1], 16;" :: "r"(dst), "l"(src) : "memory")
#define CP_COMMIT()      asm volatile("cp.async.commit_group;" ::: "memory")
#define CP_WAIT(n)       asm volatile("cp.async.wait_group %0;" :: "n"(n) : "memory")

// ---------------- copy ----------------
__global__ void copy_kernel(const float4* __restrict__ src, float4* __restrict__ dst, int n) {
    int i = blockIdx.x * blockDim.x + threadIdx.x;
    if (i < n) dst[i] = src[i];
}

// ---------------- RMSNorm (fp32 out, final only) ----------------
__global__ void rmsnorm_kernel(const float* __restrict__ x, const float* __restrict__ w,
                               float* __restrict__ out) {
    int row = blockIdx.x;
    const float* xr = x + (size_t)row * H;
    float ss = 0.f;
    for (int c = threadIdx.x; c < H; c += 256) { float v = xr[c]; ss += v * v; }
    __shared__ float red[256];
    red[threadIdx.x] = ss;
    __syncthreads();
    for (int off = 128; off > 0; off >>= 1) {
        if (threadIdx.x < off) red[threadIdx.x] += red[threadIdx.x + off];
        __syncthreads();
    }
    float rs = 1.0f / sqrtf(red[0] / (float)H + EPS);
    float* orow = out + (size_t)row * H;
    for (int c = threadIdx.x; c < H; c += 256) orow[c] = xr[c] * rs * w[c];
}

// ---------------- RMSNorm fused bf16 hi/lo split ----------------
__global__ void rmsnorm_split_kernel(const float* __restrict__ x, const float* __restrict__ w,
                                     __nv_bfloat16* __restrict__ oh, __nv_bfloat16* __restrict__ ol) {
    int row = blockIdx.x;
    const float* xr = x + (size_t)row * H;
    float ss = 0.f;
    for (int c = threadIdx.x; c < H; c += 256) { float v = xr[c]; ss += v * v; }
    __shared__ float red[256];
    red[threadIdx.x] = ss;
    __syncthreads();
    for (int off = 128; off > 0; off >>= 1) {
        if (threadIdx.x < off) red[threadIdx.x] += red[threadIdx.x + off];
        __syncthreads();
    }
    float rs = 1.0f / sqrtf(red[0] / (float)H + EPS);
    for (int c = threadIdx.x * 2; c < H; c += 512) {
        float v0 = xr[c] * rs * w[c];
        float v1 = xr[c + 1] * rs * w[c + 1];
        __nv_bfloat16 h0 = __float2bfloat16(v0), h1 = __float2bfloat16(v1);
        __nv_bfloat16 l0 = __float2bfloat16(v0 - __bfloat162float(h0));
        __nv_bfloat16 l1 = __float2bfloat16(v1 - __bfloat162float(h1));
        *(uint32_t*)(oh + (size_t)row * H + c) = pack_bf2(h0, h1);
        *(uint32_t*)(ol + (size_t)row * H + c) = pack_bf2(l0, l1);
    }
}

// ---------------- weight split (streaming, no transpose) ----------------
// W[K,Ncols] fp32 -> Th/Tl[k*ldn + coff + n] bf16
__global__ void wsplit_kernel(const float* __restrict__ W, int total4, int nc4,
                              __nv_bfloat16* __restrict__ Th, __nv_bfloat16* __restrict__ Tl,
                              int coff, int ldn) {
    int i = blockIdx.x * 256 + threadIdx.x;
    if (i >= total4) return;
    int k = i / nc4;
    int n = (i - k * nc4) * 4;
    float4 v = *(const float4*)(W + (size_t)k * (nc4 * 4) + n);
    __nv_bfloat16 h0 = __float2bfloat16(v.x), h1 = __float2bfloat16(v.y);
    __nv_bfloat16 h2 = __float2bfloat16(v.z), h3 = __float2bfloat16(v.w);
    __nv_bfloat16 l0 = __float2bfloat16(v.x - __bfloat162float(h0));
    __nv_bfloat16 l1 = __float2bfloat16(v.y - __bfloat162float(h1));
    __nv_bfloat16 l2 = __float2bfloat16(v.z - __bfloat162float(h2));
    __nv_bfloat16 l3 = __float2bfloat16(v.w - __bfloat162float(h3));
    size_t o = (size_t)k * ldn + coff + n;
    *(uint2*)(Th + o) = make_uint2(pack_bf2(h0, h1), pack_bf2(h2, h3));
    *(uint2*)(Tl + o) = make_uint2(pack_bf2(l0, l1), pack_bf2(l2, l3));
}

// gate/up interleaved at 32 cols: dst col = (n/32)*64 + n%32 + up*32
__global__ void wsplit_gu_kernel(const float* __restrict__ W, int up,
                                 __nv_bfloat16* __restrict__ Th, __nv_bfloat16* __restrict__ Tl) {
    int i = blockIdx.x * 256 + threadIdx.x;
    if (i >= H * IFF / 4) return;
    int k = i / (IFF / 4);
    int n = (i - k * (IFF / 4)) * 4;
    float4 v = *(const float4*)(W + (size_t)k * IFF + n);
    __nv_bfloat16 h0 = __float2bfloat16(v.x), h1 = __float2bfloat16(v.y);
    __nv_bfloat16 h2 = __float2bfloat16(v.z), h3 = __float2bfloat16(v.w);
    __nv_bfloat16 l0 = __float2bfloat16(v.x - __bfloat162float(h0));
    __nv_bfloat16 l1 = __float2bfloat16(v.y - __bfloat162float(h1));
    __nv_bfloat16 l2 = __float2bfloat16(v.z - __bfloat162float(h2));
    __nv_bfloat16 l3 = __float2bfloat16(v.w - __bfloat162float(h3));
    int c = ((n >> 5) << 6) + (n & 31) + up * 32;
    size_t o = (size_t)k * GUN + c;
    *(uint2*)(Th + o) = make_uint2(pack_bf2(h0, h1), pack_bf2(h2, h3));
    *(uint2*)(Tl + o) = make_uint2(pack_bf2(l0, l1), pack_bf2(l2, l3));
}

// ---------------- bias concat ----------------
__global__ void concat_bias_kernel(const float* bq, const float* bk, const float* bv,
                                   float* out) {
    int i = blockIdx.x * 256 + threadIdx.x;
    if (i < QKVN)
        out[i] = (i < QDIM) ? bq[i] : ((i < QDIM + KVDIM) ? bk[i - QDIM] : bv[i - QDIM - KVDIM]);
}

// ---------------- warp-MMA split-bf16 GEMM, 3-stage cp.async, trans-B ----------------
// C[M,N] = A[M,K] @ B[K,N], A/B pre-split bf16 hi/lo. 3 MMA passes.
// EPI 0: fp32 C += bias; EPI 1: fp32 C = acc + R; EPI 2: silu(gate)*up -> bf16 hi/lo (Nout cols)
#define APITCH 40
#define PB 136
#define A_BYTES (128 * APITCH * 2)   // 10240
#define B_BYTES (32 * PB * 2)        // 8704
#define STAGE_BYTES (2 * A_BYTES + 2 * B_BYTES)  // 37888
#define GEMM_SMEM (3 * STAGE_BYTES)              // 113664

template <int EPI>
__global__ void __launch_bounds__(256, 1) wgemm_kernel(
    const __nv_bfloat16* __restrict__ Ah, const __nv_bfloat16* __restrict__ Al,
    const __nv_bfloat16* __restrict__ Bh, const __nv_bfloat16* __restrict__ Bl, int ldb,
    const float* __restrict__ bias, const float* __restrict__ Rres, float* __restrict__ C,
    __nv_bfloat16* __restrict__ Chi, __nv_bfloat16* __restrict__ Clo,
    int K, int N, int Nout)
{
    extern __shared__ char smc[];
    uint32_t smb = smem_u32(smc);
    int tid = threadIdx.x, wid = tid >> 5, lane = tid & 31;
    int bm = blockIdx.x * 128, bn = blockIdx.y * 128;
    int mw = (wid & 3) * 32, nw = (wid >> 2) * 64;
    const int KS = K / 32;

    int arow = tid >> 1, akoff = (tid & 1) * 16;
    const __nv_bfloat16* Ahp = Ah + (size_t)(bm + arow) * K + akoff;
    const __nv_bfloat16* Alp = Al + (size_t)(bm + arow) * K + akoff;
    uint32_t a_s = (uint32_t)(arow * APITCH + akoff) * 2;

    int brow = tid >> 3, bcoff = (tid & 7) * 16;
    const __nv_bfloat16* Bhp = Bh + (size_t)brow * ldb + bn + bcoff;
    const __nv_bfloat16* Blp = Bl + (size_t)brow * ldb + bn + bcoff;
    uint32_t b_s = (uint32_t)(brow * PB + bcoff) * 2;

    auto cpstage = [&](int st, int k0) {
        uint32_t base = smb + (uint32_t)st * STAGE_BYTES;
        CP_A16(base + a_s,                         Ahp + k0);
        CP_A16(base + a_s + 16,                    Ahp + k0 + 8);
        CP_A16(base + A_BYTES + a_s,               Alp + k0);
        CP_A16(base + A_BYTES + a_s + 16,          Alp + k0 + 8);
        const __nv_bfloat16* sbh = Bhp + (size_t)k0 * ldb;
        const __nv_bfloat16* sbl = Blp + (size_t)k0 * ldb;
        CP_A16(base + 2 * A_BYTES + b_s,                sbh);
        CP_A16(base + 2 * A_BYTES + b_s + 16,           sbh + 8);
        CP_A16(base + 2 * A_BYTES + B_BYTES + b_s,      sbl);
        CP_A16(base + 2 * A_BYTES + B_BYTES + b_s + 16, sbl + 8);
    };

    float acc[2][8][4];
#pragma unroll
    for (int mt = 0; mt < 2; mt++)
#pragma unroll
        for (int nt = 0; nt < 8; nt++)
#pragma unroll
            for (int e = 0; e < 4; e++) acc[mt][nt][e] = 0.f;

    const int frow = lane & 15, fk8 = (lane >> 4) << 3;
    const int loc = lane & 7, li = lane >> 3;

    cpstage(0, 0); CP_COMMIT();
    cpstage(1, 32); CP_COMMIT();

    int st = 0;
    for (int ks = 0; ks < KS; ks++) {
        CP_WAIT(1);
        __syncthreads();
        if (ks + 2 < KS) {
            int nst = st + 2; if (nst >= 3) nst -= 3;
            cpstage(nst, (ks + 2) * 32);
            CP_COMMIT();
        }
        uint32_t Ah32 = smb + (uint32_t)st * STAGE_BYTES;
        uint32_t Al32 = Ah32 + A_BYTES;
        uint32_t Bh32 = Ah32 + 2 * A_BYTES;
        uint32_t Bl32 = Bh32 + B_BYTES;

#pragma unroll
        for (int kk = 0; kk < 32; kk += 16) {
            uint32_t ah[2][4], al[2][4];
#pragma unroll
            for (int mt = 0; mt < 2; mt++) {
                uint32_t off = (uint32_t)((mw + mt * 16 + frow) * APITCH + kk + fk8) * 2;
                ldsm_x4(ah[mt], Ah32 + off);
                ldsm_x4(al[mt], Al32 + off);
            }
#pragma unroll
            for (int p = 0; p < 4; p++) {
                uint32_t bh[4], bl[4];
                uint32_t boff = (uint32_t)((kk + (li & 1) * 8 + loc) * PB
                                           + nw + p * 16 + (li >> 1) * 8) * 2;
                ldsm_x4t(bh, Bh32 + boff);
                ldsm_x4t(bl, Bl32 + boff);
#pragma unroll
                for (int o = 0; o < 2; o++) {
                    int nt = p * 2 + o;
                    uint32_t b0h = bh[o * 2], b1h = bh[o * 2 + 1];
                    uint32_t b0l = bl[o * 2], b1l = bl[o * 2 + 1];
#pragma unroll
                    for (int mt = 0; mt < 2; mt++) {
                        mma_bf16(acc[mt][nt], ah[mt], b0h, b1h);
                        mma_bf16(acc[mt][nt], ah[mt], b0l, b1l);
                        mma_bf16(acc[mt][nt], al[mt], b0h, b1h);
                    }
                }
            }
        }
        st++; if (st >= 3) st = 0;
    }

    // ---- epilogue ----
    if (EPI == 2) {
        int j = (bn + nw) >> 6;
#pragma unroll
        for (int mt = 0; mt < 2; mt++) {
#pragma unroll
            for (int nt = 0; nt < 4; nt++) {
                int r0 = bm + mw + mt * 16 + (lane >> 2);
                int col = (j << 5) + nt * 8 + (lane & 3) * 2;
                float av[4];
#pragma unroll
                for (int e = 0; e < 4; e++) {
                    float g = acc[mt][nt][e];
                    float u = acc[mt][nt + 4][e];
                    av[e] = g / (1.f + __expf(-g)) * u;
                }
                __nv_bfloat16 h0 = __float2bfloat16(av[0]), h1 = __float2bfloat16(av[1]);
                __nv_bfloat16 h2 = __float2bfloat16(av[2]), h3 = __float2bfloat16(av[3]);
                __nv_bfloat16 l0 = __float2bfloat16(av[0] - __bfloat162float(h0));
                __nv_bfloat16 l1 = __float2bfloat16(av[1] - __bfloat162float(h1));
                __nv_bfloat16 l2 = __float2bfloat16(av[2] - __bfloat162float(h2));
                __nv_bfloat16 l3 = __float2bfloat16(av[3] - __bfloat162float(h3));
                *(uint32_t*)(Chi + (size_t)r0 * Nout + col) = pack_bf2(h0, h1);
                *(uint32_t*)(Clo + (size_t)r0 * Nout + col) = pack_bf2(l0, l1);
                *(uint32_t*)(Chi + (size_t)(r0 + 8) * Nout + col) = pack_bf2(h2, h3);
                *(uint32_t*)(Clo + (size_t)(r0 + 8) * Nout + col) = pack_bf2(l2, l3);
            }
        }
    } else {
#pragma unroll
        for (int mt = 0; mt < 2; mt++) {
#pragma unroll
            for (int nt = 0; nt < 8; nt++) {
                int r0 = bm + mw + mt * 16 + (lane >> 2);
                int col = bn + nw + nt * 8 + (lane & 3) * 2;
                float2 v0 = {acc[mt][nt][0], acc[mt][nt][1]};
                float2 v1 = {acc[mt][nt][2], acc[mt][nt][3]};
                if (EPI == 0) {
                    if (bias) {
                        float b0 = bias[col], b1 = bias[col + 1];
                        v0.x += b0; v0.y += b1; v1.x += b0; v1.y += b1;
                    }
                } else {
                    float2 r0v = *(const float2*)(Rres + (size_t)r0 * N + col);
                    float2 r1v = *(const float2*)(Rres + (size_t)(r0 + 8) * N + col);
                    v0.x += r0v.x; v0.y += r0v.y;
                    v1.x += r1v.x; v1.y += r1v.y;
                }
                *(float2*)(C + (size_t)r0 * N + col) = v0;
                *(float2*)(C + (size_t)(r0 + 8) * N + col) = v1;
            }
        }
    }
}

// ---------------- RoPE -> fp16 Q split + fp16 K/V ----------------
__global__ void rope16_kernel(const float* __restrict__ qkv,
                              const float* __restrict__ cp, const float* __restrict__ sp,
                              __half* __restrict__ qh, __half* __restrict__ ql,
                              __half* __restrict__ k16, __half* __restrict__ v16) {
    int s = blockIdx.x, slot = blockIdx.y, d = threadIdx.x;
    float c = cp[s * D + d], sn = sp[s * D + d];
    const float* row;
    if (slot < NQ)            row = qkv + (size_t)s * QKVN + slot * D;
    else if (slot < NQ + NKV) row = qkv + (size_t)s * QKVN + QDIM + (slot - NQ) * D;
    else                      row = qkv + (size_t)s * QKVN + QDIM + KVDIM + (slot - NQ - NKV) * D;
    float a = row[d];
    float b = row[d ^ 64];
    float rot = (d < 64) ? -b : b;
    if (slot < NQ) {
        float val = a * c + rot * sn;
        __half hv = __float2half_rn(val);
        __half lv = __float2half_rn(val - __half2float(hv));
        size_t o = ((size_t)slot * S + s) * D + d;
        qh[o] = hv; ql[o] = lv;
    } else if (slot < NQ + NKV) {
        float val = a * c + rot * sn;
        k16[((size_t)(slot - NQ) * S + s) * D + d] = __float2half_rn(val);
    } else {
        v16[((size_t)(slot - NQ - NKV) * S + s) * D + d] = __float2half_rn(a);
    }
}

// ---------------- tensor-core causal flash attention ----------------
#define PKV 136
#define ATT_SMEM (128 * PKV * 2)

__global__ void __launch_bounds__(256, 1) attn_kernel(
    const __half* __restrict__ qh, const __half* __restrict__ ql,
    const __half* __restrict__ k16, const __half* __restrict__ v16,
    __nv_bfloat16* __restrict__ ohi, __nv_bfloat16* __restrict__ olo)
{
    extern __shared__ __half sma[];
    uint32_t smb = smem_u32(sma);
    int tid = threadIdx.x, wid = tid >> 5, lane = tid & 31;
    int bq = (int)gridDim.x - 1 - (int)blockIdx.x;
    int h = blockIdx.y;
    int kvh = h / (NQ / NKV);
    int q0 = bq * 128;
    int wq0 = wid * 16;

    const int frow = lane & 15, fk8 = (lane >> 4) << 3;

    uint32_t qfh[8][4], qfl[8][4];
    {
        int row = tid >> 1, coff = (tid & 1) * 64;
        __half* dst = sma + row * PKV + coff;
        const __half* src = qh + ((size_t)h * S + q0 + row) * D + coff;
#pragma unroll
        for (int j = 0; j < 8; j++) *(uint4*)(dst + j * 8) = *(const uint4*)(src + j * 8);
        __syncthreads();
#pragma unroll
        for (int kd = 0; kd < 8; kd++)
            ldsm_x4(qfh[kd], smb + (uint32_t)((wq0 + frow) * PKV + kd * 16 + fk8) * 2);
        __syncthreads();
        const __half* src2 = ql + ((size_t)h * S + q0 + row) * D + coff;
#pragma unroll
        for (int j = 0; j < 8; j++) *(uint4*)(dst + j * 8) = *(const uint4*)(src2 + j * 8);
        __syncthreads();
#pragma unroll
        for (int kd = 0; kd < 8; kd++)
            ldsm_x4(qfl[kd], smb + (uint32_t)((wq0 + frow) * PKV + kd * 16 + fk8) * 2);
        __syncthreads();
    }

    auto cp_kv = [&](int st, int kt) {
        int row = tid >> 3, c16 = (tid & 7) * 16;
        const __half* ksrc = k16 + ((size_t)kvh * S + kt * 32 + row) * D + c16;
        const __half* vsrc = v16 + ((size_t)kvh * S + kt * 32 + row) * D + c16;
        uint32_t kdst = smb + (uint32_t)((st * 32 + row) * PKV + c16) * 2;
        uint32_t vdst = smb + (uint32_t)((64 + st * 32 + row) * PKV + c16) * 2;
        CP_A16(kdst, ksrc); CP_A16(kdst + 16, ksrc + 8);
        CP_A16(vdst, vsrc); CP_A16(vdst + 16, vsrc + 8);
    };

    float oacc[16][4];
#pragma unroll
    for (int nt = 0; nt < 16; nt++)
#pragma unroll
        for (int e = 0; e < 4; e++) oacc[nt][e] = 0.f;
    float mrow0 = -1e30f, mrow1 = -1e30f, lrow0 = 0.f, lrow1 = 0.f;

    const int nk = 4 * bq + 4;
    cp_kv(0, 0);
    CP_COMMIT();

    for (int kt = 0; kt < nk; kt++) {
        int st = kt & 1;
        if (kt + 1 < nk) {
            cp_kv(st ^ 1, kt + 1);
            CP_COMMIT();
            CP_WAIT(1);
        } else {
            CP_WAIT(0);
        }
        __syncthreads();

        float sc[4][4];
#pragma unroll
        for (int nt = 0; nt < 4; nt++)
#pragma unroll
            for (int e = 0; e < 4; e++) sc[nt][e] = 0.f;
        uint32_t kbase = smb + (uint32_t)(st * 32 * PKV) * 2;
#pragma unroll
        for (int kd = 0; kd < 8; kd++) {
            uint32_t bf0[4], bf1[4];
            ldsm_x4(bf0, kbase + (uint32_t)(frow * PKV + kd * 16 + fk8) * 2);
            ldsm_x4(bf1, kbase + (uint32_t)((16 + frow) * PKV + kd * 16 + fk8) * 2);
            mma_fp16(sc[0], qfh[kd], bf0[0], bf0[2]);
            mma_fp16(sc[1], qfh[kd], bf0[1], bf0[3]);
            mma_fp16(sc[2], qfh[kd], bf1[0], bf1[2]);
            mma_fp16(sc[3], qfh[kd], bf1[1], bf1[3]);
            mma_fp16(sc[0], qfl[kd], bf0[0], bf0[2]);
            mma_fp16(sc[1], qfl[kd], bf0[1], bf0[3]);
            mma_fp16(sc[2], qfl[kd], bf1[0], bf1[2]);
            mma_fp16(sc[3], qfl[kd], bf1[1], bf1[3]);
        }
        int r_lo = q0 + wq0 + (lane >> 2);
        if (kt >= 4 * bq) {
            int kk0 = kt * 32;
#pragma unroll
            for (int nt = 0; nt < 4; nt++) {
                int kc = kk0 + nt * 8 + (lane & 3) * 2;
#pragma unroll
                for (int e = 0; e < 4; e++) {
                    int key = kc + (e & 1);
                    int row = r_lo + ((e >> 1) << 3);
                    sc[nt][e] = (key > row) ? -1e30f : sc[nt][e] * SCALE;
                }
            }
        } else {
#pragma unroll
            for (int nt = 0; nt < 4; nt++)
#pragma unroll
                for (int e = 0; e < 4; e++) sc[nt][e] *= SCALE;
        }
        float mx0 = -1e30f, mx1 = -1e30f;
#pragma unroll
        for (int nt = 0; nt < 4; nt++) {
            mx0 = fmaxf(mx0, fmaxf(sc[nt][0], sc[nt][1]));
            mx1 = fmaxf(mx1, fmaxf(sc[nt][2], sc[nt][3]));
        }
        mx0 = fmaxf(mx0, __shfl_xor_sync(0xffffffffu, mx0, 1));
        mx0 = fmaxf(mx0, __shfl_xor_sync(0xffffffffu, mx0, 2));
        mx1 = fmaxf(mx1, __shfl_xor_sync(0xffffffffu, mx1, 1));
        mx1 = fmaxf(mx1, __shfl_xor_sync(0xffffffffu, mx1, 2));
        float mn0 = fmaxf(mrow0, mx0), mn1 = fmaxf(mrow1, mx1);
        float c0 = __expf(mrow0 - mn0), c1 = __expf(mrow1 - mn1);
        mrow0 = mn0; mrow1 = mn1;
        uint32_t pah[2][4], pal[2][4];
        float ps0 = 0.f, ps1 = 0.f;
#pragma unroll
        for (int b = 0; b < 2; b++) {
            float p00, p01, p10, p11, q00, q01, q10, q11;
            {
                int t0 = b * 2, t1 = b * 2 + 1;
                p00 = __expf(sc[t0][0] - mn0); p01 = __expf(sc[t0][1] - mn0);
                p10 = __expf(sc[t0][2] - mn1); p11 = __expf(sc[t0][3] - mn1);
                q00 = __expf(sc[t1][0] - mn0); q01 = __expf(sc[t1][1] - mn0);
                q10 = __expf(sc[t1][2] - mn1); q11 = __expf(sc[t1][3] - mn1);
            }
            ps0 += p00 + p01 + q00 + q01;
            ps1 += p10 + p11 + q10 + q11;
            __half h00 = __float2half_rn(p00), h01 = __float2half_rn(p01);
            __half h10 = __float2half_rn(p10), h11 = __float2half_rn(p11);
            __half g00 = __float2half_rn(q00), g01 = __float2half_rn(q01);
            __half g10 = __float2half_rn(q10), g11 = __float2half_rn(q11);
            pah[b][0] = pack_h2(h00, h01);
            pah[b][1] = pack_h2(h10, h11);
            pah[b][2] = pack_h2(g00, g01);
            pah[b][3] = pack_h2(g10, g11);
            pal[b][0] = pack_h2(__float2half_rn(p00 - __half2float(h00)),
                                __float2half_rn(p01 - __half2float(h01)));
            pal[b][1] = pack_h2(__float2half_rn(p10 - __half2float(h10)),
                                __float2half_rn(p11 - __half2float(h11)));
            pal[b][2] = pack_h2(__float2half_rn(q00 - __half2float(g00)),
                                __float2half_rn(q01 - __half2float(g01)));
            pal[b][3] = pack_h2(__float2half_rn(q10 - __half2float(g10)),
                                __float2half_rn(q11 - __half2float(g11)));
        }
        ps0 += __shfl_xor_sync(0xffffffffu, ps0, 1);
        ps0 += __shfl_xor_sync(0xffffffffu, ps0, 2);
        ps1 += __shfl_xor_sync(0xffffffffu, ps1, 1);
        ps1 += __shfl_xor_sync(0xffffffffu, ps1, 2);
        lrow0 = lrow0 * c0 + ps0;
        lrow1 = lrow1 * c1 + ps1;
#pragma unroll
        for (int nt = 0; nt < 16; nt++) {
            oacc[nt][0] *= c0; oacc[nt][1] *= c0;
            oacc[nt][2] *= c1; oacc[nt][3] *= c1;
        }
        uint32_t vbase = smb + (uint32_t)((64 + st * 32) * PKV) * 2;
        int loc = lane & 7, li = lane >> 3;
#pragma unroll
        for (int dp = 0; dp < 8; dp++) {
            uint32_t vf0[4], vf1[4];
            uint32_t col = dp * 16 + (li >> 1) * 8;
            ldsm_x4t(vf0, vbase + (uint32_t)(((li & 1) * 8 + loc) * PKV + col) * 2);
            ldsm_x4t(vf1, vbase + (uint32_t)((16 + (li & 1) * 8 + loc) * PKV + col) * 2);
            mma_fp16(oacc[dp * 2],     pah[0], vf0[0], vf0[1]);
            mma_fp16(oacc[dp * 2 + 1], pah[0], vf0[2], vf0[3]);
            mma_fp16(oacc[dp * 2],     pah[1], vf1[0], vf1[1]);
            mma_fp16(oacc[dp * 2 + 1], pah[1], vf1[2], vf1[3]);
            mma_fp16(oacc[dp * 2],     pal[0], vf0[0], vf0[1]);
            mma_fp16(oacc[dp * 2 + 1], pal[0], vf0[2], vf0[3]);
            mma_fp16(oacc[dp * 2],     pal[1], vf1[0], vf1[1]);
            mma_fp16(oacc[dp * 2 + 1], pal[1], vf1[2], vf1[3]);
        }
        __syncthreads();
    }

    float inv0 = 1.0f / lrow0, inv1 = 1.0f / lrow1;
    int r = q0 + wq0 + (lane >> 2);
    int cbase = h * D + (lane & 3) * 2;
#pragma unroll
    for (int nt = 0; nt < 16; nt++) {
        int c = cbase + nt * 8;
        float a0 = oacc[nt][0] * inv0, a1 = oacc[nt][1] * inv0;
        float a2 = oacc[nt][2] * inv1, a3 = oacc[nt][3] * inv1;
        __nv_bfloat16 h0 = __float2bfloat16(a0), h1 = __float2bfloat16(a1);
        __nv_bfloat16 h2 = __float2bfloat16(a2), h3 = __float2bfloat16(a3);
        __nv_bfloat16 l0 = __float2bfloat16(a0 - __bfloat162float(h0));
        __nv_bfloat16 l1 = __float2bfloat16(a1 - __bfloat162float(h1));
        __nv_bfloat16 l2 = __float2bfloat16(a2 - __bfloat162float(h2));
        __nv_bfloat16 l3 = __float2bfloat16(a3 - __bfloat162float(h3));
        *(uint32_t*)(ohi + (size_t)r * QDIM + c) = pack_bf2(h0, h1);
        *(uint32_t*)(olo + (size_t)r * QDIM + c) = pack_bf2(l0, l1);
        *(uint32_t*)(ohi + (size_t)(r + 8) * QDIM + c) = pack_bf2(h2, h3);
        *(uint32_t*)(olo + (size_t)(r + 8) * QDIM + c) = pack_bf2(l2, l3);
    }
}

// ---------------- host launch ----------------
extern "C" void kernel_launch(void* const* d_in, const int* in_sizes, int n_in,
                              void* d_out, int out_size) {
    const float* hs   = (const float*)d_in[0];
    const float* cosp = (const float*)d_in[1];
    const float* sinp = (const float*)d_in[2];
    const float* Wq = (const float*)d_in[4];
    const float* bq = (const float*)d_in[5];
    const float* Wk = (const float*)d_in[6];
    const float* bk = (const float*)d_in[7];
    const float* Wv = (const float*)d_in[8];
    const float* bv = (const float*)d_in[9];
    const float* Wo = (const float*)d_in[10];
    const float* Wg = (const float*)d_in[11];
    const float* Wu = (const float*)d_in[12];
    const float* Wd = (const float*)d_in[13];
    const float* ln1 = (const float*)d_in[14];
    const float* ln2 = (const float*)d_in[15];
    const float* fln = (const float*)d_in[16];

    float *p_x, *p_qkv, *p_bias;
    __nv_bfloat16 *p_whi, *p_wlo, *p_ahi, *p_alo, *p_bhi, *p_blo;
    __half *p_qh, *p_ql, *p_k16, *p_v16;
    cudaGetSymbolAddress((void**)&p_x, g_x);
    cudaGetSymbolAddress((void**)&p_qkv, g_qkv);
    cudaGetSymbolAddress((void**)&p_bias, g_biasq);
    cudaGetSymbolAddress((void**)&p_whi, g_whi);
    cudaGetSymbolAddress((void**)&p_wlo, g_wlo);
    cudaGetSymbolAddress((void**)&p_ahi, g_ahi);
    cudaGetSymbolAddress((void**)&p_alo, g_alo);
    cudaGetSymbolAddress((void**)&p_bhi, g_bhi);
    cudaGetSymbolAddress((void**)&p_blo, g_blo);
    cudaGetSymbolAddress((void**)&p_qh, g_q16h);
    cudaGetSymbolAddress((void**)&p_ql, g_q16l);
    cudaGetSymbolAddress((void**)&p_k16, g_k16);
    cudaGetSymbolAddress((void**)&p_v16, g_v16);

    cudaFuncSetAttribute(attn_kernel, cudaFuncAttributeMaxDynamicSharedMemorySize, ATT_SMEM);
    cudaFuncSetAttribute(wgemm_kernel<0>, cudaFuncAttributeMaxDynamicSharedMemorySize, GEMM_SMEM);
    cudaFuncSetAttribute(wgemm_kernel<1>, cudaFuncAttributeMaxDynamicSharedMemorySize, GEMM_SMEM);
    cudaFuncSetAttribute(wgemm_kernel<2>, cudaFuncAttributeMaxDynamicSharedMemorySize, GEMM_SMEM);

    {
        int n4 = S * H / 4;
        copy_kernel<<<(n4 + 255) / 256, 256>>>((const float4*)hs, (float4*)p_x, n4);
    }

    for (int i = 0; i < LAYERS; i++) {
        const float* Wq_i = Wq + (size_t)i * H * QDIM;
        const float* Wk_i = Wk + (size_t)i * H * KVDIM;
        const float* Wv_i = Wv + (size_t)i * H * KVDIM;
        const float* Wo_i = Wo + (size_t)i * QDIM * H;
        const float* Wg_i = Wg + (size_t)i * H * IFF;
        const float* Wu_i = Wu + (size_t)i * H * IFF;
        const float* Wd_i = Wd + (size_t)i * IFF * H;

        rmsnorm_split_kernel<<<S, 256>>>(p_x, ln1 + (size_t)i * H, p_ahi, p_alo);

        wsplit_kernel<<<(H * QDIM / 4 + 255) / 256, 256>>>(
            Wq_i, H * QDIM / 4, QDIM / 4, p_whi, p_wlo, 0, QKVN);
        wsplit_kernel<<<(H * KVDIM / 4 + 255) / 256, 256>>>(
            Wk_i, H * KVDIM / 4, KVDIM / 4, p_whi, p_wlo, QDIM, QKVN);
        wsplit_kernel<<<(H * KVDIM / 4 + 255) / 256, 256>>>(
            Wv_i, H * KVDIM / 4, KVDIM / 4, p_whi, p_wlo, QDIM + KVDIM, QKVN);
        concat_bias_kernel<<<QKVN / 256, 256>>>(bq + (size_t)i * QDIM, bk + (size_t)i * KVDIM,
                                                bv + (size_t)i * KVDIM, p_bias);
        wgemm_kernel<0><<<dim3(S / 128, QKVN / 128), 256, GEMM_SMEM>>>(
            p_ahi, p_alo, p_whi, p_wlo, QKVN, p_bias, nullptr, p_qkv,
            nullptr, nullptr, H, QKVN, 0);

        rope16_kernel<<<dim3(S, NQ + 2 * NKV), 128>>>(p_qkv, cosp, sinp, p_qh, p_ql, p_k16, p_v16);
        attn_kernel<<<dim3(S / 128, NQ), 256, ATT_SMEM>>>(p_qh, p_ql, p_k16, p_v16, p_ahi, p_alo);

        wsplit_kernel<<<(QDIM * H / 4 + 255) / 256, 256>>>(
            Wo_i, QDIM * H / 4, H / 4, p_whi, p_wlo, 0, H);
        wgemm_kernel<1><<<dim3(S / 128, H / 128), 256, GEMM_SMEM>>>(
            p_ahi, p_alo, p_whi, p_wlo, H, nullptr, p_x, p_x,
            nullptr, nullptr, QDIM, H, 0);

        rmsnorm_split_kernel<<<S, 256>>>(p_x, ln2 + (size_t)i * H, p_ahi, p_alo);

        wsplit_gu_kernel<<<(H * IFF / 4 + 255) / 256, 256>>>(Wg_i, 0, p_whi, p_wlo);
        wsplit_gu_kernel<<<(H * IFF / 4 + 255) / 256, 256>>>(Wu_i, 1, p_whi, p_wlo);
        wgemm_kernel<2><<<dim3(S / 128, GUN / 128), 256, GEMM_SMEM>>>(
            p_ahi, p_alo, p_whi, p_wlo, GUN, nullptr, nullptr, nullptr,
            p_bhi, p_blo, H, GUN, IFF);

        wsplit_kernel<<<(IFF * H / 4 + 255) / 256, 256>>>(
            Wd_i, IFF * H / 4, H / 4, p_whi, p_wlo, 0, H);
        wgemm_kernel<1><<<dim3(S / 128, H / 128), 256, GEMM_SMEM>>>(
            p_bhi, p_blo, p_whi, p_wlo, H, nullptr, p_x, p_x,
            nullptr, nullptr, IFF, H, 0);
    }

    rmsnorm_kernel<<<S, 256>>>(p_x, fln, (float*)d_out);
}

// round 8
// speedup vs baseline: 3.0458x; 1.0560x over previous
#include <cuda_runtime.h>
#include <cuda_fp16.h>
#include <cuda_bf16.h>
#include <math.h>
#include <stdint.h>

#define S 2048
#define H 1536
#define NQ 12
#define NKV 2
#define D 128
#define IFF 8960
#define LAYERS 4
#define QDIM (NQ*D)      // 1536
#define KVDIM (NKV*D)    // 256
#define QKVN 2048
#define GUN (2*IFF)      // 17920
#define EPS 1e-6f
#define SCALE 0.08838834764831845f

// ---------------- device scratch (allocation-free) ----------------
__device__ float g_x[S*H];
__device__ float g_qkv[S*QKVN];
__device__ float g_biasq[QKVN];
__device__ __nv_bfloat16 g_whi[(size_t)H*GUN];
__device__ __nv_bfloat16 g_wlo[(size_t)H*GUN];
__device__ __nv_bfloat16 g_ahi[(size_t)S*H];
__device__ __nv_bfloat16 g_alo[(size_t)S*H];
__device__ __nv_bfloat16 g_bhi[(size_t)S*IFF];
__device__ __nv_bfloat16 g_blo[(size_t)S*IFF];
__device__ __half g_q16h[(size_t)NQ*S*D];
__device__ __half g_q16l[(size_t)NQ*S*D];
__device__ __half g_k16[(size_t)NKV*S*D];
__device__ __half g_v16[(size_t)NKV*S*D];

__device__ __forceinline__ uint32_t pack_bf2(__nv_bfloat16 a, __nv_bfloat16 b) {
    __nv_bfloat162 t; t.x = a; t.y = b;
    return *reinterpret_cast<uint32_t*>(&t);
}
__device__ __forceinline__ uint32_t pack_h2(__half a, __half b) {
    __half2 t; t.x = a; t.y = b;
    return *reinterpret_cast<uint32_t*>(&t);
}
__device__ __forceinline__ uint32_t smem_u32(const void* p) {
    uint32_t a;
    asm("{ .reg .u64 t; cvta.to.shared.u64 t, %1; cvt.u32.u64 %0, t; }" : "=r"(a) : "l"(p));
    return a;
}
__device__ __forceinline__ void mma_bf16(float* d, const uint32_t* a, uint32_t b0, uint32_t b1) {
    asm volatile(
        "mma.sync.aligned.m16n8k16.row.col.f32.bf16.bf16.f32 "
        "{%0,%1,%2,%3}, {%4,%5,%6,%7}, {%8,%9}, {%0,%1,%2,%3};"
        : "+f"(d[0]), "+f"(d[1]), "+f"(d[2]), "+f"(d[3])
        : "r"(a[0]), "r"(a[1]), "r"(a[2]), "r"(a[3]), "r"(b0), "r"(b1));
}
__device__ __forceinline__ void mma_fp16(float* d, const uint32_t* a, uint32_t b0, uint32_t b1) {
    asm volatile(
        "mma.sync.aligned.m16n8k16.row.col.f32.f16.f16.f32 "
        "{%0,%1,%2,%3}, {%4,%5,%6,%7}, {%8,%9}, {%0,%1,%2,%3};"
        : "+f"(d[0]), "+f"(d[1]), "+f"(d[2]), "+f"(d[3])
        : "r"(a[0]), "r"(a[1]), "r"(a[2]), "r"(a[3]), "r"(b0), "r"(b1));
}
__device__ __forceinline__ void ldsm_x4(uint32_t* r, uint32_t addr) {
    asm volatile("ldmatrix.sync.aligned.m8n8.x4.shared.b16 {%0,%1,%2,%3}, [%4];"
        : "=r"(r[0]), "=r"(r[1]), "=r"(r[2]), "=r"(r[3]) : "r"(addr));
}
__device__ __forceinline__ void ldsm_x4t(uint32_t* r, uint32_t addr) {
    asm volatile("ldmatrix.sync.aligned.m8n8.x4.trans.shared.b16 {%0,%1,%2,%3}, [%4];"
        : "=r"(r[0]), "=r"(r[1]), "=r"(r[2]), "=r"(r[3]) : "r"(addr));
}
#define CP_A16(dst, src) asm volatile("cp.async.ca.shared.global [%0], [%1], 16;" :: "r"(dst), "l"(src) : "memory")
#define CP_COMMIT()      asm volatile("cp.async.commit_group;" ::: "memory")
#define CP_WAIT(n)       asm volatile("cp.async.wait_group %0;" :: "n"(n) : "memory")

// ---------------- copy ----------------
__global__ void copy_kernel(const float4* __restrict__ src, float4* __restrict__ dst, int n) {
    int i = blockIdx.x * blockDim.x + threadIdx.x;
    if (i < n) dst[i] = src[i];
}

// ---------------- RMSNorm (fp32 out, final only) ----------------
__global__ void rmsnorm_kernel(const float* __restrict__ x, const float* __restrict__ w,
                               float* __restrict__ out) {
    int row = blockIdx.x;
    const float* xr = x + (size_t)row * H;
    float ss = 0.f;
    for (int c = threadIdx.x; c < H; c += 256) { float v = xr[c]; ss += v * v; }
    __shared__ float red[256];
    red[threadIdx.x] = ss;
    __syncthreads();
    for (int off = 128; off > 0; off >>= 1) {
        if (threadIdx.x < off) red[threadIdx.x] += red[threadIdx.x + off];
        __syncthreads();
    }
    float rs = 1.0f / sqrtf(red[0] / (float)H + EPS);
    float* orow = out + (size_t)row * H;
    for (int c = threadIdx.x; c < H; c += 256) orow[c] = xr[c] * rs * w[c];
}

// ---------------- RMSNorm fused bf16 hi/lo split ----------------
__global__ void rmsnorm_split_kernel(const float* __restrict__ x, const float* __restrict__ w,
                                     __nv_bfloat16* __restrict__ oh, __nv_bfloat16* __restrict__ ol) {
    int row = blockIdx.x;
    const float* xr = x + (size_t)row * H;
    float ss = 0.f;
    for (int c = threadIdx.x; c < H; c += 256) { float v = xr[c]; ss += v * v; }
    __shared__ float red[256];
    red[threadIdx.x] = ss;
    __syncthreads();
    for (int off = 128; off > 0; off >>= 1) {
        if (threadIdx.x < off) red[threadIdx.x] += red[threadIdx.x + off];
        __syncthreads();
    }
    float rs = 1.0f / sqrtf(red[0] / (float)H + EPS);
    for (int c = threadIdx.x * 2; c < H; c += 512) {
        float v0 = xr[c] * rs * w[c];
        float v1 = xr[c + 1] * rs * w[c + 1];
        __nv_bfloat16 h0 = __float2bfloat16(v0), h1 = __float2bfloat16(v1);
        __nv_bfloat16 l0 = __float2bfloat16(v0 - __bfloat162float(h0));
        __nv_bfloat16 l1 = __float2bfloat16(v1 - __bfloat162float(h1));
        *(uint32_t*)(oh + (size_t)row * H + c) = pack_bf2(h0, h1);
        *(uint32_t*)(ol + (size_t)row * H + c) = pack_bf2(l0, l1);
    }
}

// ---------------- weight split (streaming, no transpose) ----------------
__global__ void wsplit_kernel(const float* __restrict__ W, int total4, int nc4,
                              __nv_bfloat16* __restrict__ Th, __nv_bfloat16* __restrict__ Tl,
                              int coff, int ldn) {
    int i = blockIdx.x * 256 + threadIdx.x;
    if (i >= total4) return;
    int k = i / nc4;
    int n = (i - k * nc4) * 4;
    float4 v = *(const float4*)(W + (size_t)k * (nc4 * 4) + n);
    __nv_bfloat16 h0 = __float2bfloat16(v.x), h1 = __float2bfloat16(v.y);
    __nv_bfloat16 h2 = __float2bfloat16(v.z), h3 = __float2bfloat16(v.w);
    __nv_bfloat16 l0 = __float2bfloat16(v.x - __bfloat162float(h0));
    __nv_bfloat16 l1 = __float2bfloat16(v.y - __bfloat162float(h1));
    __nv_bfloat16 l2 = __float2bfloat16(v.z - __bfloat162float(h2));
    __nv_bfloat16 l3 = __float2bfloat16(v.w - __bfloat162float(h3));
    size_t o = (size_t)k * ldn + coff + n;
    *(uint2*)(Th + o) = make_uint2(pack_bf2(h0, h1), pack_bf2(h2, h3));
    *(uint2*)(Tl + o) = make_uint2(pack_bf2(l0, l1), pack_bf2(l2, l3));
}

// gate/up interleaved at 32 cols: dst col = (n/32)*64 + n%32 + up*32
__global__ void wsplit_gu_kernel(const float* __restrict__ W, int up,
                                 __nv_bfloat16* __restrict__ Th, __nv_bfloat16* __restrict__ Tl) {
    int i = blockIdx.x * 256 + threadIdx.x;
    if (i >= H * IFF / 4) return;
    int k = i / (IFF / 4);
    int n = (i - k * (IFF / 4)) * 4;
    float4 v = *(const float4*)(W + (size_t)k * IFF + n);
    __nv_bfloat16 h0 = __float2bfloat16(v.x), h1 = __float2bfloat16(v.y);
    __nv_bfloat16 h2 = __float2bfloat16(v.z), h3 = __float2bfloat16(v.w);
    __nv_bfloat16 l0 = __float2bfloat16(v.x - __bfloat162float(h0));
    __nv_bfloat16 l1 = __float2bfloat16(v.y - __bfloat162float(h1));
    __nv_bfloat16 l2 = __float2bfloat16(v.z - __bfloat162float(h2));
    __nv_bfloat16 l3 = __float2bfloat16(v.w - __bfloat162float(h3));
    int c = ((n >> 5) << 6) + (n & 31) + up * 32;
    size_t o = (size_t)k * GUN + c;
    *(uint2*)(Th + o) = make_uint2(pack_bf2(h0, h1), pack_bf2(h2, h3));
    *(uint2*)(Tl + o) = make_uint2(pack_bf2(l0, l1), pack_bf2(l2, l3));
}

// ---------------- bias concat ----------------
__global__ void concat_bias_kernel(const float* bq, const float* bk, const float* bv,
                                   float* out) {
    int i = blockIdx.x * 256 + threadIdx.x;
    if (i < QKVN)
        out[i] = (i < QDIM) ? bq[i] : ((i < QDIM + KVDIM) ? bk[i - QDIM] : bv[i - QDIM - KVDIM]);
}

// ---------------- warp-MMA split-bf16 GEMM, 3-stage cp.async, trans-B ----------------
// TM = 128 or 64 (block M-rows). EPI 0: +=bias; 1: +R; 2: silu(g)*u -> bf16 split.
#define APITCH 40
#define PB 136
#define B_BYTES (32 * PB * 2)        // 8704

template <int EPI, int TM>
__global__ void __launch_bounds__(256, 1) wgemm_kernel(
    const __nv_bfloat16* __restrict__ Ah, const __nv_bfloat16* __restrict__ Al,
    const __nv_bfloat16* __restrict__ Bh, const __nv_bfloat16* __restrict__ Bl, int ldb,
    const float* __restrict__ bias, const float* __restrict__ Rres, float* __restrict__ C,
    __nv_bfloat16* __restrict__ Chi, __nv_bfloat16* __restrict__ Clo,
    int K, int N, int Nout)
{
    constexpr int MTC = TM / 64;                    // m-tiles (of 16) per warp
    constexpr int A_BYTES = TM * APITCH * 2;
    constexpr int STAGE_BYTES = 2 * A_BYTES + 2 * B_BYTES;

    extern __shared__ char smc[];
    uint32_t smb = smem_u32(smc);
    int tid = threadIdx.x, wid = tid >> 5, lane = tid & 31;
    int bm = blockIdx.x * TM, bn = blockIdx.y * 128;
    int mw = (wid & 3) * (TM / 4), nw = (wid >> 2) * 64;
    const int KS = K / 32;

    // A loader geometry
    int arow, akoff;
    if (TM == 128) { arow = tid >> 1; akoff = (tid & 1) * 16; }
    else           { arow = tid >> 2; akoff = (tid & 3) * 8; }
    const __nv_bfloat16* Ahp = Ah + (size_t)(bm + arow) * K + akoff;
    const __nv_bfloat16* Alp = Al + (size_t)(bm + arow) * K + akoff;
    uint32_t a_s = (uint32_t)(arow * APITCH + akoff) * 2;

    int brow = tid >> 3, bcoff = (tid & 7) * 16;
    const __nv_bfloat16* Bhp = Bh + (size_t)brow * ldb + bn + bcoff;
    const __nv_bfloat16* Blp = Bl + (size_t)brow * ldb + bn + bcoff;
    uint32_t b_s = (uint32_t)(brow * PB + bcoff) * 2;

    auto cpstage = [&](int st, int k0) {
        uint32_t base = smb + (uint32_t)st * STAGE_BYTES;
        if (TM == 128) {
            CP_A16(base + a_s,                Ahp + k0);
            CP_A16(base + a_s + 16,           Ahp + k0 + 8);
            CP_A16(base + A_BYTES + a_s,      Alp + k0);
            CP_A16(base + A_BYTES + a_s + 16, Alp + k0 + 8);
        } else {
            CP_A16(base + a_s,           Ahp + k0);
            CP_A16(base + A_BYTES + a_s, Alp + k0);
        }
        const __nv_bfloat16* sbh = Bhp + (size_t)k0 * ldb;
        const __nv_bfloat16* sbl = Blp + (size_t)k0 * ldb;
        CP_A16(base + 2 * A_BYTES + b_s,                sbh);
        CP_A16(base + 2 * A_BYTES + b_s + 16,           sbh + 8);
        CP_A16(base + 2 * A_BYTES + B_BYTES + b_s,      sbl);
        CP_A16(base + 2 * A_BYTES + B_BYTES + b_s + 16, sbl + 8);
    };

    float acc[MTC][8][4];
#pragma unroll
    for (int mt = 0; mt < MTC; mt++)
#pragma unroll
        for (int nt = 0; nt < 8; nt++)
#pragma unroll
            for (int e = 0; e < 4; e++) acc[mt][nt][e] = 0.f;

    const int frow = lane & 15, fk8 = (lane >> 4) << 3;
    const int loc = lane & 7, li = lane >> 3;

    cpstage(0, 0); CP_COMMIT();
    cpstage(1, 32); CP_COMMIT();

    int st = 0;
    for (int ks = 0; ks < KS; ks++) {
        CP_WAIT(1);
        __syncthreads();
        if (ks + 2 < KS) {
            int nst = st + 2; if (nst >= 3) nst -= 3;
            cpstage(nst, (ks + 2) * 32);
            CP_COMMIT();
        }
        uint32_t Ah32 = smb + (uint32_t)st * STAGE_BYTES;
        uint32_t Al32 = Ah32 + A_BYTES;
        uint32_t Bh32 = Ah32 + 2 * A_BYTES;
        uint32_t Bl32 = Bh32 + B_BYTES;

#pragma unroll
        for (int kk = 0; kk < 32; kk += 16) {
            uint32_t ah[MTC][4], al[MTC][4];
#pragma unroll
            for (int mt = 0; mt < MTC; mt++) {
                uint32_t off = (uint32_t)((mw + mt * 16 + frow) * APITCH + kk + fk8) * 2;
                ldsm_x4(ah[mt], Ah32 + off);
                ldsm_x4(al[mt], Al32 + off);
            }
#pragma unroll
            for (int p = 0; p < 4; p++) {
                uint32_t bh[4], bl[4];
                uint32_t boff = (uint32_t)((kk + (li & 1) * 8 + loc) * PB
                                           + nw + p * 16 + (li >> 1) * 8) * 2;
                ldsm_x4t(bh, Bh32 + boff);
                ldsm_x4t(bl, Bl32 + boff);
#pragma unroll
                for (int o = 0; o < 2; o++) {
                    int nt = p * 2 + o;
                    uint32_t b0h = bh[o * 2], b1h = bh[o * 2 + 1];
                    uint32_t b0l = bl[o * 2], b1l = bl[o * 2 + 1];
#pragma unroll
                    for (int mt = 0; mt < MTC; mt++) {
                        mma_bf16(acc[mt][nt], ah[mt], b0h, b1h);
                        mma_bf16(acc[mt][nt], ah[mt], b0l, b1l);
                        mma_bf16(acc[mt][nt], al[mt], b0h, b1h);
                    }
                }
            }
        }
        st++; if (st >= 3) st = 0;
    }

    // ---- epilogue ----
    if (EPI == 2) {
        int j = (bn + nw) >> 6;
#pragma unroll
        for (int mt = 0; mt < MTC; mt++) {
#pragma unroll
            for (int nt = 0; nt < 4; nt++) {
                int r0 = bm + mw + mt * 16 + (lane >> 2);
                int col = (j << 5) + nt * 8 + (lane & 3) * 2;
                float av[4];
#pragma unroll
                for (int e = 0; e < 4; e++) {
                    float g = acc[mt][nt][e];
                    float u = acc[mt][nt + 4][e];
                    av[e] = g / (1.f + __expf(-g)) * u;
                }
                __nv_bfloat16 h0 = __float2bfloat16(av[0]), h1 = __float2bfloat16(av[1]);
                __nv_bfloat16 h2 = __float2bfloat16(av[2]), h3 = __float2bfloat16(av[3]);
                __nv_bfloat16 l0 = __float2bfloat16(av[0] - __bfloat162float(h0));
                __nv_bfloat16 l1 = __float2bfloat16(av[1] - __bfloat162float(h1));
                __nv_bfloat16 l2 = __float2bfloat16(av[2] - __bfloat162float(h2));
                __nv_bfloat16 l3 = __float2bfloat16(av[3] - __bfloat162float(h3));
                *(uint32_t*)(Chi + (size_t)r0 * Nout + col) = pack_bf2(h0, h1);
                *(uint32_t*)(Clo + (size_t)r0 * Nout + col) = pack_bf2(l0, l1);
                *(uint32_t*)(Chi + (size_t)(r0 + 8) * Nout + col) = pack_bf2(h2, h3);
                *(uint32_t*)(Clo + (size_t)(r0 + 8) * Nout + col) = pack_bf2(l2, l3);
            }
        }
    } else {
#pragma unroll
        for (int mt = 0; mt < MTC; mt++) {
#pragma unroll
            for (int nt = 0; nt < 8; nt++) {
                int r0 = bm + mw + mt * 16 + (lane >> 2);
                int col = bn + nw + nt * 8 + (lane & 3) * 2;
                float2 v0 = {acc[mt][nt][0], acc[mt][nt][1]};
                float2 v1 = {acc[mt][nt][2], acc[mt][nt][3]};
                if (EPI == 0) {
                    if (bias) {
                        float b0 = bias[col], b1 = bias[col + 1];
                        v0.x += b0; v0.y += b1; v1.x += b0; v1.y += b1;
                    }
                } else {
                    float2 r0v = *(const float2*)(Rres + (size_t)r0 * N + col);
                    float2 r1v = *(const float2*)(Rres + (size_t)(r0 + 8) * N + col);
                    v0.x += r0v.x; v0.y += r0v.y;
                    v1.x += r1v.x; v1.y += r1v.y;
                }
                *(float2*)(C + (size_t)r0 * N + col) = v0;
                *(float2*)(C + (size_t)(r0 + 8) * N + col) = v1;
            }
        }
    }
}

// ---------------- RoPE -> fp16 Q split + fp16 K/V ----------------
__global__ void rope16_kernel(const float* __restrict__ qkv,
                              const float* __restrict__ cp, const float* __restrict__ sp,
                              __half* __restrict__ qh, __half* __restrict__ ql,
                              __half* __restrict__ k16, __half* __restrict__ v16) {
    int s = blockIdx.x, slot = blockIdx.y, d = threadIdx.x;
    float c = cp[s * D + d], sn = sp[s * D + d];
    const float* row;
    if (slot < NQ)            row = qkv + (size_t)s * QKVN + slot * D;
    else if (slot < NQ + NKV) row = qkv + (size_t)s * QKVN + QDIM + (slot - NQ) * D;
    else                      row = qkv + (size_t)s * QKVN + QDIM + KVDIM + (slot - NQ - NKV) * D;
    float a = row[d];
    float b = row[d ^ 64];
    float rot = (d < 64) ? -b : b;
    if (slot < NQ) {
        float val = a * c + rot * sn;
        __half hv = __float2half_rn(val);
        __half lv = __float2half_rn(val - __half2float(hv));
        size_t o = ((size_t)slot * S + s) * D + d;
        qh[o] = hv; ql[o] = lv;
    } else if (slot < NQ + NKV) {
        float val = a * c + rot * sn;
        k16[((size_t)(slot - NQ) * S + s) * D + d] = __float2half_rn(val);
    } else {
        v16[((size_t)(slot - NQ - NKV) * S + s) * D + d] = __float2half_rn(a);
    }
}

// ---------------- tensor-core causal flash attention ----------------
#define PKV 136
#define ATT_SMEM (128 * PKV * 2)

__global__ void __launch_bounds__(256, 1) attn_kernel(
    const __half* __restrict__ qh, const __half* __restrict__ ql,
    const __half* __restrict__ k16, const __half* __restrict__ v16,
    __nv_bfloat16* __restrict__ ohi, __nv_bfloat16* __restrict__ olo)
{
    extern __shared__ __half sma[];
    uint32_t smb = smem_u32(sma);
    int tid = threadIdx.x, wid = tid >> 5, lane = tid & 31;
    int bq = (int)gridDim.x - 1 - (int)blockIdx.x;
    int h = blockIdx.y;
    int kvh = h / (NQ / NKV);
    int q0 = bq * 128;
    int wq0 = wid * 16;

    const int frow = lane & 15, fk8 = (lane >> 4) << 3;

    uint32_t qfh[8][4], qfl[8][4];
    {
        int row = tid >> 1, coff = (tid & 1) * 64;
        __half* dst = sma + row * PKV + coff;
        const __half* src = qh + ((size_t)h * S + q0 + row) * D + coff;
#pragma unroll
        for (int j = 0; j < 8; j++) *(uint4*)(dst + j * 8) = *(const uint4*)(src + j * 8);
        __syncthreads();
#pragma unroll
        for (int kd = 0; kd < 8; kd++)
            ldsm_x4(qfh[kd], smb + (uint32_t)((wq0 + frow) * PKV + kd * 16 + fk8) * 2);
        __syncthreads();
        const __half* src2 = ql + ((size_t)h * S + q0 + row) * D + coff;
#pragma unroll
        for (int j = 0; j < 8; j++) *(uint4*)(dst + j * 8) = *(const uint4*)(src2 + j * 8);
        __syncthreads();
#pragma unroll
        for (int kd = 0; kd < 8; kd++)
            ldsm_x4(qfl[kd], smb + (uint32_t)((wq0 + frow) * PKV + kd * 16 + fk8) * 2);
        __syncthreads();
    }

    auto cp_kv = [&](int st, int kt) {
        int row = tid >> 3, c16 = (tid & 7) * 16;
        const __half* ksrc = k16 + ((size_t)kvh * S + kt * 32 + row) * D + c16;
        const __half* vsrc = v16 + ((size_t)kvh * S + kt * 32 + row) * D + c16;
        uint32_t kdst = smb + (uint32_t)((st * 32 + row) * PKV + c16) * 2;
        uint32_t vdst = smb + (uint32_t)((64 + st * 32 + row) * PKV + c16) * 2;
        CP_A16(kdst, ksrc); CP_A16(kdst + 16, ksrc + 8);
        CP_A16(vdst, vsrc); CP_A16(vdst + 16, vsrc + 8);
    };

    float oacc[16][4];
#pragma unroll
    for (int nt = 0; nt < 16; nt++)
#pragma unroll
        for (int e = 0; e < 4; e++) oacc[nt][e] = 0.f;
    float mrow0 = -1e30f, mrow1 = -1e30f, lrow0 = 0.f, lrow1 = 0.f;

    const int nk = 4 * bq + 4;
    cp_kv(0, 0);
    CP_COMMIT();

    for (int kt = 0; kt < nk; kt++) {
        int st = kt & 1;
        if (kt + 1 < nk) {
            cp_kv(st ^ 1, kt + 1);
            CP_COMMIT();
            CP_WAIT(1);
        } else {
            CP_WAIT(0);
        }
        __syncthreads();

        float sc[4][4];
#pragma unroll
        for (int nt = 0; nt < 4; nt++)
#pragma unroll
            for (int e = 0; e < 4; e++) sc[nt][e] = 0.f;
        uint32_t kbase = smb + (uint32_t)(st * 32 * PKV) * 2;
#pragma unroll
        for (int kd = 0; kd < 8; kd++) {
            uint32_t bf0[4], bf1[4];
            ldsm_x4(bf0, kbase + (uint32_t)(frow * PKV + kd * 16 + fk8) * 2);
            ldsm_x4(bf1, kbase + (uint32_t)((16 + frow) * PKV + kd * 16 + fk8) * 2);
            mma_fp16(sc[0], qfh[kd], bf0[0], bf0[2]);
            mma_fp16(sc[1], qfh[kd], bf0[1], bf0[3]);
            mma_fp16(sc[2], qfh[kd], bf1[0], bf1[2]);
            mma_fp16(sc[3], qfh[kd], bf1[1], bf1[3]);
            mma_fp16(sc[0], qfl[kd], bf0[0], bf0[2]);
            mma_fp16(sc[1], qfl[kd], bf0[1], bf0[3]);
            mma_fp16(sc[2], qfl[kd], bf1[0], bf1[2]);
            mma_fp16(sc[3], qfl[kd], bf1[1], bf1[3]);
        }
        int r_lo = q0 + wq0 + (lane >> 2);
        if (kt >= 4 * bq) {
            int kk0 = kt * 32;
#pragma unroll
            for (int nt = 0; nt < 4; nt++) {
                int kc = kk0 + nt * 8 + (lane & 3) * 2;
#pragma unroll
                for (int e = 0; e < 4; e++) {
                    int key = kc + (e & 1);
                    int row = r_lo + ((e >> 1) << 3);
                    sc[nt][e] = (key > row) ? -1e30f : sc[nt][e] * SCALE;
                }
            }
        } else {
#pragma unroll
            for (int nt = 0; nt < 4; nt++)
#pragma unroll
                for (int e = 0; e < 4; e++) sc[nt][e] *= SCALE;
        }
        float mx0 = -1e30f, mx1 = -1e30f;
#pragma unroll
        for (int nt = 0; nt < 4; nt++) {
            mx0 = fmaxf(mx0, fmaxf(sc[nt][0], sc[nt][1]));
            mx1 = fmaxf(mx1, fmaxf(sc[nt][2], sc[nt][3]));
        }
        mx0 = fmaxf(mx0, __shfl_xor_sync(0xffffffffu, mx0, 1));
        mx0 = fmaxf(mx0, __shfl_xor_sync(0xffffffffu, mx0, 2));
        mx1 = fmaxf(mx1, __shfl_xor_sync(0xffffffffu, mx1, 1));
        mx1 = fmaxf(mx1, __shfl_xor_sync(0xffffffffu, mx1, 2));
        float mn0 = fmaxf(mrow0, mx0), mn1 = fmaxf(mrow1, mx1);
        float c0 = __expf(mrow0 - mn0), c1 = __expf(mrow1 - mn1);
        mrow0 = mn0; mrow1 = mn1;
        uint32_t pah[2][4], pal[2][4];
        float ps0 = 0.f, ps1 = 0.f;
#pragma unroll
        for (int b = 0; b < 2; b++) {
            float p00, p01, p10, p11, q00, q01, q10, q11;
            {
                int t0 = b * 2, t1 = b * 2 + 1;
                p00 = __expf(sc[t0][0] - mn0); p01 = __expf(sc[t0][1] - mn0);
                p10 = __expf(sc[t0][2] - mn1); p11 = __expf(sc[t0][3] - mn1);
                q00 = __expf(sc[t1][0] - mn0); q01 = __expf(sc[t1][1] - mn0);
                q10 = __expf(sc[t1][2] - mn1); q11 = __expf(sc[t1][3] - mn1);
            }
            ps0 += p00 + p01 + q00 + q01;
            ps1 += p10 + p11 + q10 + q11;
            __half h00 = __float2half_rn(p00), h01 = __float2half_rn(p01);
            __half h10 = __float2half_rn(p10), h11 = __float2half_rn(p11);
            __half g00 = __float2half_rn(q00), g01 = __float2half_rn(q01);
            __half g10 = __float2half_rn(q10), g11 = __float2half_rn(q11);
            pah[b][0] = pack_h2(h00, h01);
            pah[b][1] = pack_h2(h10, h11);
            pah[b][2] = pack_h2(g00, g01);
            pah[b][3] = pack_h2(g10, g11);
            pal[b][0] = pack_h2(__float2half_rn(p00 - __half2float(h00)),
                                __float2half_rn(p01 - __half2float(h01)));
            pal[b][1] = pack_h2(__float2half_rn(p10 - __half2float(h10)),
                                __float2half_rn(p11 - __half2float(h11)));
            pal[b][2] = pack_h2(__float2half_rn(q00 - __half2float(g00)),
                                __float2half_rn(q01 - __half2float(g01)));
            pal[b][3] = pack_h2(__float2half_rn(q10 - __half2float(g10)),
                                __float2half_rn(q11 - __half2float(g11)));
        }
        ps0 += __shfl_xor_sync(0xffffffffu, ps0, 1);
        ps0 += __shfl_xor_sync(0xffffffffu, ps0, 2);
        ps1 += __shfl_xor_sync(0xffffffffu, ps1, 1);
        ps1 += __shfl_xor_sync(0xffffffffu, ps1, 2);
        lrow0 = lrow0 * c0 + ps0;
        lrow1 = lrow1 * c1 + ps1;
#pragma unroll
        for (int nt = 0; nt < 16; nt++) {
            oacc[nt][0] *= c0; oacc[nt][1] *= c0;
            oacc[nt][2] *= c1; oacc[nt][3] *= c1;
        }
        uint32_t vbase = smb + (uint32_t)((64 + st * 32) * PKV) * 2;
        int loc = lane & 7, li = lane >> 3;
#pragma unroll
        for (int dp = 0; dp < 8; dp++) {
            uint32_t vf0[4], vf1[4];
            uint32_t col = dp * 16 + (li >> 1) * 8;
            ldsm_x4t(vf0, vbase + (uint32_t)(((li & 1) * 8 + loc) * PKV + col) * 2);
            ldsm_x4t(vf1, vbase + (uint32_t)((16 + (li & 1) * 8 + loc) * PKV + col) * 2);
            mma_fp16(oacc[dp * 2],     pah[0], vf0[0], vf0[1]);
            mma_fp16(oacc[dp * 2 + 1], pah[0], vf0[2], vf0[3]);
            mma_fp16(oacc[dp * 2],     pah[1], vf1[0], vf1[1]);
            mma_fp16(oacc[dp * 2 + 1], pah[1], vf1[2], vf1[3]);
            mma_fp16(oacc[dp * 2],     pal[0], vf0[0], vf0[1]);
            mma_fp16(oacc[dp * 2 + 1], pal[0], vf0[2], vf0[3]);
            mma_fp16(oacc[dp * 2],     pal[1], vf1[0], vf1[1]);
            mma_fp16(oacc[dp * 2 + 1], pal[1], vf1[2], vf1[3]);
        }
        __syncthreads();
    }

    float inv0 = 1.0f / lrow0, inv1 = 1.0f / lrow1;
    int r = q0 + wq0 + (lane >> 2);
    int cbase = h * D + (lane & 3) * 2;
#pragma unroll
    for (int nt = 0; nt < 16; nt++) {
        int c = cbase + nt * 8;
        float a0 = oacc[nt][0] * inv0, a1 = oacc[nt][1] * inv0;
        float a2 = oacc[nt][2] * inv1, a3 = oacc[nt][3] * inv1;
        __nv_bfloat16 h0 = __float2bfloat16(a0), h1 = __float2bfloat16(a1);
        __nv_bfloat16 h2 = __float2bfloat16(a2), h3 = __float2bfloat16(a3);
        __nv_bfloat16 l0 = __float2bfloat16(a0 - __bfloat162float(h0));
        __nv_bfloat16 l1 = __float2bfloat16(a1 - __bfloat162float(h1));
        __nv_bfloat16 l2 = __float2bfloat16(a2 - __bfloat162float(h2));
        __nv_bfloat16 l3 = __float2bfloat16(a3 - __bfloat162float(h3));
        *(uint32_t*)(ohi + (size_t)r * QDIM + c) = pack_bf2(h0, h1);
        *(uint32_t*)(olo + (size_t)r * QDIM + c) = pack_bf2(l0, l1);
        *(uint32_t*)(ohi + (size_t)(r + 8) * QDIM + c) = pack_bf2(h2, h3);
        *(uint32_t*)(olo + (size_t)(r + 8) * QDIM + c) = pack_bf2(l2, l3);
    }
}

// ---------------- host launch ----------------
extern "C" void kernel_launch(void* const* d_in, const int* in_sizes, int n_in,
                              void* d_out, int out_size) {
    const float* hs   = (const float*)d_in[0];
    const float* cosp = (const float*)d_in[1];
    const float* sinp = (const float*)d_in[2];
    const float* Wq = (const float*)d_in[4];
    const float* bq = (const float*)d_in[5];
    const float* Wk = (const float*)d_in[6];
    const float* bk = (const float*)d_in[7];
    const float* Wv = (const float*)d_in[8];
    const float* bv = (const float*)d_in[9];
    const float* Wo = (const float*)d_in[10];
    const float* Wg = (const float*)d_in[11];
    const float* Wu = (const float*)d_in[12];
    const float* Wd = (const float*)d_in[13];
    const float* ln1 = (const float*)d_in[14];
    const float* ln2 = (const float*)d_in[15];
    const float* fln = (const float*)d_in[16];

    float *p_x, *p_qkv, *p_bias;
    __nv_bfloat16 *p_whi, *p_wlo, *p_ahi, *p_alo, *p_bhi, *p_blo;
    __half *p_qh, *p_ql, *p_k16, *p_v16;
    cudaGetSymbolAddress((void**)&p_x, g_x);
    cudaGetSymbolAddress((void**)&p_qkv, g_qkv);
    cudaGetSymbolAddress((void**)&p_bias, g_biasq);
    cudaGetSymbolAddress((void**)&p_whi, g_whi);
    cudaGetSymbolAddress((void**)&p_wlo, g_wlo);
    cudaGetSymbolAddress((void**)&p_ahi, g_ahi);
    cudaGetSymbolAddress((void**)&p_alo, g_alo);
    cudaGetSymbolAddress((void**)&p_bhi, g_bhi);
    cudaGetSymbolAddress((void**)&p_blo, g_blo);
    cudaGetSymbolAddress((void**)&p_qh, g_q16h);
    cudaGetSymbolAddress((void**)&p_ql, g_q16l);
    cudaGetSymbolAddress((void**)&p_k16, g_k16);
    cudaGetSymbolAddress((void**)&p_v16, g_v16);

    const int SMEM128 = 3 * (2 * 128 * APITCH * 2 + 2 * B_BYTES);
    const int SMEM64  = 3 * (2 * 64 * APITCH * 2 + 2 * B_BYTES);
    cudaFuncSetAttribute(attn_kernel, cudaFuncAttributeMaxDynamicSharedMemorySize, ATT_SMEM);
    cudaFuncSetAttribute(wgemm_kernel<0,128>, cudaFuncAttributeMaxDynamicSharedMemorySize, SMEM128);
    cudaFuncSetAttribute(wgemm_kernel<1,64>,  cudaFuncAttributeMaxDynamicSharedMemorySize, SMEM64);
    cudaFuncSetAttribute(wgemm_kernel<2,128>, cudaFuncAttributeMaxDynamicSharedMemorySize, SMEM128);

    {
        int n4 = S * H / 4;
        copy_kernel<<<(n4 + 255) / 256, 256>>>((const float4*)hs, (float4*)p_x, n4);
    }

    for (int i = 0; i < LAYERS; i++) {
        const float* Wq_i = Wq + (size_t)i * H * QDIM;
        const float* Wk_i = Wk + (size_t)i * H * KVDIM;
        const float* Wv_i = Wv + (size_t)i * H * KVDIM;
        const float* Wo_i = Wo + (size_t)i * QDIM * H;
        const float* Wg_i = Wg + (size_t)i * H * IFF;
        const float* Wu_i = Wu + (size_t)i * H * IFF;
        const float* Wd_i = Wd + (size_t)i * IFF * H;

        rmsnorm_split_kernel<<<S, 256>>>(p_x, ln1 + (size_t)i * H, p_ahi, p_alo);

        wsplit_kernel<<<(H * QDIM / 4 + 255) / 256, 256>>>(
            Wq_i, H * QDIM / 4, QDIM / 4, p_whi, p_wlo, 0, QKVN);
        wsplit_kernel<<<(H * KVDIM / 4 + 255) / 256, 256>>>(
            Wk_i, H * KVDIM / 4, KVDIM / 4, p_whi, p_wlo, QDIM, QKVN);
        wsplit_kernel<<<(H * KVDIM / 4 + 255) / 256, 256>>>(
            Wv_i, H * KVDIM / 4, KVDIM / 4, p_whi, p_wlo, QDIM + KVDIM, QKVN);
        concat_bias_kernel<<<QKVN / 256, 256>>>(bq + (size_t)i * QDIM, bk + (size_t)i * KVDIM,
                                                bv + (size_t)i * KVDIM, p_bias);
        wgemm_kernel<0,128><<<dim3(S / 128, QKVN / 128), 256, SMEM128>>>(
            p_ahi, p_alo, p_whi, p_wlo, QKVN, p_bias, nullptr, p_qkv,
            nullptr, nullptr, H, QKVN, 0);

        rope16_kernel<<<dim3(S, NQ + 2 * NKV), 128>>>(p_qkv, cosp, sinp, p_qh, p_ql, p_k16, p_v16);
        attn_kernel<<<dim3(S / 128, NQ), 256, ATT_SMEM>>>(p_qh, p_ql, p_k16, p_v16, p_ahi, p_alo);

        wsplit_kernel<<<(QDIM * H / 4 + 255) / 256, 256>>>(
            Wo_i, QDIM * H / 4, H / 4, p_whi, p_wlo, 0, H);
        wgemm_kernel<1,64><<<dim3(S / 64, H / 128), 256, SMEM64>>>(
            p_ahi, p_alo, p_whi, p_wlo, H, nullptr, p_x, p_x,
            nullptr, nullptr, QDIM, H, 0);

        rmsnorm_split_kernel<<<S, 256>>>(p_x, ln2 + (size_t)i * H, p_ahi, p_alo);

        wsplit_gu_kernel<<<(H * IFF / 4 + 255) / 256, 256>>>(Wg_i, 0, p_whi, p_wlo);
        wsplit_gu_kernel<<<(H * IFF / 4 + 255) / 256, 256>>>(Wu_i, 1, p_whi, p_wlo);
        wgemm_kernel<2,128><<<dim3(S / 128, GUN / 128), 256, SMEM128>>>(
            p_ahi, p_alo, p_whi, p_wlo, GUN, nullptr, nullptr, nullptr,
            p_bhi, p_blo, H, GUN, IFF);

        wsplit_kernel<<<(IFF * H / 4 + 255) / 256, 256>>>(
            Wd_i, IFF * H / 4, H / 4, p_whi, p_wlo, 0, H);
        wgemm_kernel<1,64><<<dim3(S / 64, H / 128), 256, SMEM64>>>(
            p_bhi, p_blo, p_whi, p_wlo, H, nullptr, p_x, p_x,
            nullptr, nullptr, IFF, H, 0);
    }

    rmsnorm_kernel<<<S, 256>>>(p_x, fln, (float*)d_out);
}